// round 8
// baseline (speedup 1.0000x reference)
#include <cuda_runtime.h>
#include <cuda_bf16.h>

// ---------------- problem constants ----------------
// x: (32, 128, 128, 80) fp32; C=80, NH=8, DH=10, WIN=GRID=8 -> 64-token windows
// windows per stage: 32 * 16 * 16 = 8192 ; tokens total 524288

#define TOK_TOTAL (32*128*128)

__device__ float g_buf1[(size_t)TOK_TOTAL * 80];
__device__ float g_buf2[(size_t)TOK_TOTAL * 80];

// pre-converted transposed bf16 weight panels (written by prep_all)
__device__ __align__(16) __nv_bfloat16 g_qkvT_b[240*88];
__device__ __align__(16) __nv_bfloat16 g_projT_b[80*88];
__device__ __align__(16) __nv_bfloat16 g_qkvT_g[240*88];
__device__ __align__(16) __nv_bfloat16 g_projT_g[80*88];
__device__ __align__(16) __nv_bfloat16 g_w1T_b[320*88];
__device__ __align__(16) __nv_bfloat16 g_w2T_b[80*344];
__device__ __align__(16) __nv_bfloat16 g_w1T_g[320*88];
__device__ __align__(16) __nv_bfloat16 g_w2T_g[80*344];

// ---------------- helpers ----------------
__device__ __forceinline__ unsigned pack2(float lo, float hi) {
    __nv_bfloat162 t = __floats2bfloat162_rn(lo, hi);
    return *reinterpret_cast<unsigned*>(&t);
}

__device__ __forceinline__ void mma_bf16(float* c, const unsigned* a, unsigned b0, unsigned b1) {
    asm volatile(
        "mma.sync.aligned.m16n8k16.row.col.f32.bf16.bf16.f32 "
        "{%0,%1,%2,%3}, {%4,%5,%6,%7}, {%8,%9}, {%0,%1,%2,%3};\n"
        : "+f"(c[0]), "+f"(c[1]), "+f"(c[2]), "+f"(c[3])
        : "r"(a[0]), "r"(a[1]), "r"(a[2]), "r"(a[3]), "r"(b0), "r"(b1));
}

__device__ __forceinline__ unsigned smem_u32(const void* p) {
    return (unsigned)__cvta_generic_to_shared(p);
}

__device__ __forceinline__ void ldsm_x4(unsigned* r, unsigned addr) {
    asm volatile("ldmatrix.sync.aligned.m8n8.x4.shared.b16 {%0,%1,%2,%3}, [%4];\n"
                 : "=r"(r[0]), "=r"(r[1]), "=r"(r[2]), "=r"(r[3]) : "r"(addr));
}
__device__ __forceinline__ void ldsm_x2(unsigned& r0, unsigned& r1, unsigned addr) {
    asm volatile("ldmatrix.sync.aligned.m8n8.x2.shared.b16 {%0,%1}, [%2];\n"
                 : "=r"(r0), "=r"(r1) : "r"(addr));
}

// ---------------- single prepass launch: all 8 weight panels ----------------
// gridDim.y = region 0..7; W[k][n] f32 -> WT[n][stride] bf16, pads zero.
__global__ void prep_all(
    const float* s0, const float* s1, const float* s2, const float* s3,
    const float* s4, const float* s5, const float* s6, const float* s7,
    __nv_bfloat16* d0, __nv_bfloat16* d1, __nv_bfloat16* d2, __nv_bfloat16* d3,
    __nv_bfloat16* d4, __nv_bfloat16* d5, __nv_bfloat16* d6, __nv_bfloat16* d7)
{
    const int r = blockIdx.y;
    const float* src; __nv_bfloat16* dst; int K, N, stride, rows;
    switch (r) {
        case 0: src=s0; dst=d0; K=80;  N=240; stride=88;  rows=240; break;
        case 1: src=s1; dst=d1; K=80;  N=80;  stride=88;  rows=80;  break;
        case 2: src=s2; dst=d2; K=80;  N=240; stride=88;  rows=240; break;
        case 3: src=s3; dst=d3; K=80;  N=80;  stride=88;  rows=80;  break;
        case 4: src=s4; dst=d4; K=80;  N=320; stride=88;  rows=320; break;
        case 5: src=s5; dst=d5; K=320; N=80;  stride=344; rows=80;  break;
        case 6: src=s6; dst=d6; K=80;  N=320; stride=88;  rows=320; break;
        default:src=s7; dst=d7; K=320; N=80;  stride=344; rows=80;  break;
    }
    const int total = rows * stride;
    for (int idx = blockIdx.x*256 + threadIdx.x; idx < total; idx += gridDim.x*256) {
        int n = idx / stride, k = idx - n*stride;
        float v = (n < N && k < K) ? src[k*N + n] : 0.f;
        dst[idx] = __float2bfloat16(v);
    }
}

// =====================================================================
// Fused window attention: 512 threads = 2 groups x 8 warps.
// Each group runs the proven R6 per-window pipeline on its own arena.
// 8 windows per CTA (4 iters x 2 parallel groups); weights staged once.
//
// smem layout (bytes):
//   sWqkvT [240][88] bf16 @     0  (42240)
//   sWprojT [80][88] bf16 @ 42240  (14080)
//   sBqkv  [240] f32      @ 56320  (960)
//   sBproj [80]  f32      @ 57280  (320)
//   per-group arena @ 57600 + grp*78080:
//     sXNh [64][88] bf16  +0      (11264)
//     sQ  [8][64][18] bf16 +11264 (18432)   k-pads 10..17 zero
//     sK  [8][64][18] bf16 +29696 (18432)   (sOut f32 [64][81]=20736 aliases sQ+sK)
//     sVT [8][16][72] bf16 +48128 (18432)
//     sO   [64][88] bf16  +66560  (11264)
//     sInv [64] f32       +77824  (256)
// total 57600 + 2*78080 = 213760 B
// =====================================================================
constexpr int ATTN_SMEM_BYTES = 213760;
constexpr int ATTN_WIN_PER_CTA = 8;
constexpr int ATTN_NCTA = 8192 / ATTN_WIN_PER_CTA;     // 1024
constexpr int GRP_BYTES = 78080;
constexpr float QK_SCALE = 0.31622776601683794f;       // DH^-0.5

template<bool IS_GRID>
__global__ void __launch_bounds__(512, 1)
attn_kernel(const float* __restrict__ x, float* __restrict__ y,
            const __nv_bfloat16* __restrict__ wqkvT, const float* __restrict__ bqkv,
            const __nv_bfloat16* __restrict__ wprojT, const float* __restrict__ bproj)
{
    extern __shared__ float smf[];
    char* smb = reinterpret_cast<char*>(smf);
    __nv_bfloat16* sWqkvT  = reinterpret_cast<__nv_bfloat16*>(smb);           // [240][88]
    __nv_bfloat16* sWprojT = reinterpret_cast<__nv_bfloat16*>(smb + 42240);   // [80][88]
    float*         sBqkv   = reinterpret_cast<float*>(smb + 56320);           // [240]
    float*         sBproj  = reinterpret_cast<float*>(smb + 57280);           // [80]

    const int tid  = threadIdx.x;
    const int grp  = tid >> 8;           // window group 0/1
    const int gtid = tid & 255;          // thread within group
    const int w    = gtid >> 5;          // warp within group 0..7
    const int lane = tid & 31;
    const int g    = lane >> 2, tq  = lane & 3;
    const int l15  = lane & 15, l7 = lane & 7;

    char* arena = smb + 57600 + grp*GRP_BYTES;
    __nv_bfloat16* sXNh = reinterpret_cast<__nv_bfloat16*>(arena);            // [64][88]
    __nv_bfloat16* sQ   = reinterpret_cast<__nv_bfloat16*>(arena + 11264);    // [8][64][18]
    __nv_bfloat16* sK   = reinterpret_cast<__nv_bfloat16*>(arena + 29696);    // [8][64][18]
    float*         sOut = reinterpret_cast<float*>(arena + 11264);            // alias Q+K [64][81]
    __nv_bfloat16* sVT  = reinterpret_cast<__nv_bfloat16*>(arena + 48128);    // [8][16][72]
    __nv_bfloat16* sO   = reinterpret_cast<__nv_bfloat16*>(arena + 66560);    // [64][88]
    float*         sInv = reinterpret_cast<float*>(arena + 77824);            // [64]

    // ---- one-time staging (all 512 threads) ----
    {
        const float4* s1 = reinterpret_cast<const float4*>(wqkvT);
        float4* d1 = reinterpret_cast<float4*>(sWqkvT);
        for (int i = tid; i < 2640; i += 512) d1[i] = s1[i];
        const float4* s2 = reinterpret_cast<const float4*>(wprojT);
        float4* d2 = reinterpret_cast<float4*>(sWprojT);
        for (int i = tid; i < 880; i += 512) d2[i] = s2[i];
        if (tid < 240) sBqkv[tid] = bqkv[tid];
        if (tid >= 256 && tid < 336) sBproj[tid-256] = bproj[tid-256];
    }

    const unsigned uXNh = smem_u32(sXNh);
    const unsigned uWq  = smem_u32(sWqkvT);
    const unsigned uO   = smem_u32(sO);
    const unsigned uWp  = smem_u32(sWprojT);

    for (int it = 0; it < 4; it++) {
        const int wIdx = blockIdx.x * ATTN_WIN_PER_CTA + it*2 + grp;
        const int bb  = wIdx >> 8;
        const int rem = wIdx & 255;
        const int wh  = rem >> 4, ww = rem & 15;

        // zero k-pads d=10..17 of this group's sQ and sK (scatter below only
        // writes d<10; sQ/sK were clobbered by the sOut alias last iter)
        for (int i = gtid; i < 2048; i += 256) {
            int row = i >> 2, p = i & 3;
            reinterpret_cast<unsigned*>(sQ + row*18 + 10)[p] = 0u;
            reinterpret_cast<unsigned*>(sK + row*18 + 10)[p] = 0u;
        }

        // ---- load + l2norm (4 thr/token, float4); bf16 panel + inv only ----
        {
            const int t = gtid >> 2, lg = gtid & 3;
            const int ti = t >> 3, tj = t & 7;
            int pr, pc;
            if (IS_GRID) { pr = ti*16 + wh; pc = tj*16 + ww; }
            else         { pr = wh*8 + ti;  pc = ww*8 + tj;  }
            const long pix = ((long)bb*128 + pr)*128 + pc;
            const float4* xr = reinterpret_cast<const float4*>(x + pix*80) + lg*5;
            float v[20]; float ss = 0.f;
            #pragma unroll
            for (int u = 0; u < 5; u++) {
                float4 f = xr[u];
                v[4*u+0]=f.x; v[4*u+1]=f.y; v[4*u+2]=f.z; v[4*u+3]=f.w;
                ss += f.x*f.x + f.y*f.y + f.z*f.z + f.w*f.w;
            }
            ss += __shfl_xor_sync(0xffffffffu, ss, 1);
            ss += __shfl_xor_sync(0xffffffffu, ss, 2);
            const float inv = rsqrtf(fmaxf(ss, 1e-24f));
            unsigned* xh = reinterpret_cast<unsigned*>(sXNh + t*88 + lg*20);
            #pragma unroll
            for (int u = 0; u < 10; u++) xh[u] = pack2(v[2*u]*inv, v[2*u+1]*inv);
            if (lg == 0) sInv[t] = inv;
        }
        __syncthreads();

        // ---- QKV GEMM: 8 warps = 4 mt x 2 j-groups of 15 ntiles (ldmatrix) ----
        {
            const int mt    = w >> 1;
            const int jbase = (w & 1) * 15;
            const unsigned aBase = uXNh + (mt*16 + l15)*176 + (lane>>4)*16;
            const unsigned bBase = uWq + (jbase*8 + l7)*176 + (l15>>3)*16;
            float acc[15][4];
            #pragma unroll
            for (int j = 0; j < 15; j++)
                #pragma unroll
                for (int e = 0; e < 4; e++) acc[j][e] = 0.f;

            #pragma unroll
            for (int ks = 0; ks < 5; ks++) {
                unsigned a[4];
                ldsm_x4(a, aBase + ks*32);
                #pragma unroll
                for (int j = 0; j < 15; j++) {
                    unsigned b0, b1;
                    ldsm_x2(b0, b1, bBase + j*1408 + ks*32);   // 8*176 = 1408
                    mma_bf16(acc[j], a, b0, b1);
                }
            }
            const int rowA = mt*16 + g;
            #pragma unroll
            for (int j = 0; j < 15; j++) {
                #pragma unroll
                for (int e = 0; e < 2; e++) {
                    const int col = (jbase+j)*8 + 2*tq + e;
                    const int h = col / 30;
                    const int r = col - h*30;
                    const int d = (r >= 20) ? r - 20 : (r >= 10 ? r - 10 : r);
                    const float bias = sBqkv[col];
                    float vA = acc[j][e]   + bias;
                    float vB = acc[j][2+e] + bias;
                    if (r < 10) {
                        sQ[h*1152 + rowA*18 + d]     = __float2bfloat16(vA * QK_SCALE);
                        sQ[h*1152 + (rowA+8)*18 + d] = __float2bfloat16(vB * QK_SCALE);
                    } else if (r < 20) {
                        sK[h*1152 + rowA*18 + d]     = __float2bfloat16(vA);
                        sK[h*1152 + (rowA+8)*18 + d] = __float2bfloat16(vB);
                    } else {
                        sVT[h*1152 + d*72 + rowA]     = __float2bfloat16(vA);
                        sVT[h*1152 + d*72 + rowA + 8] = __float2bfloat16(vB);
                    }
                }
            }
        }
        __syncthreads();

        // ---- attention: warp w == head w, register-resident (2 passes) ----
        {
            const int h = w;
            const __nv_bfloat16* Qh = sQ  + h*1152;
            const __nv_bfloat16* Kh = sK  + h*1152;
            const __nv_bfloat16* Vh = sVT + h*1152;

            #pragma unroll
            for (int pass = 0; pass < 2; pass++) {
                float s[2][8][4];
                unsigned qa[2][4];
                #pragma unroll
                for (int mi = 0; mi < 2; mi++) {
                    const __nv_bfloat16* qp = Qh + ((pass*2+mi)*16 + g)*18;
                    qa[mi][0] = *reinterpret_cast<const unsigned*>(qp + 2*tq);
                    qa[mi][1] = *reinterpret_cast<const unsigned*>(qp + 8*18 + 2*tq);
                    qa[mi][2] = *reinterpret_cast<const unsigned*>(qp + 2*tq + 8);
                    qa[mi][3] = *reinterpret_cast<const unsigned*>(qp + 8*18 + 2*tq + 8);
                }
                #pragma unroll
                for (int nt = 0; nt < 8; nt++) {
                    const __nv_bfloat16* kp = Kh + (nt*8 + g)*18;
                    unsigned b0 = *reinterpret_cast<const unsigned*>(kp + 2*tq);
                    unsigned b1 = *reinterpret_cast<const unsigned*>(kp + 2*tq + 8);
                    #pragma unroll
                    for (int mi = 0; mi < 2; mi++) {
                        #pragma unroll
                        for (int e = 0; e < 4; e++) s[mi][nt][e] = 0.f;
                        mma_bf16(s[mi][nt], qa[mi], b0, b1);
                    }
                }
                float invA[2], invB[2];
                #pragma unroll
                for (int mi = 0; mi < 2; mi++) {
                    float mA = -1e30f, mB = -1e30f;
                    #pragma unroll
                    for (int nt = 0; nt < 8; nt++) {
                        mA = fmaxf(mA, fmaxf(s[mi][nt][0], s[mi][nt][1]));
                        mB = fmaxf(mB, fmaxf(s[mi][nt][2], s[mi][nt][3]));
                    }
                    mA = fmaxf(mA, __shfl_xor_sync(0xffffffffu, mA, 1));
                    mA = fmaxf(mA, __shfl_xor_sync(0xffffffffu, mA, 2));
                    mB = fmaxf(mB, __shfl_xor_sync(0xffffffffu, mB, 1));
                    mB = fmaxf(mB, __shfl_xor_sync(0xffffffffu, mB, 2));
                    float sA = 0.f, sB = 0.f;
                    #pragma unroll
                    for (int nt = 0; nt < 8; nt++) {
                        float e0 = __expf(s[mi][nt][0] - mA);
                        float e1 = __expf(s[mi][nt][1] - mA);
                        float e2 = __expf(s[mi][nt][2] - mB);
                        float e3 = __expf(s[mi][nt][3] - mB);
                        s[mi][nt][0]=e0; s[mi][nt][1]=e1; s[mi][nt][2]=e2; s[mi][nt][3]=e3;
                        sA += e0 + e1; sB += e2 + e3;
                    }
                    sA += __shfl_xor_sync(0xffffffffu, sA, 1);
                    sA += __shfl_xor_sync(0xffffffffu, sA, 2);
                    sB += __shfl_xor_sync(0xffffffffu, sB, 1);
                    sB += __shfl_xor_sync(0xffffffffu, sB, 2);
                    invA[mi] = 1.0f / sA;
                    invB[mi] = 1.0f / sB;
                }
                float o[2][2][4];
                #pragma unroll
                for (int mi = 0; mi < 2; mi++)
                    #pragma unroll
                    for (int nt2 = 0; nt2 < 2; nt2++)
                        #pragma unroll
                        for (int e = 0; e < 4; e++) o[mi][nt2][e] = 0.f;
                #pragma unroll
                for (int ks = 0; ks < 4; ks++) {
                    unsigned pa[2][4];
                    #pragma unroll
                    for (int mi = 0; mi < 2; mi++) {
                        pa[mi][0] = pack2(s[mi][2*ks  ][0], s[mi][2*ks  ][1]);
                        pa[mi][1] = pack2(s[mi][2*ks  ][2], s[mi][2*ks  ][3]);
                        pa[mi][2] = pack2(s[mi][2*ks+1][0], s[mi][2*ks+1][1]);
                        pa[mi][3] = pack2(s[mi][2*ks+1][2], s[mi][2*ks+1][3]);
                    }
                    #pragma unroll
                    for (int nt2 = 0; nt2 < 2; nt2++) {
                        const __nv_bfloat16* vp = Vh + (nt2*8 + g)*72 + ks*16;
                        unsigned b0 = *reinterpret_cast<const unsigned*>(vp + 2*tq);
                        unsigned b1 = *reinterpret_cast<const unsigned*>(vp + 2*tq + 8);
                        mma_bf16(o[0][nt2], pa[0], b0, b1);
                        mma_bf16(o[1][nt2], pa[1], b0, b1);
                    }
                }
                #pragma unroll
                for (int mi = 0; mi < 2; mi++) {
                    const int row = (pass*2+mi)*16 + g;
                    #pragma unroll
                    for (int nt2 = 0; nt2 < 2; nt2++) {
                        const int dh = nt2*8 + 2*tq;
                        if (dh < 10) {
                            *reinterpret_cast<unsigned*>(sO + row*88 + h*10 + dh) =
                                pack2(o[mi][nt2][0]*invA[mi], o[mi][nt2][1]*invA[mi]);
                            *reinterpret_cast<unsigned*>(sO + (row+8)*88 + h*10 + dh) =
                                pack2(o[mi][nt2][2]*invB[mi], o[mi][nt2][3]*invB[mi]);
                        }
                    }
                }
            }
        }
        __syncthreads();

        // ---- proj GEMM: 4 mt x 2 groups of 5 ntiles (ldmatrix) ----
        // writes fp32 result+bias into sOut (aliases dead sQ/sK)
        {
            const int mt = w >> 1;
            const int nb = (w & 1) * 5;
            const unsigned aBase = uO + (mt*16 + l15)*176 + (lane>>4)*16;
            const unsigned bBase = uWp + (nb*8 + l7)*176 + (l15>>3)*16;
            float acc[5][4];
            #pragma unroll
            for (int j = 0; j < 5; j++)
                #pragma unroll
                for (int e = 0; e < 4; e++) acc[j][e] = 0.f;
            #pragma unroll
            for (int ks = 0; ks < 5; ks++) {
                unsigned a[4];
                ldsm_x4(a, aBase + ks*32);
                #pragma unroll
                for (int j = 0; j < 5; j++) {
                    unsigned b0, b1;
                    ldsm_x2(b0, b1, bBase + j*1408 + ks*32);
                    mma_bf16(acc[j], a, b0, b1);
                }
            }
            const int rowA = mt*16 + g;
            #pragma unroll
            for (int j = 0; j < 5; j++) {
                const int c = (nb+j)*8 + 2*tq;
                sOut[rowA*81 + c]         = acc[j][0] + sBproj[c];
                sOut[rowA*81 + c + 1]     = acc[j][1] + sBproj[c+1];
                sOut[(rowA+8)*81 + c]     = acc[j][2] + sBproj[c];
                sOut[(rowA+8)*81 + c + 1] = acc[j][3] + sBproj[c+1];
            }
        }
        __syncthreads();

        // ---- epilogue: reload x, out = x*inv + proj; coalesced ----
        {
            const int t = gtid >> 2, lg = gtid & 3;
            const int ti = t >> 3, tj = t & 7;
            int pr, pc;
            if (IS_GRID) { pr = ti*16 + wh; pc = tj*16 + ww; }
            else         { pr = wh*8 + ti;  pc = ww*8 + tj;  }
            const long pix = ((long)bb*128 + pr)*128 + pc;
            const float inv = sInv[t];
            const float4* xr = reinterpret_cast<const float4*>(x + pix*80) + lg*5;
            float4* yr = reinterpret_cast<float4*>(y + pix*80) + lg*5;
            const float* po = sOut + t*81 + lg*20;
            #pragma unroll
            for (int u = 0; u < 5; u++) {
                float4 xf = xr[u];
                yr[u] = make_float4(xf.x*inv + po[4*u],   xf.y*inv + po[4*u+1],
                                    xf.z*inv + po[4*u+2], xf.w*inv + po[4*u+3]);
            }
        }
        __syncthreads();   // before next iter reuses arena
    }
}

// =====================================================================
// Fused MLP (unchanged from R6): M=128 supertiles, 512 thr, ldmatrix.
// =====================================================================
constexpr int MLP_SMEM_BYTES = 223104;
constexpr int MLP_NCTA = TOK_TOTAL / 256;   // 2048

template<bool RELU2>
__global__ void __launch_bounds__(512, 1)
mlp_kernel(const float* __restrict__ xin, float* __restrict__ xout,
           const __nv_bfloat16* __restrict__ w1T, const __nv_bfloat16* __restrict__ w2T,
           const float* __restrict__ b2, const float* __restrict__ gamma)
{
    extern __shared__ float smf[];
    char* smb = reinterpret_cast<char*>(smf);
    __nv_bfloat16* sW1T  = reinterpret_cast<__nv_bfloat16*>(smb);            // [320][88]
    __nv_bfloat16* sW2T  = reinterpret_cast<__nv_bfloat16*>(smb + 56320);    // [80][344]
    __nv_bfloat16* sXNh  = reinterpret_cast<__nv_bfloat16*>(smb + 111360);   // [128][88]
    __nv_bfloat16* sH    = reinterpret_cast<__nv_bfloat16*>(smb + 133888);   // [128][344]
    float*         sOutA = reinterpret_cast<float*>(smb + 133888);           // alias [128][81]
    float*         sOutB = reinterpret_cast<float*>(smb + 175360);           // alias [128][81]
    float*         sInv  = reinterpret_cast<float*>(smb + 221952);           // [128]
    float*         sB2   = reinterpret_cast<float*>(smb + 222464);
    float*         sG    = reinterpret_cast<float*>(smb + 222784);

    const int tid = threadIdx.x;
    const int w = tid >> 5, lane = tid & 31;
    const int g = lane >> 2, tq = lane & 3;
    const int l15 = lane & 15, l7 = lane & 7;

    {
        const float4* s1 = reinterpret_cast<const float4*>(w1T);
        float4* d1 = reinterpret_cast<float4*>(sW1T);
        for (int i = tid; i < 3520; i += 512) d1[i] = s1[i];
        const float4* s2 = reinterpret_cast<const float4*>(w2T);
        float4* d2 = reinterpret_cast<float4*>(sW2T);
        for (int i = tid; i < 3440; i += 512) d2[i] = s2[i];
        if (tid < 80) { sB2[tid] = b2[tid]; sG[tid] = gamma[tid]; }
    }

    const unsigned uXNh = smem_u32(sXNh);
    const unsigned uW1  = smem_u32(sW1T);
    const unsigned uH   = smem_u32(sH);
    const unsigned uW2  = smem_u32(sW2T);

    for (int st = 0; st < 2; st++) {
        const long tokBase = ((long)blockIdx.x*2 + st) * 128;

        {
            const int t = tid >> 2, lg = tid & 3;
            const float4* xr = reinterpret_cast<const float4*>(xin + (tokBase + t)*80) + lg*5;
            float v[20]; float ss = 0.f;
            #pragma unroll
            for (int u = 0; u < 5; u++) {
                float4 f = xr[u];
                v[4*u]=f.x; v[4*u+1]=f.y; v[4*u+2]=f.z; v[4*u+3]=f.w;
                ss += f.x*f.x + f.y*f.y + f.z*f.z + f.w*f.w;
            }
            ss += __shfl_xor_sync(0xffffffffu, ss, 1);
            ss += __shfl_xor_sync(0xffffffffu, ss, 2);
            const float inv = rsqrtf(fmaxf(ss, 1e-24f));
            unsigned* xh = reinterpret_cast<unsigned*>(sXNh + t*88 + lg*20);
            #pragma unroll
            for (int u = 0; u < 10; u++) xh[u] = pack2(v[2*u]*inv, v[2*u+1]*inv);
            if (lg == 0) sInv[t] = inv;
        }
        __syncthreads();

        {
            const int mp = w & 3;
            const int ng = w >> 2;
            const unsigned aBase = uXNh + (mp*32 + l15)*176 + (lane>>4)*16;
            const unsigned bBase = uW1 + (ng*80 + l7)*176 + (l15>>3)*16;
            float acc[2][10][4];
            #pragma unroll
            for (int mi = 0; mi < 2; mi++)
                #pragma unroll
                for (int j = 0; j < 10; j++)
                    #pragma unroll
                    for (int e = 0; e < 4; e++) acc[mi][j][e] = 0.f;

            #pragma unroll
            for (int ks = 0; ks < 5; ks++) {
                unsigned a[2][4];
                ldsm_x4(a[0], aBase + ks*32);
                ldsm_x4(a[1], aBase + 16*176 + ks*32);
                #pragma unroll
                for (int j = 0; j < 10; j++) {
                    unsigned b0, b1;
                    ldsm_x2(b0, b1, bBase + j*1408 + ks*32);
                    mma_bf16(acc[0][j], a[0], b0, b1);
                    mma_bf16(acc[1][j], a[1], b0, b1);
                }
            }
            #pragma unroll
            for (int mi = 0; mi < 2; mi++) {
                const int r0 = mp*32 + mi*16 + g;
                #pragma unroll
                for (int j = 0; j < 10; j++) {
                    const int c = (ng*10+j)*8 + 2*tq;
                    *reinterpret_cast<unsigned*>(sH + r0*344 + c) =
                        pack2(fmaxf(acc[mi][j][0], 0.f), fmaxf(acc[mi][j][1], 0.f));
                    *reinterpret_cast<unsigned*>(sH + (r0+8)*344 + c) =
                        pack2(fmaxf(acc[mi][j][2], 0.f), fmaxf(acc[mi][j][3], 0.f));
                }
            }
        }
        __syncthreads();

        {
            const int mp = w & 3;
            const int ng = (w >> 2) & 1;
            const int kh = w >> 3;
            const unsigned aBase = uH + (mp*32 + l15)*688 + (lane>>4)*16 + kh*320;
            const unsigned bBase = uW2 + (ng*40 + l7)*688 + (l15>>3)*16 + kh*320;
            float acc2[2][5][4];
            #pragma unroll
            for (int mi = 0; mi < 2; mi++)
                #pragma unroll
                for (int j = 0; j < 5; j++)
                    #pragma unroll
                    for (int e = 0; e < 4; e++) acc2[mi][j][e] = 0.f;

            #pragma unroll
            for (int ks = 0; ks < 10; ks++) {
                unsigned a[2][4];
                ldsm_x4(a[0], aBase + ks*32);
                ldsm_x4(a[1], aBase + 16*688 + ks*32);
                #pragma unroll
                for (int j = 0; j < 5; j++) {
                    unsigned b0, b1;
                    ldsm_x2(b0, b1, bBase + j*5504 + ks*32);
                    mma_bf16(acc2[0][j], a[0], b0, b1);
                    mma_bf16(acc2[1][j], a[1], b0, b1);
                }
            }
            __syncthreads();
            float* sOut = kh ? sOutB : sOutA;
            #pragma unroll
            for (int mi = 0; mi < 2; mi++) {
                const int r0 = mp*32 + mi*16 + g;
                #pragma unroll
                for (int j = 0; j < 5; j++) {
                    const int c = (ng*5+j)*8 + 2*tq;
                    sOut[r0*81 + c]         = acc2[mi][j][0];
                    sOut[r0*81 + c + 1]     = acc2[mi][j][1];
                    sOut[(r0+8)*81 + c]     = acc2[mi][j][2];
                    sOut[(r0+8)*81 + c + 1] = acc2[mi][j][3];
                }
            }
        }
        __syncthreads();

        {
            const int t = tid >> 2, lg = tid & 3;
            const float inv = sInv[t];
            const float4* xr = reinterpret_cast<const float4*>(xin + (tokBase + t)*80) + lg*5;
            float4* yr = reinterpret_cast<float4*>(xout + (tokBase + t)*80) + lg*5;
            #pragma unroll
            for (int u = 0; u < 5; u++) {
                float4 xf = xr[u];
                float xv[4] = {xf.x, xf.y, xf.z, xf.w};
                float f[4];
                #pragma unroll
                for (int e = 0; e < 4; e++) {
                    const int idx = lg*20 + 4*u + e;
                    float hv = sOutA[t*81 + idx] + sOutB[t*81 + idx] + sB2[idx];
                    if (RELU2) hv = fmaxf(hv, 0.f);
                    f[e] = xv[e]*inv + hv * sG[idx];
                }
                yr[u] = make_float4(f[0], f[1], f[2], f[3]);
            }
        }
        __syncthreads();
    }
}

// =====================================================================
extern "C" void kernel_launch(void* const* d_in, const int* in_sizes, int n_in,
                              void* d_out, int out_size)
{
    const float* x       = (const float*)d_in[0];
    const float* bw_qkv  = (const float*)d_in[1];
    const float* bb_qkv  = (const float*)d_in[2];
    const float* bw_proj = (const float*)d_in[3];
    const float* bb_proj = (const float*)d_in[4];
    const float* b_gamma = (const float*)d_in[5];
    const float* bw_mlp1 = (const float*)d_in[6];
    const float* bw_mlp2 = (const float*)d_in[7];
    const float* bb_mlp2 = (const float*)d_in[8];
    const float* gw_qkv  = (const float*)d_in[9];
    const float* gb_qkv  = (const float*)d_in[10];
    const float* gw_proj = (const float*)d_in[11];
    const float* gb_proj = (const float*)d_in[12];
    const float* g_gamma = (const float*)d_in[13];
    const float* gw_mlp1 = (const float*)d_in[14];
    const float* gw_mlp2 = (const float*)d_in[15];
    const float* gb_mlp2 = (const float*)d_in[16];
    float* out = (float*)d_out;

    float *buf1 = nullptr, *buf2 = nullptr;
    cudaGetSymbolAddress((void**)&buf1, g_buf1);
    cudaGetSymbolAddress((void**)&buf2, g_buf2);

    __nv_bfloat16 *qkvT_b, *projT_b, *qkvT_g, *projT_g, *w1T_b, *w2T_b, *w1T_g, *w2T_g;
    cudaGetSymbolAddress((void**)&qkvT_b,  g_qkvT_b);
    cudaGetSymbolAddress((void**)&projT_b, g_projT_b);
    cudaGetSymbolAddress((void**)&qkvT_g,  g_qkvT_g);
    cudaGetSymbolAddress((void**)&projT_g, g_projT_g);
    cudaGetSymbolAddress((void**)&w1T_b,   g_w1T_b);
    cudaGetSymbolAddress((void**)&w2T_b,   g_w2T_b);
    cudaGetSymbolAddress((void**)&w1T_g,   g_w1T_g);
    cudaGetSymbolAddress((void**)&w2T_g,   g_w2T_g);

    const size_t smA = ATTN_SMEM_BYTES;   // 213,760 B
    const size_t smM = MLP_SMEM_BYTES;    // 223,104 B
    cudaFuncSetAttribute(attn_kernel<false>, cudaFuncAttributeMaxDynamicSharedMemorySize, (int)smA);
    cudaFuncSetAttribute(attn_kernel<true>,  cudaFuncAttributeMaxDynamicSharedMemorySize, (int)smA);
    cudaFuncSetAttribute(mlp_kernel<true>,   cudaFuncAttributeMaxDynamicSharedMemorySize, (int)smM);
    cudaFuncSetAttribute(mlp_kernel<false>,  cudaFuncAttributeMaxDynamicSharedMemorySize, (int)smM);

    // ---- single prepass launch: all 8 weight panels ----
    {
        dim3 grid(16, 8);
        prep_all<<<grid, 256>>>(bw_qkv, bw_proj, gw_qkv, gw_proj,
                                bw_mlp1, bw_mlp2, gw_mlp1, gw_mlp2,
                                qkvT_b, projT_b, qkvT_g, projT_g,
                                w1T_b, w2T_b, w1T_g, w2T_g);
    }

    // stage 1: block SA
    attn_kernel<false><<<ATTN_NCTA, 512, smA>>>(x,    buf1, qkvT_b, bb_qkv, projT_b, bb_proj);
    mlp_kernel<true>  <<<MLP_NCTA,  512, smM>>>(buf1, buf2, w1T_b, w2T_b, bb_mlp2, b_gamma);
    // stage 2: grid SA
    attn_kernel<true> <<<ATTN_NCTA, 512, smA>>>(buf2, buf1, qkvT_g, gb_qkv, projT_g, gb_proj);
    mlp_kernel<false> <<<MLP_NCTA,  512, smM>>>(buf1, out, w1T_g, w2T_g, gb_mlp2, g_gamma);
}

// round 9
// speedup vs baseline: 1.2353x; 1.2353x over previous
#include <cuda_runtime.h>
#include <cuda_bf16.h>

// ---------------- problem constants ----------------
// x: (32, 128, 128, 80) fp32; C=80, NH=8, DH=10, WIN=GRID=8 -> 64-token windows
// windows per stage: 32 * 16 * 16 = 8192 ; tokens total 524288

#define TOK_TOTAL (32*128*128)

__device__ float g_buf1[(size_t)TOK_TOTAL * 80];
__device__ float g_buf2[(size_t)TOK_TOTAL * 80];

// pre-converted transposed bf16 weight panels (written by prep_all)
__device__ __align__(16) __nv_bfloat16 g_qkvT_b[240*88];
__device__ __align__(16) __nv_bfloat16 g_projT_b[80*88];
__device__ __align__(16) __nv_bfloat16 g_qkvT_g[240*88];
__device__ __align__(16) __nv_bfloat16 g_projT_g[80*88];
__device__ __align__(16) __nv_bfloat16 g_w1T_b[320*88];
__device__ __align__(16) __nv_bfloat16 g_w2T_b[80*344];
__device__ __align__(16) __nv_bfloat16 g_w1T_g[320*88];
__device__ __align__(16) __nv_bfloat16 g_w2T_g[80*344];

// ---------------- helpers ----------------
__device__ __forceinline__ unsigned pack2(float lo, float hi) {
    __nv_bfloat162 t = __floats2bfloat162_rn(lo, hi);
    return *reinterpret_cast<unsigned*>(&t);
}

__device__ __forceinline__ void mma_bf16(float* c, const unsigned* a, unsigned b0, unsigned b1) {
    asm volatile(
        "mma.sync.aligned.m16n8k16.row.col.f32.bf16.bf16.f32 "
        "{%0,%1,%2,%3}, {%4,%5,%6,%7}, {%8,%9}, {%0,%1,%2,%3};\n"
        : "+f"(c[0]), "+f"(c[1]), "+f"(c[2]), "+f"(c[3])
        : "r"(a[0]), "r"(a[1]), "r"(a[2]), "r"(a[3]), "r"(b0), "r"(b1));
}

__device__ __forceinline__ unsigned smem_u32(const void* p) {
    return (unsigned)__cvta_generic_to_shared(p);
}

__device__ __forceinline__ void ldsm_x4(unsigned* r, unsigned addr) {
    asm volatile("ldmatrix.sync.aligned.m8n8.x4.shared.b16 {%0,%1,%2,%3}, [%4];\n"
                 : "=r"(r[0]), "=r"(r[1]), "=r"(r[2]), "=r"(r[3]) : "r"(addr));
}
__device__ __forceinline__ void ldsm_x2(unsigned& r0, unsigned& r1, unsigned addr) {
    asm volatile("ldmatrix.sync.aligned.m8n8.x2.shared.b16 {%0,%1}, [%2];\n"
                 : "=r"(r0), "=r"(r1) : "r"(addr));
}

// ---------------- single prepass launch: all 8 weight panels ----------------
__global__ void prep_all(
    const float* s0, const float* s1, const float* s2, const float* s3,
    const float* s4, const float* s5, const float* s6, const float* s7,
    __nv_bfloat16* d0, __nv_bfloat16* d1, __nv_bfloat16* d2, __nv_bfloat16* d3,
    __nv_bfloat16* d4, __nv_bfloat16* d5, __nv_bfloat16* d6, __nv_bfloat16* d7)
{
    const int r = blockIdx.y;
    const float* src; __nv_bfloat16* dst; int K, N, stride, rows;
    switch (r) {
        case 0: src=s0; dst=d0; K=80;  N=240; stride=88;  rows=240; break;
        case 1: src=s1; dst=d1; K=80;  N=80;  stride=88;  rows=80;  break;
        case 2: src=s2; dst=d2; K=80;  N=240; stride=88;  rows=240; break;
        case 3: src=s3; dst=d3; K=80;  N=80;  stride=88;  rows=80;  break;
        case 4: src=s4; dst=d4; K=80;  N=320; stride=88;  rows=320; break;
        case 5: src=s5; dst=d5; K=320; N=80;  stride=344; rows=80;  break;
        case 6: src=s6; dst=d6; K=80;  N=320; stride=88;  rows=320; break;
        default:src=s7; dst=d7; K=320; N=80;  stride=344; rows=80;  break;
    }
    const int total = rows * stride;
    for (int idx = blockIdx.x*256 + threadIdx.x; idx < total; idx += gridDim.x*256) {
        int n = idx / stride, k = idx - n*stride;
        float v = (n < N && k < K) ? src[k*N + n] : 0.f;
        dst[idx] = __float2bfloat16(v);
    }
}

// =====================================================================
// Fused window attention: 256 threads = 8 warps (proven R6 config),
// 4 windows per CTA.  R8 deltas vs R6: no fp32 residual buffer
// (reload-x epilogue, sOut aliases dead Q/K), packed u32 Q/K scatter.
// smem total 135680 B (layout in offsets below).
// =====================================================================
constexpr int ATTN_SMEM_BYTES = 135680;
constexpr int ATTN_TILES_PER_CTA = 4;
constexpr int ATTN_NCTA = 8192 / ATTN_TILES_PER_CTA;   // 2048
constexpr float QK_SCALE = 0.31622776601683794f;       // DH^-0.5

template<bool IS_GRID>
__global__ void __launch_bounds__(256, 1)
attn_kernel(const float* __restrict__ x, float* __restrict__ y,
            const __nv_bfloat16* __restrict__ wqkvT, const float* __restrict__ bqkv,
            const __nv_bfloat16* __restrict__ wprojT, const float* __restrict__ bproj)
{
    extern __shared__ float smf[];
    char* smb = reinterpret_cast<char*>(smf);
    __nv_bfloat16* sWqkvT  = reinterpret_cast<__nv_bfloat16*>(smb);           // [240][88]
    __nv_bfloat16* sWprojT = reinterpret_cast<__nv_bfloat16*>(smb + 42240);   // [80][88]
    float*         sBqkv   = reinterpret_cast<float*>(smb + 56320);           // [240]
    float*         sBproj  = reinterpret_cast<float*>(smb + 57280);           // [80]
    __nv_bfloat16* sXNh    = reinterpret_cast<__nv_bfloat16*>(smb + 57600);   // [64][88]
    __nv_bfloat16* sQ      = reinterpret_cast<__nv_bfloat16*>(smb + 68864);   // [8][64][18]
    __nv_bfloat16* sK      = reinterpret_cast<__nv_bfloat16*>(smb + 87296);   // [8][64][18]
    float*         sOut    = reinterpret_cast<float*>(smb + 68864);           // alias [64][81]
    __nv_bfloat16* sVT     = reinterpret_cast<__nv_bfloat16*>(smb + 105728);  // [8][16][72]
    __nv_bfloat16* sO      = reinterpret_cast<__nv_bfloat16*>(smb + 124160);  // [64][88]
    float*         sInv    = reinterpret_cast<float*>(smb + 135424);          // [64]

    const int tid  = threadIdx.x;
    const int w    = tid >> 5, lane = tid & 31;
    const int g    = lane >> 2, tq  = lane & 3;
    const int l15  = lane & 15, l7 = lane & 7;

    // ---- one-time staging: vector copies of pre-converted weights ----
    {
        const float4* s1 = reinterpret_cast<const float4*>(wqkvT);
        float4* d1 = reinterpret_cast<float4*>(sWqkvT);
        for (int i = tid; i < 2640; i += 256) d1[i] = s1[i];
        const float4* s2 = reinterpret_cast<const float4*>(wprojT);
        float4* d2 = reinterpret_cast<float4*>(sWprojT);
        for (int i = tid; i < 880; i += 256) d2[i] = s2[i];
        if (tid < 240) sBqkv[tid] = bqkv[tid];
        if (tid < 80)  sBproj[tid] = bproj[tid];
    }

    const unsigned uXNh = smem_u32(sXNh);
    const unsigned uWq  = smem_u32(sWqkvT);
    const unsigned uO   = smem_u32(sO);
    const unsigned uWp  = smem_u32(sWprojT);

    for (int it = 0; it < ATTN_TILES_PER_CTA; it++) {
        const int wIdx = blockIdx.x * ATTN_TILES_PER_CTA + it;
        const int bb  = wIdx >> 8;
        const int rem = wIdx & 255;
        const int wh  = rem >> 4, ww = rem & 15;

        // re-zero k-pads d=10..17 of sQ/sK (clobbered by sOut alias last iter)
        for (int i = tid; i < 2048; i += 256) {
            int row = i >> 2, p = i & 3;
            reinterpret_cast<unsigned*>(sQ + row*18 + 10)[p] = 0u;
            reinterpret_cast<unsigned*>(sK + row*18 + 10)[p] = 0u;
        }

        // ---- load + l2norm (4 thr/token, float4): bf16 panel + inv only ----
        {
            const int t = tid >> 2, lg = tid & 3;
            const int ti = t >> 3, tj = t & 7;
            int pr, pc;
            if (IS_GRID) { pr = ti*16 + wh; pc = tj*16 + ww; }
            else         { pr = wh*8 + ti;  pc = ww*8 + tj;  }
            const long pix = ((long)bb*128 + pr)*128 + pc;
            const float4* xr = reinterpret_cast<const float4*>(x + pix*80) + lg*5;
            float v[20]; float ss = 0.f;
            #pragma unroll
            for (int u = 0; u < 5; u++) {
                float4 f = xr[u];
                v[4*u+0]=f.x; v[4*u+1]=f.y; v[4*u+2]=f.z; v[4*u+3]=f.w;
                ss += f.x*f.x + f.y*f.y + f.z*f.z + f.w*f.w;
            }
            ss += __shfl_xor_sync(0xffffffffu, ss, 1);
            ss += __shfl_xor_sync(0xffffffffu, ss, 2);
            const float inv = rsqrtf(fmaxf(ss, 1e-24f));
            unsigned* xh = reinterpret_cast<unsigned*>(sXNh + t*88 + lg*20);
            #pragma unroll
            for (int u = 0; u < 10; u++) xh[u] = pack2(v[2*u]*inv, v[2*u+1]*inv);
            if (lg == 0) sInv[t] = inv;
        }
        __syncthreads();

        // ---- QKV GEMM: 8 warps = 4 mt x 2 j-groups of 15 ntiles (ldmatrix) ----
        {
            const int mt    = w >> 1;
            const int jbase = (w & 1) * 15;
            const unsigned aBase = uXNh + (mt*16 + l15)*176 + (lane>>4)*16;
            const unsigned bBase = uWq + (jbase*8 + l7)*176 + (l15>>3)*16;
            float acc[15][4];
            #pragma unroll
            for (int j = 0; j < 15; j++)
                #pragma unroll
                for (int e = 0; e < 4; e++) acc[j][e] = 0.f;

            #pragma unroll
            for (int ks = 0; ks < 5; ks++) {
                unsigned a[4];
                ldsm_x4(a, aBase + ks*32);
                #pragma unroll
                for (int j = 0; j < 15; j++) {
                    unsigned b0, b1;
                    ldsm_x2(b0, b1, bBase + j*1408 + ks*32);
                    mma_bf16(acc[j], a, b0, b1);
                }
            }
            // packed scatter: c0 even; segment boundaries are odd -> pair never splits
            const int rowA = mt*16 + g;
            #pragma unroll
            for (int j = 0; j < 15; j++) {
                const int c0 = (jbase+j)*8 + 2*tq;
                const int h  = c0 / 30;
                const int r  = c0 - h*30;          // even
                const float b0 = sBqkv[c0], b1 = sBqkv[c0+1];
                const float vA0 = acc[j][0] + b0, vA1 = acc[j][1] + b1;
                const float vB0 = acc[j][2] + b0, vB1 = acc[j][3] + b1;
                if (r < 10) {
                    *reinterpret_cast<unsigned*>(sQ + h*1152 + rowA*18 + r) =
                        pack2(vA0*QK_SCALE, vA1*QK_SCALE);
                    *reinterpret_cast<unsigned*>(sQ + h*1152 + (rowA+8)*18 + r) =
                        pack2(vB0*QK_SCALE, vB1*QK_SCALE);
                } else if (r < 20) {
                    const int d = r - 10;
                    *reinterpret_cast<unsigned*>(sK + h*1152 + rowA*18 + d) = pack2(vA0, vA1);
                    *reinterpret_cast<unsigned*>(sK + h*1152 + (rowA+8)*18 + d) = pack2(vB0, vB1);
                } else {
                    const int d = r - 20;
                    sVT[h*1152 + d*72     + rowA]     = __float2bfloat16(vA0);
                    sVT[h*1152 + (d+1)*72 + rowA]     = __float2bfloat16(vA1);
                    sVT[h*1152 + d*72     + rowA + 8] = __float2bfloat16(vB0);
                    sVT[h*1152 + (d+1)*72 + rowA + 8] = __float2bfloat16(vB1);
                }
            }
        }
        __syncthreads();

        // ---- attention: warp w == head w, register-resident (2 passes) ----
        {
            const int h = w;
            const __nv_bfloat16* Qh = sQ  + h*1152;
            const __nv_bfloat16* Kh = sK  + h*1152;
            const __nv_bfloat16* Vh = sVT + h*1152;

            #pragma unroll
            for (int pass = 0; pass < 2; pass++) {
                float s[2][8][4];
                unsigned qa[2][4];
                #pragma unroll
                for (int mi = 0; mi < 2; mi++) {
                    const __nv_bfloat16* qp = Qh + ((pass*2+mi)*16 + g)*18;
                    qa[mi][0] = *reinterpret_cast<const unsigned*>(qp + 2*tq);
                    qa[mi][1] = *reinterpret_cast<const unsigned*>(qp + 8*18 + 2*tq);
                    qa[mi][2] = *reinterpret_cast<const unsigned*>(qp + 2*tq + 8);
                    qa[mi][3] = *reinterpret_cast<const unsigned*>(qp + 8*18 + 2*tq + 8);
                }
                #pragma unroll
                for (int nt = 0; nt < 8; nt++) {
                    const __nv_bfloat16* kp = Kh + (nt*8 + g)*18;
                    unsigned b0 = *reinterpret_cast<const unsigned*>(kp + 2*tq);
                    unsigned b1 = *reinterpret_cast<const unsigned*>(kp + 2*tq + 8);
                    #pragma unroll
                    for (int mi = 0; mi < 2; mi++) {
                        #pragma unroll
                        for (int e = 0; e < 4; e++) s[mi][nt][e] = 0.f;
                        mma_bf16(s[mi][nt], qa[mi], b0, b1);
                    }
                }
                float invA[2], invB[2];
                #pragma unroll
                for (int mi = 0; mi < 2; mi++) {
                    float mA = -1e30f, mB = -1e30f;
                    #pragma unroll
                    for (int nt = 0; nt < 8; nt++) {
                        mA = fmaxf(mA, fmaxf(s[mi][nt][0], s[mi][nt][1]));
                        mB = fmaxf(mB, fmaxf(s[mi][nt][2], s[mi][nt][3]));
                    }
                    mA = fmaxf(mA, __shfl_xor_sync(0xffffffffu, mA, 1));
                    mA = fmaxf(mA, __shfl_xor_sync(0xffffffffu, mA, 2));
                    mB = fmaxf(mB, __shfl_xor_sync(0xffffffffu, mB, 1));
                    mB = fmaxf(mB, __shfl_xor_sync(0xffffffffu, mB, 2));
                    float sA = 0.f, sB = 0.f;
                    #pragma unroll
                    for (int nt = 0; nt < 8; nt++) {
                        float e0 = __expf(s[mi][nt][0] - mA);
                        float e1 = __expf(s[mi][nt][1] - mA);
                        float e2 = __expf(s[mi][nt][2] - mB);
                        float e3 = __expf(s[mi][nt][3] - mB);
                        s[mi][nt][0]=e0; s[mi][nt][1]=e1; s[mi][nt][2]=e2; s[mi][nt][3]=e3;
                        sA += e0 + e1; sB += e2 + e3;
                    }
                    sA += __shfl_xor_sync(0xffffffffu, sA, 1);
                    sA += __shfl_xor_sync(0xffffffffu, sA, 2);
                    sB += __shfl_xor_sync(0xffffffffu, sB, 1);
                    sB += __shfl_xor_sync(0xffffffffu, sB, 2);
                    invA[mi] = 1.0f / sA;
                    invB[mi] = 1.0f / sB;
                }
                float o[2][2][4];
                #pragma unroll
                for (int mi = 0; mi < 2; mi++)
                    #pragma unroll
                    for (int nt2 = 0; nt2 < 2; nt2++)
                        #pragma unroll
                        for (int e = 0; e < 4; e++) o[mi][nt2][e] = 0.f;
                #pragma unroll
                for (int ks = 0; ks < 4; ks++) {
                    unsigned pa[2][4];
                    #pragma unroll
                    for (int mi = 0; mi < 2; mi++) {
                        pa[mi][0] = pack2(s[mi][2*ks  ][0], s[mi][2*ks  ][1]);
                        pa[mi][1] = pack2(s[mi][2*ks  ][2], s[mi][2*ks  ][3]);
                        pa[mi][2] = pack2(s[mi][2*ks+1][0], s[mi][2*ks+1][1]);
                        pa[mi][3] = pack2(s[mi][2*ks+1][2], s[mi][2*ks+1][3]);
                    }
                    #pragma unroll
                    for (int nt2 = 0; nt2 < 2; nt2++) {
                        const __nv_bfloat16* vp = Vh + (nt2*8 + g)*72 + ks*16;
                        unsigned b0 = *reinterpret_cast<const unsigned*>(vp + 2*tq);
                        unsigned b1 = *reinterpret_cast<const unsigned*>(vp + 2*tq + 8);
                        mma_bf16(o[0][nt2], pa[0], b0, b1);
                        mma_bf16(o[1][nt2], pa[1], b0, b1);
                    }
                }
                #pragma unroll
                for (int mi = 0; mi < 2; mi++) {
                    const int row = (pass*2+mi)*16 + g;
                    #pragma unroll
                    for (int nt2 = 0; nt2 < 2; nt2++) {
                        const int dh = nt2*8 + 2*tq;
                        if (dh < 10) {
                            *reinterpret_cast<unsigned*>(sO + row*88 + h*10 + dh) =
                                pack2(o[mi][nt2][0]*invA[mi], o[mi][nt2][1]*invA[mi]);
                            *reinterpret_cast<unsigned*>(sO + (row+8)*88 + h*10 + dh) =
                                pack2(o[mi][nt2][2]*invB[mi], o[mi][nt2][3]*invB[mi]);
                        }
                    }
                }
            }
        }
        __syncthreads();

        // ---- proj GEMM: 4 mt x 2 groups of 5 ntiles (ldmatrix) ----
        {
            const int mt = w >> 1;
            const int nb = (w & 1) * 5;
            const unsigned aBase = uO + (mt*16 + l15)*176 + (lane>>4)*16;
            const unsigned bBase = uWp + (nb*8 + l7)*176 + (l15>>3)*16;
            float acc[5][4];
            #pragma unroll
            for (int j = 0; j < 5; j++)
                #pragma unroll
                for (int e = 0; e < 4; e++) acc[j][e] = 0.f;
            #pragma unroll
            for (int ks = 0; ks < 5; ks++) {
                unsigned a[4];
                ldsm_x4(a, aBase + ks*32);
                #pragma unroll
                for (int j = 0; j < 5; j++) {
                    unsigned b0, b1;
                    ldsm_x2(b0, b1, bBase + j*1408 + ks*32);
                    mma_bf16(acc[j], a, b0, b1);
                }
            }
            const int rowA = mt*16 + g;
            #pragma unroll
            for (int j = 0; j < 5; j++) {
                const int c = (nb+j)*8 + 2*tq;
                sOut[rowA*81 + c]         = acc[j][0] + sBproj[c];
                sOut[rowA*81 + c + 1]     = acc[j][1] + sBproj[c+1];
                sOut[(rowA+8)*81 + c]     = acc[j][2] + sBproj[c];
                sOut[(rowA+8)*81 + c + 1] = acc[j][3] + sBproj[c+1];
            }
        }
        __syncthreads();

        // ---- epilogue: reload x, out = x*inv + proj; coalesced ----
        {
            const int t = tid >> 2, lg = tid & 3;
            const int ti = t >> 3, tj = t & 7;
            int pr, pc;
            if (IS_GRID) { pr = ti*16 + wh; pc = tj*16 + ww; }
            else         { pr = wh*8 + ti;  pc = ww*8 + tj;  }
            const long pix = ((long)bb*128 + pr)*128 + pc;
            const float inv = sInv[t];
            const float4* xr = reinterpret_cast<const float4*>(x + pix*80) + lg*5;
            float4* yr = reinterpret_cast<float4*>(y + pix*80) + lg*5;
            const float* po = sOut + t*81 + lg*20;
            #pragma unroll
            for (int u = 0; u < 5; u++) {
                float4 xf = xr[u];
                yr[u] = make_float4(xf.x*inv + po[4*u],   xf.y*inv + po[4*u+1],
                                    xf.z*inv + po[4*u+2], xf.w*inv + po[4*u+3]);
            }
        }
        __syncthreads();
    }
}

// =====================================================================
// Fused MLP (unchanged from R6 passing build).
// =====================================================================
constexpr int MLP_SMEM_BYTES = 223104;
constexpr int MLP_NCTA = TOK_TOTAL / 256;   // 2048

template<bool RELU2>
__global__ void __launch_bounds__(512, 1)
mlp_kernel(const float* __restrict__ xin, float* __restrict__ xout,
           const __nv_bfloat16* __restrict__ w1T, const __nv_bfloat16* __restrict__ w2T,
           const float* __restrict__ b2, const float* __restrict__ gamma)
{
    extern __shared__ float smf[];
    char* smb = reinterpret_cast<char*>(smf);
    __nv_bfloat16* sW1T  = reinterpret_cast<__nv_bfloat16*>(smb);            // [320][88]
    __nv_bfloat16* sW2T  = reinterpret_cast<__nv_bfloat16*>(smb + 56320);    // [80][344]
    __nv_bfloat16* sXNh  = reinterpret_cast<__nv_bfloat16*>(smb + 111360);   // [128][88]
    __nv_bfloat16* sH    = reinterpret_cast<__nv_bfloat16*>(smb + 133888);   // [128][344]
    float*         sOutA = reinterpret_cast<float*>(smb + 133888);           // alias [128][81]
    float*         sOutB = reinterpret_cast<float*>(smb + 175360);           // alias [128][81]
    float*         sInv  = reinterpret_cast<float*>(smb + 221952);           // [128]
    float*         sB2   = reinterpret_cast<float*>(smb + 222464);
    float*         sG    = reinterpret_cast<float*>(smb + 222784);

    const int tid = threadIdx.x;
    const int w = tid >> 5, lane = tid & 31;
    const int g = lane >> 2, tq = lane & 3;
    const int l15 = lane & 15, l7 = lane & 7;

    {
        const float4* s1 = reinterpret_cast<const float4*>(w1T);
        float4* d1 = reinterpret_cast<float4*>(sW1T);
        for (int i = tid; i < 3520; i += 512) d1[i] = s1[i];
        const float4* s2 = reinterpret_cast<const float4*>(w2T);
        float4* d2 = reinterpret_cast<float4*>(sW2T);
        for (int i = tid; i < 3440; i += 512) d2[i] = s2[i];
        if (tid < 80) { sB2[tid] = b2[tid]; sG[tid] = gamma[tid]; }
    }

    const unsigned uXNh = smem_u32(sXNh);
    const unsigned uW1  = smem_u32(sW1T);
    const unsigned uH   = smem_u32(sH);
    const unsigned uW2  = smem_u32(sW2T);

    for (int st = 0; st < 2; st++) {
        const long tokBase = ((long)blockIdx.x*2 + st) * 128;

        {
            const int t = tid >> 2, lg = tid & 3;
            const float4* xr = reinterpret_cast<const float4*>(xin + (tokBase + t)*80) + lg*5;
            float v[20]; float ss = 0.f;
            #pragma unroll
            for (int u = 0; u < 5; u++) {
                float4 f = xr[u];
                v[4*u]=f.x; v[4*u+1]=f.y; v[4*u+2]=f.z; v[4*u+3]=f.w;
                ss += f.x*f.x + f.y*f.y + f.z*f.z + f.w*f.w;
            }
            ss += __shfl_xor_sync(0xffffffffu, ss, 1);
            ss += __shfl_xor_sync(0xffffffffu, ss, 2);
            const float inv = rsqrtf(fmaxf(ss, 1e-24f));
            unsigned* xh = reinterpret_cast<unsigned*>(sXNh + t*88 + lg*20);
            #pragma unroll
            for (int u = 0; u < 10; u++) xh[u] = pack2(v[2*u]*inv, v[2*u+1]*inv);
            if (lg == 0) sInv[t] = inv;
        }
        __syncthreads();

        {
            const int mp = w & 3;
            const int ng = w >> 2;
            const unsigned aBase = uXNh + (mp*32 + l15)*176 + (lane>>4)*16;
            const unsigned bBase = uW1 + (ng*80 + l7)*176 + (l15>>3)*16;
            float acc[2][10][4];
            #pragma unroll
            for (int mi = 0; mi < 2; mi++)
                #pragma unroll
                for (int j = 0; j < 10; j++)
                    #pragma unroll
                    for (int e = 0; e < 4; e++) acc[mi][j][e] = 0.f;

            #pragma unroll
            for (int ks = 0; ks < 5; ks++) {
                unsigned a[2][4];
                ldsm_x4(a[0], aBase + ks*32);
                ldsm_x4(a[1], aBase + 16*176 + ks*32);
                #pragma unroll
                for (int j = 0; j < 10; j++) {
                    unsigned b0, b1;
                    ldsm_x2(b0, b1, bBase + j*1408 + ks*32);
                    mma_bf16(acc[0][j], a[0], b0, b1);
                    mma_bf16(acc[1][j], a[1], b0, b1);
                }
            }
            #pragma unroll
            for (int mi = 0; mi < 2; mi++) {
                const int r0 = mp*32 + mi*16 + g;
                #pragma unroll
                for (int j = 0; j < 10; j++) {
                    const int c = (ng*10+j)*8 + 2*tq;
                    *reinterpret_cast<unsigned*>(sH + r0*344 + c) =
                        pack2(fmaxf(acc[mi][j][0], 0.f), fmaxf(acc[mi][j][1], 0.f));
                    *reinterpret_cast<unsigned*>(sH + (r0+8)*344 + c) =
                        pack2(fmaxf(acc[mi][j][2], 0.f), fmaxf(acc[mi][j][3], 0.f));
                }
            }
        }
        __syncthreads();

        {
            const int mp = w & 3;
            const int ng = (w >> 2) & 1;
            const int kh = w >> 3;
            const unsigned aBase = uH + (mp*32 + l15)*688 + (lane>>4)*16 + kh*320;
            const unsigned bBase = uW2 + (ng*40 + l7)*688 + (l15>>3)*16 + kh*320;
            float acc2[2][5][4];
            #pragma unroll
            for (int mi = 0; mi < 2; mi++)
                #pragma unroll
                for (int j = 0; j < 5; j++)
                    #pragma unroll
                    for (int e = 0; e < 4; e++) acc2[mi][j][e] = 0.f;

            #pragma unroll
            for (int ks = 0; ks < 10; ks++) {
                unsigned a[2][4];
                ldsm_x4(a[0], aBase + ks*32);
                ldsm_x4(a[1], aBase + 16*688 + ks*32);
                #pragma unroll
                for (int j = 0; j < 5; j++) {
                    unsigned b0, b1;
                    ldsm_x2(b0, b1, bBase + j*5504 + ks*32);
                    mma_bf16(acc2[0][j], a[0], b0, b1);
                    mma_bf16(acc2[1][j], a[1], b0, b1);
                }
            }
            __syncthreads();
            float* sOut = kh ? sOutB : sOutA;
            #pragma unroll
            for (int mi = 0; mi < 2; mi++) {
                const int r0 = mp*32 + mi*16 + g;
                #pragma unroll
                for (int j = 0; j < 5; j++) {
                    const int c = (ng*5+j)*8 + 2*tq;
                    sOut[r0*81 + c]         = acc2[mi][j][0];
                    sOut[r0*81 + c + 1]     = acc2[mi][j][1];
                    sOut[(r0+8)*81 + c]     = acc2[mi][j][2];
                    sOut[(r0+8)*81 + c + 1] = acc2[mi][j][3];
                }
            }
        }
        __syncthreads();

        {
            const int t = tid >> 2, lg = tid & 3;
            const float inv = sInv[t];
            const float4* xr = reinterpret_cast<const float4*>(xin + (tokBase + t)*80) + lg*5;
            float4* yr = reinterpret_cast<float4*>(xout + (tokBase + t)*80) + lg*5;
            #pragma unroll
            for (int u = 0; u < 5; u++) {
                float4 xf = xr[u];
                float xv[4] = {xf.x, xf.y, xf.z, xf.w};
                float f[4];
                #pragma unroll
                for (int e = 0; e < 4; e++) {
                    const int idx = lg*20 + 4*u + e;
                    float hv = sOutA[t*81 + idx] + sOutB[t*81 + idx] + sB2[idx];
                    if (RELU2) hv = fmaxf(hv, 0.f);
                    f[e] = xv[e]*inv + hv * sG[idx];
                }
                yr[u] = make_float4(f[0], f[1], f[2], f[3]);
            }
        }
        __syncthreads();
    }
}

// =====================================================================
extern "C" void kernel_launch(void* const* d_in, const int* in_sizes, int n_in,
                              void* d_out, int out_size)
{
    const float* x       = (const float*)d_in[0];
    const float* bw_qkv  = (const float*)d_in[1];
    const float* bb_qkv  = (const float*)d_in[2];
    const float* bw_proj = (const float*)d_in[3];
    const float* bb_proj = (const float*)d_in[4];
    const float* b_gamma = (const float*)d_in[5];
    const float* bw_mlp1 = (const float*)d_in[6];
    const float* bw_mlp2 = (const float*)d_in[7];
    const float* bb_mlp2 = (const float*)d_in[8];
    const float* gw_qkv  = (const float*)d_in[9];
    const float* gb_qkv  = (const float*)d_in[10];
    const float* gw_proj = (const float*)d_in[11];
    const float* gb_proj = (const float*)d_in[12];
    const float* g_gamma = (const float*)d_in[13];
    const float* gw_mlp1 = (const float*)d_in[14];
    const float* gw_mlp2 = (const float*)d_in[15];
    const float* gb_mlp2 = (const float*)d_in[16];
    float* out = (float*)d_out;

    float *buf1 = nullptr, *buf2 = nullptr;
    cudaGetSymbolAddress((void**)&buf1, g_buf1);
    cudaGetSymbolAddress((void**)&buf2, g_buf2);

    __nv_bfloat16 *qkvT_b, *projT_b, *qkvT_g, *projT_g, *w1T_b, *w2T_b, *w1T_g, *w2T_g;
    cudaGetSymbolAddress((void**)&qkvT_b,  g_qkvT_b);
    cudaGetSymbolAddress((void**)&projT_b, g_projT_b);
    cudaGetSymbolAddress((void**)&qkvT_g,  g_qkvT_g);
    cudaGetSymbolAddress((void**)&projT_g, g_projT_g);
    cudaGetSymbolAddress((void**)&w1T_b,   g_w1T_b);
    cudaGetSymbolAddress((void**)&w2T_b,   g_w2T_b);
    cudaGetSymbolAddress((void**)&w1T_g,   g_w1T_g);
    cudaGetSymbolAddress((void**)&w2T_g,   g_w2T_g);

    const size_t smA = ATTN_SMEM_BYTES;   // 135,680 B
    const size_t smM = MLP_SMEM_BYTES;    // 223,104 B
    cudaFuncSetAttribute(attn_kernel<false>, cudaFuncAttributeMaxDynamicSharedMemorySize, (int)smA);
    cudaFuncSetAttribute(attn_kernel<true>,  cudaFuncAttributeMaxDynamicSharedMemorySize, (int)smA);
    cudaFuncSetAttribute(mlp_kernel<true>,   cudaFuncAttributeMaxDynamicSharedMemorySize, (int)smM);
    cudaFuncSetAttribute(mlp_kernel<false>,  cudaFuncAttributeMaxDynamicSharedMemorySize, (int)smM);

    // ---- single prepass launch: all 8 weight panels ----
    {
        dim3 grid(16, 8);
        prep_all<<<grid, 256>>>(bw_qkv, bw_proj, gw_qkv, gw_proj,
                                bw_mlp1, bw_mlp2, gw_mlp1, gw_mlp2,
                                qkvT_b, projT_b, qkvT_g, projT_g,
                                w1T_b, w2T_b, w1T_g, w2T_g);
    }

    // stage 1: block SA
    attn_kernel<false><<<ATTN_NCTA, 256, smA>>>(x,    buf1, qkvT_b, bb_qkv, projT_b, bb_proj);
    mlp_kernel<true>  <<<MLP_NCTA,  512, smM>>>(buf1, buf2, w1T_b, w2T_b, bb_mlp2, b_gamma);
    // stage 2: grid SA
    attn_kernel<true> <<<ATTN_NCTA, 256, smA>>>(buf2, buf1, qkvT_g, gb_qkv, projT_g, gb_proj);
    mlp_kernel<false> <<<MLP_NCTA,  512, smM>>>(buf1, out, w1T_g, w2T_g, gb_mlp2, g_gamma);
}

// round 11
// speedup vs baseline: 1.3260x; 1.0734x over previous
#include <cuda_runtime.h>
#include <cuda_bf16.h>

// ---------------- problem constants ----------------
// x: (32, 128, 128, 80) fp32; C=80, NH=8, DH=10, WIN=GRID=8 -> 64-token windows
// windows per stage: 32 * 16 * 16 = 8192 ; tokens total 524288

#define TOK_TOTAL (32*128*128)

__device__ float g_buf1[(size_t)TOK_TOTAL * 80];
__device__ float g_buf2[(size_t)TOK_TOTAL * 80];

// pre-converted transposed bf16 weight panels (written by prep_all)
__device__ __align__(16) __nv_bfloat16 g_qkvT_b[240*88];
__device__ __align__(16) __nv_bfloat16 g_projT_b[80*88];
__device__ __align__(16) __nv_bfloat16 g_qkvT_g[240*88];
__device__ __align__(16) __nv_bfloat16 g_projT_g[80*88];
__device__ __align__(16) __nv_bfloat16 g_w1T_b[320*88];
__device__ __align__(16) __nv_bfloat16 g_w2T_b[80*344];
__device__ __align__(16) __nv_bfloat16 g_w1T_g[320*88];
__device__ __align__(16) __nv_bfloat16 g_w2T_g[80*344];

// ---------------- helpers ----------------
__device__ __forceinline__ unsigned pack2(float lo, float hi) {
    __nv_bfloat162 t = __floats2bfloat162_rn(lo, hi);
    return *reinterpret_cast<unsigned*>(&t);
}

__device__ __forceinline__ void mma_bf16(float* c, const unsigned* a, unsigned b0, unsigned b1) {
    asm volatile(
        "mma.sync.aligned.m16n8k16.row.col.f32.bf16.bf16.f32 "
        "{%0,%1,%2,%3}, {%4,%5,%6,%7}, {%8,%9}, {%0,%1,%2,%3};\n"
        : "+f"(c[0]), "+f"(c[1]), "+f"(c[2]), "+f"(c[3])
        : "r"(a[0]), "r"(a[1]), "r"(a[2]), "r"(a[3]), "r"(b0), "r"(b1));
}

__device__ __forceinline__ unsigned smem_u32(const void* p) {
    return (unsigned)__cvta_generic_to_shared(p);
}

__device__ __forceinline__ void ldsm_x4(unsigned* r, unsigned addr) {
    asm volatile("ldmatrix.sync.aligned.m8n8.x4.shared.b16 {%0,%1,%2,%3}, [%4];\n"
                 : "=r"(r[0]), "=r"(r[1]), "=r"(r[2]), "=r"(r[3]) : "r"(addr));
}
__device__ __forceinline__ void ldsm_x2(unsigned& r0, unsigned& r1, unsigned addr) {
    asm volatile("ldmatrix.sync.aligned.m8n8.x2.shared.b16 {%0,%1}, [%2];\n"
                 : "=r"(r0), "=r"(r1) : "r"(addr));
}

// ---------------- single prepass launch: all 8 weight panels ----------------
__global__ void prep_all(
    const float* s0, const float* s1, const float* s2, const float* s3,
    const float* s4, const float* s5, const float* s6, const float* s7,
    __nv_bfloat16* d0, __nv_bfloat16* d1, __nv_bfloat16* d2, __nv_bfloat16* d3,
    __nv_bfloat16* d4, __nv_bfloat16* d5, __nv_bfloat16* d6, __nv_bfloat16* d7)
{
    const int r = blockIdx.y;
    const float* src; __nv_bfloat16* dst; int K, N, stride, rows;
    switch (r) {
        case 0: src=s0; dst=d0; K=80;  N=240; stride=88;  rows=240; break;
        case 1: src=s1; dst=d1; K=80;  N=80;  stride=88;  rows=80;  break;
        case 2: src=s2; dst=d2; K=80;  N=240; stride=88;  rows=240; break;
        case 3: src=s3; dst=d3; K=80;  N=80;  stride=88;  rows=80;  break;
        case 4: src=s4; dst=d4; K=80;  N=320; stride=88;  rows=320; break;
        case 5: src=s5; dst=d5; K=320; N=80;  stride=344; rows=80;  break;
        case 6: src=s6; dst=d6; K=80;  N=320; stride=88;  rows=320; break;
        default:src=s7; dst=d7; K=320; N=80;  stride=344; rows=80;  break;
    }
    const int total = rows * stride;
    for (int idx = blockIdx.x*256 + threadIdx.x; idx < total; idx += gridDim.x*256) {
        int n = idx / stride, k = idx - n*stride;
        float v = (n < N && k < K) ? src[k*N + n] : 0.f;
        dst[idx] = __float2bfloat16(v);
    }
}

// =====================================================================
// Fused window attention: 256 threads = 8 warps, M=128 supertiles
// (2 windows per iteration, 8 windows per CTA over 4 iterations).
// QKV/proj GEMMs span both windows (acc[2][..]) -> B-fragment loads
// halved per mma.  Proj epilogue writes directly to global with
// residual (no sOut buffer, pads zeroed once).  Softmax without
// max-subtraction (logits provably bounded << 88).
//
// smem (bytes):
//   sWqkvT [240][88] bf16 @     0  (42240)
//   sWprojT [80][88] bf16 @ 42240  (14080)
//   sBqkv  [240] f32      @ 56320  (960)
//   sBproj [80]  f32      @ 57280  (320)
//   per-window arena @ 57600 + win*78080:
//     sXNh [64][88] bf16  +0      (11264)
//     sQ  [8][64][18] bf16 +11264 (18432)   k-pads d=10..17 zero (set once)
//     sK  [8][64][18] bf16 +29696 (18432)
//     sVT [8][16][72] bf16 +48128 (18432)
//     sO   [64][88] bf16  +66560  (11264)
//     sInv [64] f32       +77824  (256)
// total 57600 + 2*78080 = 213760 B
// =====================================================================
constexpr int ATTN_SMEM_BYTES = 213760;
constexpr int ATTN_WIN_PER_CTA = 8;
constexpr int ATTN_NCTA = 8192 / ATTN_WIN_PER_CTA;     // 1024
constexpr int ARENA = 78080;
constexpr float QK_SCALE = 0.31622776601683794f;       // DH^-0.5

template<bool IS_GRID>
__global__ void __launch_bounds__(256, 1)
attn_kernel(const float* __restrict__ x, float* __restrict__ y,
            const __nv_bfloat16* __restrict__ wqkvT, const float* __restrict__ bqkv,
            const __nv_bfloat16* __restrict__ wprojT, const float* __restrict__ bproj)
{
    extern __shared__ float smf[];
    char* smb = reinterpret_cast<char*>(smf);
    __nv_bfloat16* sWqkvT  = reinterpret_cast<__nv_bfloat16*>(smb);           // [240][88]
    __nv_bfloat16* sWprojT = reinterpret_cast<__nv_bfloat16*>(smb + 42240);   // [80][88]
    float*         sBqkv   = reinterpret_cast<float*>(smb + 56320);           // [240]
    float*         sBproj  = reinterpret_cast<float*>(smb + 57280);           // [80]
    char*          ar0     = smb + 57600;

    const int tid  = threadIdx.x;
    const int w    = tid >> 5, lane = tid & 31;
    const int g    = lane >> 2, tq  = lane & 3;
    const int l15  = lane & 15, l7 = lane & 7;

    // ---- one-time staging + pad zeroing ----
    {
        const float4* s1 = reinterpret_cast<const float4*>(wqkvT);
        float4* d1 = reinterpret_cast<float4*>(sWqkvT);
        for (int i = tid; i < 2640; i += 256) d1[i] = s1[i];
        const float4* s2 = reinterpret_cast<const float4*>(wprojT);
        float4* d2 = reinterpret_cast<float4*>(sWprojT);
        for (int i = tid; i < 880; i += 256) d2[i] = s2[i];
        if (tid < 240) sBqkv[tid] = bqkv[tid];
        if (tid < 80)  sBproj[tid] = bproj[tid];
        // zero k-pads d=10..17 of sQ/sK in BOTH arenas (never clobbered)
        for (int i = tid; i < 4096; i += 256) {
            int a = i >> 11, r = i & 2047;
            int row = r >> 2, p = r & 3;
            char* ar = ar0 + a*ARENA;
            reinterpret_cast<unsigned*>(reinterpret_cast<__nv_bfloat16*>(ar + 11264) + row*18 + 10)[p] = 0u;
            reinterpret_cast<unsigned*>(reinterpret_cast<__nv_bfloat16*>(ar + 29696) + row*18 + 10)[p] = 0u;
        }
    }

    const unsigned uAr0 = smem_u32(ar0);
    const unsigned uWq  = smem_u32(sWqkvT);
    const unsigned uWp  = smem_u32(sWprojT);

    for (int it = 0; it < 4; it++) {
        const int wBase = blockIdx.x * ATTN_WIN_PER_CTA + it*2;

        // ---- load + l2norm: 2 threads per token (128 tokens) ----
        {
            const int t  = tid >> 1, lg = tid & 1;
            const int wn = t >> 6, tr = t & 63;
            const int wIdx = wBase + wn;
            const int bb = wIdx >> 8, rem = wIdx & 255;
            const int wh = rem >> 4, ww = rem & 15;
            const int ti = tr >> 3, tj = tr & 7;
            int pr, pc;
            if (IS_GRID) { pr = ti*16 + wh; pc = tj*16 + ww; }
            else         { pr = wh*8 + ti;  pc = ww*8 + tj;  }
            const long pix = ((long)bb*128 + pr)*128 + pc;
            const float4* xr = reinterpret_cast<const float4*>(x + pix*80) + lg*10;
            float v[40]; float ss = 0.f;
            #pragma unroll
            for (int u = 0; u < 10; u++) {
                float4 f = xr[u];
                v[4*u+0]=f.x; v[4*u+1]=f.y; v[4*u+2]=f.z; v[4*u+3]=f.w;
                ss += f.x*f.x + f.y*f.y + f.z*f.z + f.w*f.w;
            }
            ss += __shfl_xor_sync(0xffffffffu, ss, 1);
            const float inv = rsqrtf(fmaxf(ss, 1e-24f));
            char* ar = ar0 + wn*ARENA;
            unsigned* xh = reinterpret_cast<unsigned*>(
                reinterpret_cast<__nv_bfloat16*>(ar) + tr*88 + lg*40);
            #pragma unroll
            for (int u = 0; u < 20; u++) xh[u] = pack2(v[2*u]*inv, v[2*u+1]*inv);
            if (lg == 0) reinterpret_cast<float*>(ar + 77824)[tr] = inv;
        }
        __syncthreads();

        // ---- QKV GEMM M=128: 8 warps = 4 mt-pairs x 2 j-groups of 15 ----
        {
            const int p = w >> 1, jbase = (w & 1) * 15;
            unsigned aB[2];
            #pragma unroll
            for (int mi = 0; mi < 2; mi++) {
                const int mt = 2*p + mi, wn = mt >> 2, lr = (mt & 3)*16;
                aB[mi] = uAr0 + wn*ARENA + (lr + l15)*176 + (lane>>4)*16;
            }
            const unsigned bBase = uWq + (jbase*8 + l7)*176 + (l15>>3)*16;
            float acc[2][15][4];
            #pragma unroll
            for (int mi = 0; mi < 2; mi++)
                #pragma unroll
                for (int j = 0; j < 15; j++)
                    #pragma unroll
                    for (int e = 0; e < 4; e++) acc[mi][j][e] = 0.f;

            #pragma unroll
            for (int ks = 0; ks < 5; ks++) {
                unsigned a0[4], a1[4];
                ldsm_x4(a0, aB[0] + ks*32);
                ldsm_x4(a1, aB[1] + ks*32);
                #pragma unroll
                for (int j = 0; j < 15; j++) {
                    unsigned b0, b1;
                    ldsm_x2(b0, b1, bBase + j*1408 + ks*32);   // 8*176 = 1408
                    mma_bf16(acc[0][j], a0, b0, b1);
                    mma_bf16(acc[1][j], a1, b0, b1);
                }
            }
            // packed scatter (c0 even; segment boundaries odd -> pair never splits)
            #pragma unroll
            for (int mi = 0; mi < 2; mi++) {
                const int mt = 2*p + mi, wn = mt >> 2;
                const int rowA = (mt & 3)*16 + g;
                char* ar = ar0 + wn*ARENA;
                __nv_bfloat16* sQw  = reinterpret_cast<__nv_bfloat16*>(ar + 11264);
                __nv_bfloat16* sKw  = reinterpret_cast<__nv_bfloat16*>(ar + 29696);
                __nv_bfloat16* sVTw = reinterpret_cast<__nv_bfloat16*>(ar + 48128);
                #pragma unroll
                for (int j = 0; j < 15; j++) {
                    const int c0 = (jbase+j)*8 + 2*tq;
                    const int h  = c0 / 30;
                    const int r  = c0 - h*30;          // even
                    const float b0 = sBqkv[c0], b1 = sBqkv[c0+1];
                    const float vA0 = acc[mi][j][0] + b0, vA1 = acc[mi][j][1] + b1;
                    const float vB0 = acc[mi][j][2] + b0, vB1 = acc[mi][j][3] + b1;
                    if (r < 10) {
                        *reinterpret_cast<unsigned*>(sQw + h*1152 + rowA*18 + r) =
                            pack2(vA0*QK_SCALE, vA1*QK_SCALE);
                        *reinterpret_cast<unsigned*>(sQw + h*1152 + (rowA+8)*18 + r) =
                            pack2(vB0*QK_SCALE, vB1*QK_SCALE);
                    } else if (r < 20) {
                        const int d = r - 10;
                        *reinterpret_cast<unsigned*>(sKw + h*1152 + rowA*18 + d) = pack2(vA0, vA1);
                        *reinterpret_cast<unsigned*>(sKw + h*1152 + (rowA+8)*18 + d) = pack2(vB0, vB1);
                    } else {
                        const int d = r - 20;
                        sVTw[h*1152 + d*72     + rowA]     = __float2bfloat16(vA0);
                        sVTw[h*1152 + (d+1)*72 + rowA]     = __float2bfloat16(vA1);
                        sVTw[h*1152 + d*72     + rowA + 8] = __float2bfloat16(vB0);
                        sVTw[h*1152 + (d+1)*72 + rowA + 8] = __float2bfloat16(vB1);
                    }
                }
            }
        }
        __syncthreads();

        // ---- attention: warp w == head w, both windows, reg-resident ----
        {
            const int h = w;
            for (int wn = 0; wn < 2; wn++) {
                char* ar = ar0 + wn*ARENA;
                const __nv_bfloat16* Qh = reinterpret_cast<__nv_bfloat16*>(ar + 11264) + h*1152;
                const __nv_bfloat16* Kh = reinterpret_cast<__nv_bfloat16*>(ar + 29696) + h*1152;
                const __nv_bfloat16* Vh = reinterpret_cast<__nv_bfloat16*>(ar + 48128) + h*1152;
                __nv_bfloat16*       sOw = reinterpret_cast<__nv_bfloat16*>(ar + 66560);

                #pragma unroll
                for (int pass = 0; pass < 2; pass++) {
                    float s[2][8][4];
                    unsigned qa[2][4];
                    #pragma unroll
                    for (int mi = 0; mi < 2; mi++) {
                        const __nv_bfloat16* qp = Qh + ((pass*2+mi)*16 + g)*18;
                        qa[mi][0] = *reinterpret_cast<const unsigned*>(qp + 2*tq);
                        qa[mi][1] = *reinterpret_cast<const unsigned*>(qp + 8*18 + 2*tq);
                        qa[mi][2] = *reinterpret_cast<const unsigned*>(qp + 2*tq + 8);
                        qa[mi][3] = *reinterpret_cast<const unsigned*>(qp + 8*18 + 2*tq + 8);
                    }
                    #pragma unroll
                    for (int nt = 0; nt < 8; nt++) {
                        const __nv_bfloat16* kp = Kh + (nt*8 + g)*18;
                        unsigned b0 = *reinterpret_cast<const unsigned*>(kp + 2*tq);
                        unsigned b1 = *reinterpret_cast<const unsigned*>(kp + 2*tq + 8);
                        #pragma unroll
                        for (int mi = 0; mi < 2; mi++) {
                            #pragma unroll
                            for (int e = 0; e < 4; e++) s[mi][nt][e] = 0.f;
                            mma_bf16(s[mi][nt], qa[mi], b0, b1);
                        }
                    }
                    // softmax, no max-subtraction (logits bounded << 88)
                    float invA[2], invB[2];
                    #pragma unroll
                    for (int mi = 0; mi < 2; mi++) {
                        float sA = 0.f, sB = 0.f;
                        #pragma unroll
                        for (int nt = 0; nt < 8; nt++) {
                            float e0 = __expf(s[mi][nt][0]);
                            float e1 = __expf(s[mi][nt][1]);
                            float e2 = __expf(s[mi][nt][2]);
                            float e3 = __expf(s[mi][nt][3]);
                            s[mi][nt][0]=e0; s[mi][nt][1]=e1; s[mi][nt][2]=e2; s[mi][nt][3]=e3;
                            sA += e0 + e1; sB += e2 + e3;
                        }
                        sA += __shfl_xor_sync(0xffffffffu, sA, 1);
                        sA += __shfl_xor_sync(0xffffffffu, sA, 2);
                        sB += __shfl_xor_sync(0xffffffffu, sB, 1);
                        sB += __shfl_xor_sync(0xffffffffu, sB, 2);
                        invA[mi] = 1.0f / sA;
                        invB[mi] = 1.0f / sB;
                    }
                    float o[2][2][4];
                    #pragma unroll
                    for (int mi = 0; mi < 2; mi++)
                        #pragma unroll
                        for (int nt2 = 0; nt2 < 2; nt2++)
                            #pragma unroll
                            for (int e = 0; e < 4; e++) o[mi][nt2][e] = 0.f;
                    #pragma unroll
                    for (int ks = 0; ks < 4; ks++) {
                        unsigned pa[2][4];
                        #pragma unroll
                        for (int mi = 0; mi < 2; mi++) {
                            pa[mi][0] = pack2(s[mi][2*ks  ][0], s[mi][2*ks  ][1]);
                            pa[mi][1] = pack2(s[mi][2*ks  ][2], s[mi][2*ks  ][3]);
                            pa[mi][2] = pack2(s[mi][2*ks+1][0], s[mi][2*ks+1][1]);
                            pa[mi][3] = pack2(s[mi][2*ks+1][2], s[mi][2*ks+1][3]);
                        }
                        #pragma unroll
                        for (int nt2 = 0; nt2 < 2; nt2++) {
                            const __nv_bfloat16* vp = Vh + (nt2*8 + g)*72 + ks*16;
                            unsigned b0 = *reinterpret_cast<const unsigned*>(vp + 2*tq);
                            unsigned b1 = *reinterpret_cast<const unsigned*>(vp + 2*tq + 8);
                            mma_bf16(o[0][nt2], pa[0], b0, b1);
                            mma_bf16(o[1][nt2], pa[1], b0, b1);
                        }
                    }
                    #pragma unroll
                    for (int mi = 0; mi < 2; mi++) {
                        const int row = (pass*2+mi)*16 + g;
                        #pragma unroll
                        for (int nt2 = 0; nt2 < 2; nt2++) {
                            const int dh = nt2*8 + 2*tq;
                            if (dh < 10) {
                                *reinterpret_cast<unsigned*>(sOw + row*88 + h*10 + dh) =
                                    pack2(o[mi][nt2][0]*invA[mi], o[mi][nt2][1]*invA[mi]);
                                *reinterpret_cast<unsigned*>(sOw + (row+8)*88 + h*10 + dh) =
                                    pack2(o[mi][nt2][2]*invB[mi], o[mi][nt2][3]*invB[mi]);
                            }
                        }
                    }
                }
            }
        }
        __syncthreads();

        // ---- proj GEMM M=128 + direct-global residual epilogue ----
        {
            const int p = w >> 1, nb = (w & 1) * 5;
            unsigned aB[2];
            #pragma unroll
            for (int mi = 0; mi < 2; mi++) {
                const int mt = 2*p + mi, wn = mt >> 2, lr = (mt & 3)*16;
                aB[mi] = uAr0 + wn*ARENA + 66560 + (lr + l15)*176 + (lane>>4)*16;
            }
            const unsigned bBase = uWp + (nb*8 + l7)*176 + (l15>>3)*16;
            float acc[2][5][4];
            #pragma unroll
            for (int mi = 0; mi < 2; mi++)
                #pragma unroll
                for (int j = 0; j < 5; j++)
                    #pragma unroll
                    for (int e = 0; e < 4; e++) acc[mi][j][e] = 0.f;

            #pragma unroll
            for (int ks = 0; ks < 5; ks++) {
                unsigned a0[4], a1[4];
                ldsm_x4(a0, aB[0] + ks*32);
                ldsm_x4(a1, aB[1] + ks*32);
                #pragma unroll
                for (int j = 0; j < 5; j++) {
                    unsigned b0, b1;
                    ldsm_x2(b0, b1, bBase + j*1408 + ks*32);
                    mma_bf16(acc[0][j], a0, b0, b1);
                    mma_bf16(acc[1][j], a1, b0, b1);
                }
            }
            // epilogue: y = x*inv + acc + bias, fragment layout, float2
            #pragma unroll
            for (int mi = 0; mi < 2; mi++) {
                const int mt = 2*p + mi, wn = mt >> 2;
                const int wIdx = wBase + wn;
                const int bb = wIdx >> 8, rem = wIdx & 255;
                const int wh = rem >> 4, ww = rem & 15;
                char* ar = ar0 + wn*ARENA;
                const float* sInvw = reinterpret_cast<float*>(ar + 77824);
                #pragma unroll
                for (int half = 0; half < 2; half++) {
                    const int tr = (mt & 3)*16 + g + half*8;
                    const int ti = tr >> 3, tj = tr & 7;
                    int pr, pc;
                    if (IS_GRID) { pr = ti*16 + wh; pc = tj*16 + ww; }
                    else         { pr = wh*8 + ti;  pc = ww*8 + tj;  }
                    const long pix = ((long)bb*128 + pr)*128 + pc;
                    const float inv = sInvw[tr];
                    const float* xb = x + pix*80;
                    float* yb = y + pix*80;
                    #pragma unroll
                    for (int j = 0; j < 5; j++) {
                        const int c = (nb+j)*8 + 2*tq;
                        float2 xf = *reinterpret_cast<const float2*>(xb + c);
                        float r0 = xf.x*inv + acc[mi][j][half*2]   + sBproj[c];
                        float r1 = xf.y*inv + acc[mi][j][half*2+1] + sBproj[c+1];
                        *reinterpret_cast<float2*>(yb + c) = make_float2(r0, r1);
                    }
                }
            }
        }
        __syncthreads();   // protect sInv/sXNh/sO before next iteration
    }
}

// =====================================================================
// Fused MLP (unchanged from R6/R8 passing builds).
// =====================================================================
constexpr int MLP_SMEM_BYTES = 223104;
constexpr int MLP_NCTA = TOK_TOTAL / 256;   // 2048

template<bool RELU2>
__global__ void __launch_bounds__(512, 1)
mlp_kernel(const float* __restrict__ xin, float* __restrict__ xout,
           const __nv_bfloat16* __restrict__ w1T, const __nv_bfloat16* __restrict__ w2T,
           const float* __restrict__ b2, const float* __restrict__ gamma)
{
    extern __shared__ float smf[];
    char* smb = reinterpret_cast<char*>(smf);
    __nv_bfloat16* sW1T  = reinterpret_cast<__nv_bfloat16*>(smb);            // [320][88]
    __nv_bfloat16* sW2T  = reinterpret_cast<__nv_bfloat16*>(smb + 56320);    // [80][344]
    __nv_bfloat16* sXNh  = reinterpret_cast<__nv_bfloat16*>(smb + 111360);   // [128][88]
    __nv_bfloat16* sH    = reinterpret_cast<__nv_bfloat16*>(smb + 133888);   // [128][344]
    float*         sOutA = reinterpret_cast<float*>(smb + 133888);           // alias [128][81]
    float*         sOutB = reinterpret_cast<float*>(smb + 175360);           // alias [128][81]
    float*         sInv  = reinterpret_cast<float*>(smb + 221952);           // [128]
    float*         sB2   = reinterpret_cast<float*>(smb + 222464);
    float*         sG    = reinterpret_cast<float*>(smb + 222784);

    const int tid = threadIdx.x;
    const int w = tid >> 5, lane = tid & 31;
    const int g = lane >> 2, tq = lane & 3;
    const int l15 = lane & 15, l7 = lane & 7;

    {
        const float4* s1 = reinterpret_cast<const float4*>(w1T);
        float4* d1 = reinterpret_cast<float4*>(sW1T);
        for (int i = tid; i < 3520; i += 512) d1[i] = s1[i];
        const float4* s2 = reinterpret_cast<const float4*>(w2T);
        float4* d2 = reinterpret_cast<float4*>(sW2T);
        for (int i = tid; i < 3440; i += 512) d2[i] = s2[i];
        if (tid < 80) { sB2[tid] = b2[tid]; sG[tid] = gamma[tid]; }
    }

    const unsigned uXNh = smem_u32(sXNh);
    const unsigned uW1  = smem_u32(sW1T);
    const unsigned uH   = smem_u32(sH);
    const unsigned uW2  = smem_u32(sW2T);

    for (int st = 0; st < 2; st++) {
        const long tokBase = ((long)blockIdx.x*2 + st) * 128;

        {
            const int t = tid >> 2, lg = tid & 3;
            const float4* xr = reinterpret_cast<const float4*>(xin + (tokBase + t)*80) + lg*5;
            float v[20]; float ss = 0.f;
            #pragma unroll
            for (int u = 0; u < 5; u++) {
                float4 f = xr[u];
                v[4*u]=f.x; v[4*u+1]=f.y; v[4*u+2]=f.z; v[4*u+3]=f.w;
                ss += f.x*f.x + f.y*f.y + f.z*f.z + f.w*f.w;
            }
            ss += __shfl_xor_sync(0xffffffffu, ss, 1);
            ss += __shfl_xor_sync(0xffffffffu, ss, 2);
            const float inv = rsqrtf(fmaxf(ss, 1e-24f));
            unsigned* xh = reinterpret_cast<unsigned*>(sXNh + t*88 + lg*20);
            #pragma unroll
            for (int u = 0; u < 10; u++) xh[u] = pack2(v[2*u]*inv, v[2*u+1]*inv);
            if (lg == 0) sInv[t] = inv;
        }
        __syncthreads();

        {
            const int mp = w & 3;
            const int ng = w >> 2;
            const unsigned aBase = uXNh + (mp*32 + l15)*176 + (lane>>4)*16;
            const unsigned bBase = uW1 + (ng*80 + l7)*176 + (l15>>3)*16;
            float acc[2][10][4];
            #pragma unroll
            for (int mi = 0; mi < 2; mi++)
                #pragma unroll
                for (int j = 0; j < 10; j++)
                    #pragma unroll
                    for (int e = 0; e < 4; e++) acc[mi][j][e] = 0.f;

            #pragma unroll
            for (int ks = 0; ks < 5; ks++) {
                unsigned a[2][4];
                ldsm_x4(a[0], aBase + ks*32);
                ldsm_x4(a[1], aBase + 16*176 + ks*32);
                #pragma unroll
                for (int j = 0; j < 10; j++) {
                    unsigned b0, b1;
                    ldsm_x2(b0, b1, bBase + j*1408 + ks*32);
                    mma_bf16(acc[0][j], a[0], b0, b1);
                    mma_bf16(acc[1][j], a[1], b0, b1);
                }
            }
            #pragma unroll
            for (int mi = 0; mi < 2; mi++) {
                const int r0 = mp*32 + mi*16 + g;
                #pragma unroll
                for (int j = 0; j < 10; j++) {
                    const int c = (ng*10+j)*8 + 2*tq;
                    *reinterpret_cast<unsigned*>(sH + r0*344 + c) =
                        pack2(fmaxf(acc[mi][j][0], 0.f), fmaxf(acc[mi][j][1], 0.f));
                    *reinterpret_cast<unsigned*>(sH + (r0+8)*344 + c) =
                        pack2(fmaxf(acc[mi][j][2], 0.f), fmaxf(acc[mi][j][3], 0.f));
                }
            }
        }
        __syncthreads();

        {
            const int mp = w & 3;
            const int ng = (w >> 2) & 1;
            const int kh = w >> 3;
            const unsigned aBase = uH + (mp*32 + l15)*688 + (lane>>4)*16 + kh*320;
            const unsigned bBase = uW2 + (ng*40 + l7)*688 + (l15>>3)*16 + kh*320;
            float acc2[2][5][4];
            #pragma unroll
            for (int mi = 0; mi < 2; mi++)
                #pragma unroll
                for (int j = 0; j < 5; j++)
                    #pragma unroll
                    for (int e = 0; e < 4; e++) acc2[mi][j][e] = 0.f;

            #pragma unroll
            for (int ks = 0; ks < 10; ks++) {
                unsigned a[2][4];
                ldsm_x4(a[0], aBase + ks*32);
                ldsm_x4(a[1], aBase + 16*688 + ks*32);
                #pragma unroll
                for (int j = 0; j < 5; j++) {
                    unsigned b0, b1;
                    ldsm_x2(b0, b1, bBase + j*5504 + ks*32);
                    mma_bf16(acc2[0][j], a[0], b0, b1);
                    mma_bf16(acc2[1][j], a[1], b0, b1);
                }
            }
            __syncthreads();
            float* sOut = kh ? sOutB : sOutA;
            #pragma unroll
            for (int mi = 0; mi < 2; mi++) {
                const int r0 = mp*32 + mi*16 + g;
                #pragma unroll
                for (int j = 0; j < 5; j++) {
                    const int c = (ng*5+j)*8 + 2*tq;
                    sOut[r0*81 + c]         = acc2[mi][j][0];
                    sOut[r0*81 + c + 1]     = acc2[mi][j][1];
                    sOut[(r0+8)*81 + c]     = acc2[mi][j][2];
                    sOut[(r0+8)*81 + c + 1] = acc2[mi][j][3];
                }
            }
        }
        __syncthreads();

        {
            const int t = tid >> 2, lg = tid & 3;
            const float inv = sInv[t];
            const float4* xr = reinterpret_cast<const float4*>(xin + (tokBase + t)*80) + lg*5;
            float4* yr = reinterpret_cast<float4*>(xout + (tokBase + t)*80) + lg*5;
            #pragma unroll
            for (int u = 0; u < 5; u++) {
                float4 xf = xr[u];
                float xv[4] = {xf.x, xf.y, xf.z, xf.w};
                float f[4];
                #pragma unroll
                for (int e = 0; e < 4; e++) {
                    const int idx = lg*20 + 4*u + e;
                    float hv = sOutA[t*81 + idx] + sOutB[t*81 + idx] + sB2[idx];
                    if (RELU2) hv = fmaxf(hv, 0.f);
                    f[e] = xv[e]*inv + hv * sG[idx];
                }
                yr[u] = make_float4(f[0], f[1], f[2], f[3]);
            }
        }
        __syncthreads();
    }
}

// =====================================================================
extern "C" void kernel_launch(void* const* d_in, const int* in_sizes, int n_in,
                              void* d_out, int out_size)
{
    const float* x       = (const float*)d_in[0];
    const float* bw_qkv  = (const float*)d_in[1];
    const float* bb_qkv  = (const float*)d_in[2];
    const float* bw_proj = (const float*)d_in[3];
    const float* bb_proj = (const float*)d_in[4];
    const float* b_gamma = (const float*)d_in[5];
    const float* bw_mlp1 = (const float*)d_in[6];
    const float* bw_mlp2 = (const float*)d_in[7];
    const float* bb_mlp2 = (const float*)d_in[8];
    const float* gw_qkv  = (const float*)d_in[9];
    const float* gb_qkv  = (const float*)d_in[10];
    const float* gw_proj = (const float*)d_in[11];
    const float* gb_proj = (const float*)d_in[12];
    const float* g_gamma = (const float*)d_in[13];
    const float* gw_mlp1 = (const float*)d_in[14];
    const float* gw_mlp2 = (const float*)d_in[15];
    const float* gb_mlp2 = (const float*)d_in[16];
    float* out = (float*)d_out;

    float *buf1 = nullptr, *buf2 = nullptr;
    cudaGetSymbolAddress((void**)&buf1, g_buf1);
    cudaGetSymbolAddress((void**)&buf2, g_buf2);

    __nv_bfloat16 *qkvT_b, *projT_b, *qkvT_g, *projT_g, *w1T_b, *w2T_b, *w1T_g, *w2T_g;
    cudaGetSymbolAddress((void**)&qkvT_b,  g_qkvT_b);
    cudaGetSymbolAddress((void**)&projT_b, g_projT_b);
    cudaGetSymbolAddress((void**)&qkvT_g,  g_qkvT_g);
    cudaGetSymbolAddress((void**)&projT_g, g_projT_g);
    cudaGetSymbolAddress((void**)&w1T_b,   g_w1T_b);
    cudaGetSymbolAddress((void**)&w2T_b,   g_w2T_b);
    cudaGetSymbolAddress((void**)&w1T_g,   g_w1T_g);
    cudaGetSymbolAddress((void**)&w2T_g,   g_w2T_g);

    const size_t smA = ATTN_SMEM_BYTES;   // 213,760 B
    const size_t smM = MLP_SMEM_BYTES;    // 223,104 B
    cudaFuncSetAttribute(attn_kernel<false>, cudaFuncAttributeMaxDynamicSharedMemorySize, (int)smA);
    cudaFuncSetAttribute(attn_kernel<true>,  cudaFuncAttributeMaxDynamicSharedMemorySize, (int)smA);
    cudaFuncSetAttribute(mlp_kernel<true>,   cudaFuncAttributeMaxDynamicSharedMemorySize, (int)smM);
    cudaFuncSetAttribute(mlp_kernel<false>,  cudaFuncAttributeMaxDynamicSharedMemorySize, (int)smM);

    // ---- single prepass launch: all 8 weight panels ----
    {
        dim3 grid(16, 8);
        prep_all<<<grid, 256>>>(bw_qkv, bw_proj, gw_qkv, gw_proj,
                                bw_mlp1, bw_mlp2, gw_mlp1, gw_mlp2,
                                qkvT_b, projT_b, qkvT_g, projT_g,
                                w1T_b, w2T_b, w1T_g, w2T_g);
    }

    // stage 1: block SA
    attn_kernel<false><<<ATTN_NCTA, 256, smA>>>(x,    buf1, qkvT_b, bb_qkv, projT_b, bb_proj);
    mlp_kernel<true>  <<<MLP_NCTA,  512, smM>>>(buf1, buf2, w1T_b, w2T_b, bb_mlp2, b_gamma);
    // stage 2: grid SA
    attn_kernel<true> <<<ATTN_NCTA, 256, smA>>>(buf2, buf1, qkvT_g, gb_qkv, projT_g, gb_proj);
    mlp_kernel<false> <<<MLP_NCTA,  512, smM>>>(buf1, out, w1T_g, w2T_g, gb_mlp2, g_gamma);
}

// round 13
// speedup vs baseline: 1.3488x; 1.0172x over previous
#include <cuda_runtime.h>
#include <cuda_bf16.h>

// ---------------- problem constants ----------------
// x: (32, 128, 128, 80) fp32; C=80, NH=8, DH=10, WIN=GRID=8 -> 64-token windows
// windows per stage: 32 * 16 * 16 = 8192 ; tokens total 524288

#define TOK_TOTAL (32*128*128)

__device__ float g_buf1[(size_t)TOK_TOTAL * 80];
__device__ float g_buf2[(size_t)TOK_TOTAL * 80];

// pre-converted transposed bf16 weight panels (written by prep_all)
__device__ __align__(16) __nv_bfloat16 g_qkvT_b[240*88];
__device__ __align__(16) __nv_bfloat16 g_projT_b[80*88];
__device__ __align__(16) __nv_bfloat16 g_qkvT_g[240*88];
__device__ __align__(16) __nv_bfloat16 g_projT_g[80*88];
__device__ __align__(16) __nv_bfloat16 g_w1T_b[320*88];
__device__ __align__(16) __nv_bfloat16 g_w2T_b[80*344];
__device__ __align__(16) __nv_bfloat16 g_w1T_g[320*88];
__device__ __align__(16) __nv_bfloat16 g_w2T_g[80*344];

// ---------------- helpers ----------------
__device__ __forceinline__ unsigned pack2(float lo, float hi) {
    __nv_bfloat162 t = __floats2bfloat162_rn(lo, hi);
    return *reinterpret_cast<unsigned*>(&t);
}

__device__ __forceinline__ void mma_bf16(float* c, const unsigned* a, unsigned b0, unsigned b1) {
    asm volatile(
        "mma.sync.aligned.m16n8k16.row.col.f32.bf16.bf16.f32 "
        "{%0,%1,%2,%3}, {%4,%5,%6,%7}, {%8,%9}, {%0,%1,%2,%3};\n"
        : "+f"(c[0]), "+f"(c[1]), "+f"(c[2]), "+f"(c[3])
        : "r"(a[0]), "r"(a[1]), "r"(a[2]), "r"(a[3]), "r"(b0), "r"(b1));
}

__device__ __forceinline__ unsigned smem_u32(const void* p) {
    return (unsigned)__cvta_generic_to_shared(p);
}

__device__ __forceinline__ void ldsm_x4(unsigned* r, unsigned addr) {
    asm volatile("ldmatrix.sync.aligned.m8n8.x4.shared.b16 {%0,%1,%2,%3}, [%4];\n"
                 : "=r"(r[0]), "=r"(r[1]), "=r"(r[2]), "=r"(r[3]) : "r"(addr));
}
__device__ __forceinline__ void ldsm_x2(unsigned& r0, unsigned& r1, unsigned addr) {
    asm volatile("ldmatrix.sync.aligned.m8n8.x2.shared.b16 {%0,%1}, [%2];\n"
                 : "=r"(r0), "=r"(r1) : "r"(addr));
}

// ---------------- single prepass launch: all 8 weight panels ----------------
__global__ void prep_all(
    const float* s0, const float* s1, const float* s2, const float* s3,
    const float* s4, const float* s5, const float* s6, const float* s7,
    __nv_bfloat16* d0, __nv_bfloat16* d1, __nv_bfloat16* d2, __nv_bfloat16* d3,
    __nv_bfloat16* d4, __nv_bfloat16* d5, __nv_bfloat16* d6, __nv_bfloat16* d7)
{
    const int r = blockIdx.y;
    const float* src; __nv_bfloat16* dst; int K, N, stride, rows;
    switch (r) {
        case 0: src=s0; dst=d0; K=80;  N=240; stride=88;  rows=240; break;
        case 1: src=s1; dst=d1; K=80;  N=80;  stride=88;  rows=80;  break;
        case 2: src=s2; dst=d2; K=80;  N=240; stride=88;  rows=240; break;
        case 3: src=s3; dst=d3; K=80;  N=80;  stride=88;  rows=80;  break;
        case 4: src=s4; dst=d4; K=80;  N=320; stride=88;  rows=320; break;
        case 5: src=s5; dst=d5; K=320; N=80;  stride=344; rows=80;  break;
        case 6: src=s6; dst=d6; K=80;  N=320; stride=88;  rows=320; break;
        default:src=s7; dst=d7; K=320; N=80;  stride=344; rows=80;  break;
    }
    const int total = rows * stride;
    for (int idx = blockIdx.x*256 + threadIdx.x; idx < total; idx += gridDim.x*256) {
        int n = idx / stride, k = idx - n*stride;
        float v = (n < N && k < K) ? src[k*N + n] : 0.f;
        dst[idx] = __float2bfloat16(v);
    }
}

// =====================================================================
// Fused window attention: 256 threads = 8 warps, M=128 supertiles
// (2 windows per iteration, 8 windows per CTA over 4 iterations).
// R11 delta: B-operand ldmatrix.x4 pairing (2 j-tiles per ldsm) in
// QKV/proj; V fragments via ldmatrix.x2 in PV.
// smem layout identical to R10 (213760 B).
// =====================================================================
constexpr int ATTN_SMEM_BYTES = 213760;
constexpr int ATTN_WIN_PER_CTA = 8;
constexpr int ATTN_NCTA = 8192 / ATTN_WIN_PER_CTA;     // 1024
constexpr int ARENA = 78080;
constexpr float QK_SCALE = 0.31622776601683794f;       // DH^-0.5

template<bool IS_GRID>
__global__ void __launch_bounds__(256, 1)
attn_kernel(const float* __restrict__ x, float* __restrict__ y,
            const __nv_bfloat16* __restrict__ wqkvT, const float* __restrict__ bqkv,
            const __nv_bfloat16* __restrict__ wprojT, const float* __restrict__ bproj)
{
    extern __shared__ float smf[];
    char* smb = reinterpret_cast<char*>(smf);
    __nv_bfloat16* sWqkvT  = reinterpret_cast<__nv_bfloat16*>(smb);           // [240][88]
    __nv_bfloat16* sWprojT = reinterpret_cast<__nv_bfloat16*>(smb + 42240);   // [80][88]
    float*         sBqkv   = reinterpret_cast<float*>(smb + 56320);           // [240]
    float*         sBproj  = reinterpret_cast<float*>(smb + 57280);           // [80]
    char*          ar0     = smb + 57600;

    const int tid  = threadIdx.x;
    const int w    = tid >> 5, lane = tid & 31;
    const int g    = lane >> 2, tq  = lane & 3;
    const int l15  = lane & 15, l7 = lane & 7;
    const int joff = lane >> 4;            // x4 B pairing: j-offset 0/1
    const int khalf = (lane >> 3) & 1;     // k-half 0/1

    // ---- one-time staging + pad zeroing ----
    {
        const float4* s1 = reinterpret_cast<const float4*>(wqkvT);
        float4* d1 = reinterpret_cast<float4*>(sWqkvT);
        for (int i = tid; i < 2640; i += 256) d1[i] = s1[i];
        const float4* s2 = reinterpret_cast<const float4*>(wprojT);
        float4* d2 = reinterpret_cast<float4*>(sWprojT);
        for (int i = tid; i < 880; i += 256) d2[i] = s2[i];
        if (tid < 240) sBqkv[tid] = bqkv[tid];
        if (tid < 80)  sBproj[tid] = bproj[tid];
        // zero k-pads d=10..17 of sQ/sK in BOTH arenas (never clobbered)
        for (int i = tid; i < 4096; i += 256) {
            int a = i >> 11, r = i & 2047;
            int row = r >> 2, p = r & 3;
            char* ar = ar0 + a*ARENA;
            reinterpret_cast<unsigned*>(reinterpret_cast<__nv_bfloat16*>(ar + 11264) + row*18 + 10)[p] = 0u;
            reinterpret_cast<unsigned*>(reinterpret_cast<__nv_bfloat16*>(ar + 29696) + row*18 + 10)[p] = 0u;
        }
    }

    const unsigned uAr0 = smem_u32(ar0);
    const unsigned uWq  = smem_u32(sWqkvT);
    const unsigned uWp  = smem_u32(sWprojT);

    for (int it = 0; it < 4; it++) {
        const int wBase = blockIdx.x * ATTN_WIN_PER_CTA + it*2;

        // ---- load + l2norm: 2 threads per token (128 tokens) ----
        {
            const int t  = tid >> 1, lg = tid & 1;
            const int wn = t >> 6, tr = t & 63;
            const int wIdx = wBase + wn;
            const int bb = wIdx >> 8, rem = wIdx & 255;
            const int wh = rem >> 4, ww = rem & 15;
            const int ti = tr >> 3, tj = tr & 7;
            int pr, pc;
            if (IS_GRID) { pr = ti*16 + wh; pc = tj*16 + ww; }
            else         { pr = wh*8 + ti;  pc = ww*8 + tj;  }
            const long pix = ((long)bb*128 + pr)*128 + pc;
            const float4* xr = reinterpret_cast<const float4*>(x + pix*80) + lg*10;
            float v[40]; float ss = 0.f;
            #pragma unroll
            for (int u = 0; u < 10; u++) {
                float4 f = xr[u];
                v[4*u+0]=f.x; v[4*u+1]=f.y; v[4*u+2]=f.z; v[4*u+3]=f.w;
                ss += f.x*f.x + f.y*f.y + f.z*f.z + f.w*f.w;
            }
            ss += __shfl_xor_sync(0xffffffffu, ss, 1);
            const float inv = rsqrtf(fmaxf(ss, 1e-24f));
            char* ar = ar0 + wn*ARENA;
            unsigned* xh = reinterpret_cast<unsigned*>(
                reinterpret_cast<__nv_bfloat16*>(ar) + tr*88 + lg*40);
            #pragma unroll
            for (int u = 0; u < 20; u++) xh[u] = pack2(v[2*u]*inv, v[2*u+1]*inv);
            if (lg == 0) reinterpret_cast<float*>(ar + 77824)[tr] = inv;
        }
        __syncthreads();

        // ---- QKV GEMM M=128: 8 warps = 4 mt-pairs x 2 j-groups of 15 ----
        // B via ldmatrix.x4 pairs (7 pairs + 1 x2 tail)
        {
            const int p = w >> 1, jbase = (w & 1) * 15;
            unsigned aB[2];
            #pragma unroll
            for (int mi = 0; mi < 2; mi++) {
                const int mt = 2*p + mi, wn = mt >> 2, lr = (mt & 3)*16;
                aB[mi] = uAr0 + wn*ARENA + (lr + l15)*176 + (lane>>4)*16;
            }
            const unsigned bB4 = uWq + ((jbase + joff)*8 + l7)*176 + khalf*16;
            const unsigned bX2 = uWq + ((jbase + 14)*8 + l7)*176 + (l15>>3)*16;
            float acc[2][15][4];
            #pragma unroll
            for (int mi = 0; mi < 2; mi++)
                #pragma unroll
                for (int j = 0; j < 15; j++)
                    #pragma unroll
                    for (int e = 0; e < 4; e++) acc[mi][j][e] = 0.f;

            #pragma unroll
            for (int ks = 0; ks < 5; ks++) {
                unsigned a0[4], a1[4];
                ldsm_x4(a0, aB[0] + ks*32);
                ldsm_x4(a1, aB[1] + ks*32);
                #pragma unroll
                for (int p2 = 0; p2 < 7; p2++) {
                    unsigned b[4];
                    ldsm_x4(b, bB4 + p2*2816 + ks*32);   // 2 j-tiles = 16 rows * 176B
                    mma_bf16(acc[0][2*p2],   a0, b[0], b[1]);
                    mma_bf16(acc[1][2*p2],   a1, b[0], b[1]);
                    mma_bf16(acc[0][2*p2+1], a0, b[2], b[3]);
                    mma_bf16(acc[1][2*p2+1], a1, b[2], b[3]);
                }
                unsigned b0, b1;
                ldsm_x2(b0, b1, bX2 + ks*32);
                mma_bf16(acc[0][14], a0, b0, b1);
                mma_bf16(acc[1][14], a1, b0, b1);
            }
            // packed scatter (c0 even; segment boundaries odd -> pair never splits)
            #pragma unroll
            for (int mi = 0; mi < 2; mi++) {
                const int mt = 2*p + mi, wn = mt >> 2;
                const int rowA = (mt & 3)*16 + g;
                char* ar = ar0 + wn*ARENA;
                __nv_bfloat16* sQw  = reinterpret_cast<__nv_bfloat16*>(ar + 11264);
                __nv_bfloat16* sKw  = reinterpret_cast<__nv_bfloat16*>(ar + 29696);
                __nv_bfloat16* sVTw = reinterpret_cast<__nv_bfloat16*>(ar + 48128);
                #pragma unroll
                for (int j = 0; j < 15; j++) {
                    const int c0 = (jbase+j)*8 + 2*tq;
                    const int h  = c0 / 30;
                    const int r  = c0 - h*30;          // even
                    const float b0 = sBqkv[c0], b1 = sBqkv[c0+1];
                    const float vA0 = acc[mi][j][0] + b0, vA1 = acc[mi][j][1] + b1;
                    const float vB0 = acc[mi][j][2] + b0, vB1 = acc[mi][j][3] + b1;
                    if (r < 10) {
                        *reinterpret_cast<unsigned*>(sQw + h*1152 + rowA*18 + r) =
                            pack2(vA0*QK_SCALE, vA1*QK_SCALE);
                        *reinterpret_cast<unsigned*>(sQw + h*1152 + (rowA+8)*18 + r) =
                            pack2(vB0*QK_SCALE, vB1*QK_SCALE);
                    } else if (r < 20) {
                        const int d = r - 10;
                        *reinterpret_cast<unsigned*>(sKw + h*1152 + rowA*18 + d) = pack2(vA0, vA1);
                        *reinterpret_cast<unsigned*>(sKw + h*1152 + (rowA+8)*18 + d) = pack2(vB0, vB1);
                    } else {
                        const int d = r - 20;
                        sVTw[h*1152 + d*72     + rowA]     = __float2bfloat16(vA0);
                        sVTw[h*1152 + (d+1)*72 + rowA]     = __float2bfloat16(vA1);
                        sVTw[h*1152 + d*72     + rowA + 8] = __float2bfloat16(vB0);
                        sVTw[h*1152 + (d+1)*72 + rowA + 8] = __float2bfloat16(vB1);
                    }
                }
            }
        }
        __syncthreads();

        // ---- attention: warp w == head w, both windows, reg-resident ----
        {
            const int h = w;
            for (int wn = 0; wn < 2; wn++) {
                char* ar = ar0 + wn*ARENA;
                const __nv_bfloat16* Qh = reinterpret_cast<__nv_bfloat16*>(ar + 11264) + h*1152;
                const __nv_bfloat16* Kh = reinterpret_cast<__nv_bfloat16*>(ar + 29696) + h*1152;
                __nv_bfloat16*       sOw = reinterpret_cast<__nv_bfloat16*>(ar + 66560);
                // V fragment ldsm base: [8][16][72] bf16, row stride 144 B (16-aligned)
                const unsigned vBase = uAr0 + wn*ARENA + 48128 + h*2304
                                     + l7*144 + khalf*16;

                #pragma unroll
                for (int pass = 0; pass < 2; pass++) {
                    float s[2][8][4];
                    unsigned qa[2][4];
                    #pragma unroll
                    for (int mi = 0; mi < 2; mi++) {
                        const __nv_bfloat16* qp = Qh + ((pass*2+mi)*16 + g)*18;
                        qa[mi][0] = *reinterpret_cast<const unsigned*>(qp + 2*tq);
                        qa[mi][1] = *reinterpret_cast<const unsigned*>(qp + 8*18 + 2*tq);
                        qa[mi][2] = *reinterpret_cast<const unsigned*>(qp + 2*tq + 8);
                        qa[mi][3] = *reinterpret_cast<const unsigned*>(qp + 8*18 + 2*tq + 8);
                    }
                    #pragma unroll
                    for (int nt = 0; nt < 8; nt++) {
                        const __nv_bfloat16* kp = Kh + (nt*8 + g)*18;
                        unsigned b0 = *reinterpret_cast<const unsigned*>(kp + 2*tq);
                        unsigned b1 = *reinterpret_cast<const unsigned*>(kp + 2*tq + 8);
                        #pragma unroll
                        for (int mi = 0; mi < 2; mi++) {
                            #pragma unroll
                            for (int e = 0; e < 4; e++) s[mi][nt][e] = 0.f;
                            mma_bf16(s[mi][nt], qa[mi], b0, b1);
                        }
                    }
                    // softmax, no max-subtraction (logits bounded << 88)
                    float invA[2], invB[2];
                    #pragma unroll
                    for (int mi = 0; mi < 2; mi++) {
                        float sA = 0.f, sB = 0.f;
                        #pragma unroll
                        for (int nt = 0; nt < 8; nt++) {
                            float e0 = __expf(s[mi][nt][0]);
                            float e1 = __expf(s[mi][nt][1]);
                            float e2 = __expf(s[mi][nt][2]);
                            float e3 = __expf(s[mi][nt][3]);
                            s[mi][nt][0]=e0; s[mi][nt][1]=e1; s[mi][nt][2]=e2; s[mi][nt][3]=e3;
                            sA += e0 + e1; sB += e2 + e3;
                        }
                        sA += __shfl_xor_sync(0xffffffffu, sA, 1);
                        sA += __shfl_xor_sync(0xffffffffu, sA, 2);
                        sB += __shfl_xor_sync(0xffffffffu, sB, 1);
                        sB += __shfl_xor_sync(0xffffffffu, sB, 2);
                        invA[mi] = 1.0f / sA;
                        invB[mi] = 1.0f / sB;
                    }
                    float o[2][2][4];
                    #pragma unroll
                    for (int mi = 0; mi < 2; mi++)
                        #pragma unroll
                        for (int nt2 = 0; nt2 < 2; nt2++)
                            #pragma unroll
                            for (int e = 0; e < 4; e++) o[mi][nt2][e] = 0.f;
                    #pragma unroll
                    for (int ks = 0; ks < 4; ks++) {
                        unsigned pa[2][4];
                        #pragma unroll
                        for (int mi = 0; mi < 2; mi++) {
                            pa[mi][0] = pack2(s[mi][2*ks  ][0], s[mi][2*ks  ][1]);
                            pa[mi][1] = pack2(s[mi][2*ks  ][2], s[mi][2*ks  ][3]);
                            pa[mi][2] = pack2(s[mi][2*ks+1][0], s[mi][2*ks+1][1]);
                            pa[mi][3] = pack2(s[mi][2*ks+1][2], s[mi][2*ks+1][3]);
                        }
                        #pragma unroll
                        for (int nt2 = 0; nt2 < 2; nt2++) {
                            unsigned vb0, vb1;
                            ldsm_x2(vb0, vb1, vBase + nt2*1152 + ks*32);
                            mma_bf16(o[0][nt2], pa[0], vb0, vb1);
                            mma_bf16(o[1][nt2], pa[1], vb0, vb1);
                        }
                    }
                    #pragma unroll
                    for (int mi = 0; mi < 2; mi++) {
                        const int row = (pass*2+mi)*16 + g;
                        #pragma unroll
                        for (int nt2 = 0; nt2 < 2; nt2++) {
                            const int dh = nt2*8 + 2*tq;
                            if (dh < 10) {
                                *reinterpret_cast<unsigned*>(sOw + row*88 + h*10 + dh) =
                                    pack2(o[mi][nt2][0]*invA[mi], o[mi][nt2][1]*invA[mi]);
                                *reinterpret_cast<unsigned*>(sOw + (row+8)*88 + h*10 + dh) =
                                    pack2(o[mi][nt2][2]*invB[mi], o[mi][nt2][3]*invB[mi]);
                            }
                        }
                    }
                }
            }
        }
        __syncthreads();

        // ---- proj GEMM M=128 + direct-global residual epilogue ----
        // B via ldmatrix.x4 pairs (2 pairs + 1 x2 tail)
        {
            const int p = w >> 1, nb = (w & 1) * 5;
            unsigned aB[2];
            #pragma unroll
            for (int mi = 0; mi < 2; mi++) {
                const int mt = 2*p + mi, wn = mt >> 2, lr = (mt & 3)*16;
                aB[mi] = uAr0 + wn*ARENA + 66560 + (lr + l15)*176 + (lane>>4)*16;
            }
            const unsigned bB4 = uWp + ((nb + joff)*8 + l7)*176 + khalf*16;
            const unsigned bX2 = uWp + ((nb + 4)*8 + l7)*176 + (l15>>3)*16;
            float acc[2][5][4];
            #pragma unroll
            for (int mi = 0; mi < 2; mi++)
                #pragma unroll
                for (int j = 0; j < 5; j++)
                    #pragma unroll
                    for (int e = 0; e < 4; e++) acc[mi][j][e] = 0.f;

            #pragma unroll
            for (int ks = 0; ks < 5; ks++) {
                unsigned a0[4], a1[4];
                ldsm_x4(a0, aB[0] + ks*32);
                ldsm_x4(a1, aB[1] + ks*32);
                #pragma unroll
                for (int p2 = 0; p2 < 2; p2++) {
                    unsigned b[4];
                    ldsm_x4(b, bB4 + p2*2816 + ks*32);
                    mma_bf16(acc[0][2*p2],   a0, b[0], b[1]);
                    mma_bf16(acc[1][2*p2],   a1, b[0], b[1]);
                    mma_bf16(acc[0][2*p2+1], a0, b[2], b[3]);
                    mma_bf16(acc[1][2*p2+1], a1, b[2], b[3]);
                }
                unsigned b0, b1;
                ldsm_x2(b0, b1, bX2 + ks*32);
                mma_bf16(acc[0][4], a0, b0, b1);
                mma_bf16(acc[1][4], a1, b0, b1);
            }
            // epilogue: y = x*inv + acc + bias, fragment layout, float2
            #pragma unroll
            for (int mi = 0; mi < 2; mi++) {
                const int mt = 2*p + mi, wn = mt >> 2;
                const int wIdx = wBase + wn;
                const int bb = wIdx >> 8, rem = wIdx & 255;
                const int wh = rem >> 4, ww = rem & 15;
                char* ar = ar0 + wn*ARENA;
                const float* sInvw = reinterpret_cast<float*>(ar + 77824);
                #pragma unroll
                for (int half = 0; half < 2; half++) {
                    const int tr = (mt & 3)*16 + g + half*8;
                    const int ti = tr >> 3, tj = tr & 7;
                    int pr, pc;
                    if (IS_GRID) { pr = ti*16 + wh; pc = tj*16 + ww; }
                    else         { pr = wh*8 + ti;  pc = ww*8 + tj;  }
                    const long pix = ((long)bb*128 + pr)*128 + pc;
                    const float inv = sInvw[tr];
                    const float* xb = x + pix*80;
                    float* yb = y + pix*80;
                    #pragma unroll
                    for (int j = 0; j < 5; j++) {
                        const int c = (nb+j)*8 + 2*tq;
                        float2 xf = *reinterpret_cast<const float2*>(xb + c);
                        float r0 = xf.x*inv + acc[mi][j][half*2]   + sBproj[c];
                        float r1 = xf.y*inv + acc[mi][j][half*2+1] + sBproj[c+1];
                        *reinterpret_cast<float2*>(yb + c) = make_float2(r0, r1);
                    }
                }
            }
        }
        __syncthreads();   // protect sInv/sXNh/sO before next iteration
    }
}

// =====================================================================
// Fused MLP: M=128 supertiles, 512 thr.  R11 delta: B-operand
// ldmatrix.x4 pairing in both GEMMs.
// =====================================================================
constexpr int MLP_SMEM_BYTES = 223104;
constexpr int MLP_NCTA = TOK_TOTAL / 256;   // 2048

template<bool RELU2>
__global__ void __launch_bounds__(512, 1)
mlp_kernel(const float* __restrict__ xin, float* __restrict__ xout,
           const __nv_bfloat16* __restrict__ w1T, const __nv_bfloat16* __restrict__ w2T,
           const float* __restrict__ b2, const float* __restrict__ gamma)
{
    extern __shared__ float smf[];
    char* smb = reinterpret_cast<char*>(smf);
    __nv_bfloat16* sW1T  = reinterpret_cast<__nv_bfloat16*>(smb);            // [320][88]
    __nv_bfloat16* sW2T  = reinterpret_cast<__nv_bfloat16*>(smb + 56320);    // [80][344]
    __nv_bfloat16* sXNh  = reinterpret_cast<__nv_bfloat16*>(smb + 111360);   // [128][88]
    __nv_bfloat16* sH    = reinterpret_cast<__nv_bfloat16*>(smb + 133888);   // [128][344]
    float*         sOutA = reinterpret_cast<float*>(smb + 133888);           // alias [128][81]
    float*         sOutB = reinterpret_cast<float*>(smb + 175360);           // alias [128][81]
    float*         sInv  = reinterpret_cast<float*>(smb + 221952);           // [128]
    float*         sB2   = reinterpret_cast<float*>(smb + 222464);
    float*         sG    = reinterpret_cast<float*>(smb + 222784);

    const int tid = threadIdx.x;
    const int w = tid >> 5, lane = tid & 31;
    const int g = lane >> 2, tq = lane & 3;
    const int l15 = lane & 15, l7 = lane & 7;
    const int joff = lane >> 4;
    const int khalf = (lane >> 3) & 1;

    {
        const float4* s1 = reinterpret_cast<const float4*>(w1T);
        float4* d1 = reinterpret_cast<float4*>(sW1T);
        for (int i = tid; i < 3520; i += 512) d1[i] = s1[i];
        const float4* s2 = reinterpret_cast<const float4*>(w2T);
        float4* d2 = reinterpret_cast<float4*>(sW2T);
        for (int i = tid; i < 3440; i += 512) d2[i] = s2[i];
        if (tid < 80) { sB2[tid] = b2[tid]; sG[tid] = gamma[tid]; }
    }

    const unsigned uXNh = smem_u32(sXNh);
    const unsigned uW1  = smem_u32(sW1T);
    const unsigned uH   = smem_u32(sH);
    const unsigned uW2  = smem_u32(sW2T);

    for (int st = 0; st < 2; st++) {
        const long tokBase = ((long)blockIdx.x*2 + st) * 128;

        {
            const int t = tid >> 2, lg = tid & 3;
            const float4* xr = reinterpret_cast<const float4*>(xin + (tokBase + t)*80) + lg*5;
            float v[20]; float ss = 0.f;
            #pragma unroll
            for (int u = 0; u < 5; u++) {
                float4 f = xr[u];
                v[4*u]=f.x; v[4*u+1]=f.y; v[4*u+2]=f.z; v[4*u+3]=f.w;
                ss += f.x*f.x + f.y*f.y + f.z*f.z + f.w*f.w;
            }
            ss += __shfl_xor_sync(0xffffffffu, ss, 1);
            ss += __shfl_xor_sync(0xffffffffu, ss, 2);
            const float inv = rsqrtf(fmaxf(ss, 1e-24f));
            unsigned* xh = reinterpret_cast<unsigned*>(sXNh + t*88 + lg*20);
            #pragma unroll
            for (int u = 0; u < 10; u++) xh[u] = pack2(v[2*u]*inv, v[2*u+1]*inv);
            if (lg == 0) sInv[t] = inv;
        }
        __syncthreads();

        // ---- GEMM1: 16 warps = 4 mp x 4 ng of 10 ntiles; B x4 pairs ----
        {
            const int mp = w & 3;
            const int ng = w >> 2;
            const unsigned aBase = uXNh + (mp*32 + l15)*176 + (lane>>4)*16;
            const unsigned bB4 = uW1 + ((ng*10 + joff)*8 + l7)*176 + khalf*16;
            float acc[2][10][4];
            #pragma unroll
            for (int mi = 0; mi < 2; mi++)
                #pragma unroll
                for (int j = 0; j < 10; j++)
                    #pragma unroll
                    for (int e = 0; e < 4; e++) acc[mi][j][e] = 0.f;

            #pragma unroll
            for (int ks = 0; ks < 5; ks++) {
                unsigned a[2][4];
                ldsm_x4(a[0], aBase + ks*32);
                ldsm_x4(a[1], aBase + 16*176 + ks*32);
                #pragma unroll
                for (int p2 = 0; p2 < 5; p2++) {
                    unsigned b[4];
                    ldsm_x4(b, bB4 + p2*2816 + ks*32);
                    mma_bf16(acc[0][2*p2],   a[0], b[0], b[1]);
                    mma_bf16(acc[1][2*p2],   a[1], b[0], b[1]);
                    mma_bf16(acc[0][2*p2+1], a[0], b[2], b[3]);
                    mma_bf16(acc[1][2*p2+1], a[1], b[2], b[3]);
                }
            }
            #pragma unroll
            for (int mi = 0; mi < 2; mi++) {
                const int r0 = mp*32 + mi*16 + g;
                #pragma unroll
                for (int j = 0; j < 10; j++) {
                    const int c = (ng*10+j)*8 + 2*tq;
                    *reinterpret_cast<unsigned*>(sH + r0*344 + c) =
                        pack2(fmaxf(acc[mi][j][0], 0.f), fmaxf(acc[mi][j][1], 0.f));
                    *reinterpret_cast<unsigned*>(sH + (r0+8)*344 + c) =
                        pack2(fmaxf(acc[mi][j][2], 0.f), fmaxf(acc[mi][j][3], 0.f));
                }
            }
        }
        __syncthreads();

        // ---- GEMM2: 4 mp x 2 ng x 2 kh; B x4 pairs (2) + x2 tail ----
        {
            const int mp = w & 3;
            const int ng = (w >> 2) & 1;
            const int kh = w >> 3;
            const unsigned aBase = uH + (mp*32 + l15)*688 + (lane>>4)*16 + kh*320;
            const unsigned bB4 = uW2 + ((ng*5 + joff)*8 + l7)*688 + khalf*16 + kh*320;
            const unsigned bX2 = uW2 + ((ng*5 + 4)*8 + l7)*688 + (l15>>3)*16 + kh*320;
            float acc2[2][5][4];
            #pragma unroll
            for (int mi = 0; mi < 2; mi++)
                #pragma unroll
                for (int j = 0; j < 5; j++)
                    #pragma unroll
                    for (int e = 0; e < 4; e++) acc2[mi][j][e] = 0.f;

            #pragma unroll
            for (int ks = 0; ks < 10; ks++) {
                unsigned a[2][4];
                ldsm_x4(a[0], aBase + ks*32);
                ldsm_x4(a[1], aBase + 16*688 + ks*32);
                #pragma unroll
                for (int p2 = 0; p2 < 2; p2++) {
                    unsigned b[4];
                    ldsm_x4(b, bB4 + p2*11008 + ks*32);   // 16 rows * 688B
                    mma_bf16(acc2[0][2*p2],   a[0], b[0], b[1]);
                    mma_bf16(acc2[1][2*p2],   a[1], b[0], b[1]);
                    mma_bf16(acc2[0][2*p2+1], a[0], b[2], b[3]);
                    mma_bf16(acc2[1][2*p2+1], a[1], b[2], b[3]);
                }
                unsigned b0, b1;
                ldsm_x2(b0, b1, bX2 + ks*32);
                mma_bf16(acc2[0][4], a[0], b0, b1);
                mma_bf16(acc2[1][4], a[1], b0, b1);
            }
            __syncthreads();
            float* sOut = kh ? sOutB : sOutA;
            #pragma unroll
            for (int mi = 0; mi < 2; mi++) {
                const int r0 = mp*32 + mi*16 + g;
                #pragma unroll
                for (int j = 0; j < 5; j++) {
                    const int c = (ng*5+j)*8 + 2*tq;
                    sOut[r0*81 + c]         = acc2[mi][j][0];
                    sOut[r0*81 + c + 1]     = acc2[mi][j][1];
                    sOut[(r0+8)*81 + c]     = acc2[mi][j][2];
                    sOut[(r0+8)*81 + c + 1] = acc2[mi][j][3];
                }
            }
        }
        __syncthreads();

        {
            const int t = tid >> 2, lg = tid & 3;
            const float inv = sInv[t];
            const float4* xr = reinterpret_cast<const float4*>(xin + (tokBase + t)*80) + lg*5;
            float4* yr = reinterpret_cast<float4*>(xout + (tokBase + t)*80) + lg*5;
            #pragma unroll
            for (int u = 0; u < 5; u++) {
                float4 xf = xr[u];
                float xv[4] = {xf.x, xf.y, xf.z, xf.w};
                float f[4];
                #pragma unroll
                for (int e = 0; e < 4; e++) {
                    const int idx = lg*20 + 4*u + e;
                    float hv = sOutA[t*81 + idx] + sOutB[t*81 + idx] + sB2[idx];
                    if (RELU2) hv = fmaxf(hv, 0.f);
                    f[e] = xv[e]*inv + hv * sG[idx];
                }
                yr[u] = make_float4(f[0], f[1], f[2], f[3]);
            }
        }
        __syncthreads();
    }
}

// =====================================================================
extern "C" void kernel_launch(void* const* d_in, const int* in_sizes, int n_in,
                              void* d_out, int out_size)
{
    const float* x       = (const float*)d_in[0];
    const float* bw_qkv  = (const float*)d_in[1];
    const float* bb_qkv  = (const float*)d_in[2];
    const float* bw_proj = (const float*)d_in[3];
    const float* bb_proj = (const float*)d_in[4];
    const float* b_gamma = (const float*)d_in[5];
    const float* bw_mlp1 = (const float*)d_in[6];
    const float* bw_mlp2 = (const float*)d_in[7];
    const float* bb_mlp2 = (const float*)d_in[8];
    const float* gw_qkv  = (const float*)d_in[9];
    const float* gb_qkv  = (const float*)d_in[10];
    const float* gw_proj = (const float*)d_in[11];
    const float* gb_proj = (const float*)d_in[12];
    const float* g_gamma = (const float*)d_in[13];
    const float* gw_mlp1 = (const float*)d_in[14];
    const float* gw_mlp2 = (const float*)d_in[15];
    const float* gb_mlp2 = (const float*)d_in[16];
    float* out = (float*)d_out;

    float *buf1 = nullptr, *buf2 = nullptr;
    cudaGetSymbolAddress((void**)&buf1, g_buf1);
    cudaGetSymbolAddress((void**)&buf2, g_buf2);

    __nv_bfloat16 *qkvT_b, *projT_b, *qkvT_g, *projT_g, *w1T_b, *w2T_b, *w1T_g, *w2T_g;
    cudaGetSymbolAddress((void**)&qkvT_b,  g_qkvT_b);
    cudaGetSymbolAddress((void**)&projT_b, g_projT_b);
    cudaGetSymbolAddress((void**)&qkvT_g,  g_qkvT_g);
    cudaGetSymbolAddress((void**)&projT_g, g_projT_g);
    cudaGetSymbolAddress((void**)&w1T_b,   g_w1T_b);
    cudaGetSymbolAddress((void**)&w2T_b,   g_w2T_b);
    cudaGetSymbolAddress((void**)&w1T_g,   g_w1T_g);
    cudaGetSymbolAddress((void**)&w2T_g,   g_w2T_g);

    const size_t smA = ATTN_SMEM_BYTES;   // 213,760 B
    const size_t smM = MLP_SMEM_BYTES;    // 223,104 B
    cudaFuncSetAttribute(attn_kernel<false>, cudaFuncAttributeMaxDynamicSharedMemorySize, (int)smA);
    cudaFuncSetAttribute(attn_kernel<true>,  cudaFuncAttributeMaxDynamicSharedMemorySize, (int)smA);
    cudaFuncSetAttribute(mlp_kernel<true>,   cudaFuncAttributeMaxDynamicSharedMemorySize, (int)smM);
    cudaFuncSetAttribute(mlp_kernel<false>,  cudaFuncAttributeMaxDynamicSharedMemorySize, (int)smM);

    // ---- single prepass launch: all 8 weight panels ----
    {
        dim3 grid(16, 8);
        prep_all<<<grid, 256>>>(bw_qkv, bw_proj, gw_qkv, gw_proj,
                                bw_mlp1, bw_mlp2, gw_mlp1, gw_mlp2,
                                qkvT_b, projT_b, qkvT_g, projT_g,
                                w1T_b, w2T_b, w1T_g, w2T_g);
    }

    // stage 1: block SA
    attn_kernel<false><<<ATTN_NCTA, 256, smA>>>(x,    buf1, qkvT_b, bb_qkv, projT_b, bb_proj);
    mlp_kernel<true>  <<<MLP_NCTA,  512, smM>>>(buf1, buf2, w1T_b, w2T_b, bb_mlp2, b_gamma);
    // stage 2: grid SA
    attn_kernel<true> <<<ATTN_NCTA, 256, smA>>>(buf2, buf1, qkvT_g, gb_qkv, projT_g, gb_proj);
    mlp_kernel<false> <<<MLP_NCTA,  512, smM>>>(buf1, out, w1T_g, w2T_g, gb_mlp2, g_gamma);
}

// round 14
// speedup vs baseline: 1.3592x; 1.0077x over previous
#include <cuda_runtime.h>
#include <cuda_bf16.h>

// ---------------- problem constants ----------------
// x: (32, 128, 128, 80) fp32; C=80, NH=8, DH=10, WIN=GRID=8 -> 64-token windows
// windows per stage: 32 * 16 * 16 = 8192 ; tokens total 524288

#define TOK_TOTAL (32*128*128)

__device__ float g_buf1[(size_t)TOK_TOTAL * 80];
__device__ float g_buf2[(size_t)TOK_TOTAL * 80];

// pre-converted transposed bf16 weight panels (written by prep_all)
__device__ __align__(16) __nv_bfloat16 g_qkvT_b[240*88];
__device__ __align__(16) __nv_bfloat16 g_projT_b[80*88];
__device__ __align__(16) __nv_bfloat16 g_qkvT_g[240*88];
__device__ __align__(16) __nv_bfloat16 g_projT_g[80*88];
__device__ __align__(16) __nv_bfloat16 g_w1T_b[320*88];
__device__ __align__(16) __nv_bfloat16 g_w2T_b[80*344];
__device__ __align__(16) __nv_bfloat16 g_w1T_g[320*88];
__device__ __align__(16) __nv_bfloat16 g_w2T_g[80*344];

// ---------------- helpers ----------------
__device__ __forceinline__ unsigned pack2(float lo, float hi) {
    __nv_bfloat162 t = __floats2bfloat162_rn(lo, hi);
    return *reinterpret_cast<unsigned*>(&t);
}

__device__ __forceinline__ void mma_bf16(float* c, const unsigned* a, unsigned b0, unsigned b1) {
    asm volatile(
        "mma.sync.aligned.m16n8k16.row.col.f32.bf16.bf16.f32 "
        "{%0,%1,%2,%3}, {%4,%5,%6,%7}, {%8,%9}, {%0,%1,%2,%3};\n"
        : "+f"(c[0]), "+f"(c[1]), "+f"(c[2]), "+f"(c[3])
        : "r"(a[0]), "r"(a[1]), "r"(a[2]), "r"(a[3]), "r"(b0), "r"(b1));
}

__device__ __forceinline__ unsigned smem_u32(const void* p) {
    return (unsigned)__cvta_generic_to_shared(p);
}

__device__ __forceinline__ void ldsm_x4(unsigned* r, unsigned addr) {
    asm volatile("ldmatrix.sync.aligned.m8n8.x4.shared.b16 {%0,%1,%2,%3}, [%4];\n"
                 : "=r"(r[0]), "=r"(r[1]), "=r"(r[2]), "=r"(r[3]) : "r"(addr));
}
__device__ __forceinline__ void ldsm_x2(unsigned& r0, unsigned& r1, unsigned addr) {
    asm volatile("ldmatrix.sync.aligned.m8n8.x2.shared.b16 {%0,%1}, [%2];\n"
                 : "=r"(r0), "=r"(r1) : "r"(addr));
}

// ---------------- single prepass launch: all 8 weight panels ----------------
__global__ void prep_all(
    const float* s0, const float* s1, const float* s2, const float* s3,
    const float* s4, const float* s5, const float* s6, const float* s7,
    __nv_bfloat16* d0, __nv_bfloat16* d1, __nv_bfloat16* d2, __nv_bfloat16* d3,
    __nv_bfloat16* d4, __nv_bfloat16* d5, __nv_bfloat16* d6, __nv_bfloat16* d7)
{
    const int r = blockIdx.y;
    const float* src; __nv_bfloat16* dst; int K, N, stride, rows;
    switch (r) {
        case 0: src=s0; dst=d0; K=80;  N=240; stride=88;  rows=240; break;
        case 1: src=s1; dst=d1; K=80;  N=80;  stride=88;  rows=80;  break;
        case 2: src=s2; dst=d2; K=80;  N=240; stride=88;  rows=240; break;
        case 3: src=s3; dst=d3; K=80;  N=80;  stride=88;  rows=80;  break;
        case 4: src=s4; dst=d4; K=80;  N=320; stride=88;  rows=320; break;
        case 5: src=s5; dst=d5; K=320; N=80;  stride=344; rows=80;  break;
        case 6: src=s6; dst=d6; K=80;  N=320; stride=88;  rows=320; break;
        default:src=s7; dst=d7; K=320; N=80;  stride=344; rows=80;  break;
    }
    const int total = rows * stride;
    for (int idx = blockIdx.x*256 + threadIdx.x; idx < total; idx += gridDim.x*256) {
        int n = idx / stride, k = idx - n*stride;
        float v = (n < N && k < K) ? src[k*N + n] : 0.f;
        dst[idx] = __float2bfloat16(v);
    }
}

// =====================================================================
// Fused window attention: 256 threads = 8 warps, M=128 supertiles.
// R13 delta: Q/K row stride 18 -> 24 bf16 (48 B, 16-aligned) so the
// attention phase uses ldmatrix for Q (x4) and K (paired x4); sO now
// aliases sXNh (dead after QKV) to fit smem.
//
// per-window arena (79104 B):
//   sXNh [64][88] bf16  +0      (11264)   aliased by sO [64][88] bf16
//   sQ  [8][64][24] bf16 +11264 (24576)   k-pads d=10..15 zero (set once)
//   sK  [8][64][24] bf16 +35840 (24576)
//   sVT [8][16][72] bf16 +60416 (18432)
//   sInv [64] f32       +78848  (256)
// total smem: 57600 + 2*79104 = 215808 B
// =====================================================================
constexpr int ATTN_SMEM_BYTES = 215808;
constexpr int ATTN_WIN_PER_CTA = 8;
constexpr int ATTN_NCTA = 8192 / ATTN_WIN_PER_CTA;     // 1024
constexpr int ARENA = 79104;
constexpr float QK_SCALE = 0.31622776601683794f;       // DH^-0.5

template<bool IS_GRID>
__global__ void __launch_bounds__(256, 1)
attn_kernel(const float* __restrict__ x, float* __restrict__ y,
            const __nv_bfloat16* __restrict__ wqkvT, const float* __restrict__ bqkv,
            const __nv_bfloat16* __restrict__ wprojT, const float* __restrict__ bproj)
{
    extern __shared__ float smf[];
    char* smb = reinterpret_cast<char*>(smf);
    __nv_bfloat16* sWqkvT  = reinterpret_cast<__nv_bfloat16*>(smb);           // [240][88]
    __nv_bfloat16* sWprojT = reinterpret_cast<__nv_bfloat16*>(smb + 42240);   // [80][88]
    float*         sBqkv   = reinterpret_cast<float*>(smb + 56320);           // [240]
    float*         sBproj  = reinterpret_cast<float*>(smb + 57280);           // [80]
    char*          ar0     = smb + 57600;

    const int tid  = threadIdx.x;
    const int w    = tid >> 5, lane = tid & 31;
    const int g    = lane >> 2, tq  = lane & 3;
    const int l15  = lane & 15, l7 = lane & 7;
    const int joff = lane >> 4;            // x4 B pairing: j-offset 0/1
    const int khalf = (lane >> 3) & 1;     // k-half 0/1

    // ---- one-time staging + pad zeroing ----
    {
        const float4* s1 = reinterpret_cast<const float4*>(wqkvT);
        float4* d1 = reinterpret_cast<float4*>(sWqkvT);
        for (int i = tid; i < 2640; i += 256) d1[i] = s1[i];
        const float4* s2 = reinterpret_cast<const float4*>(wprojT);
        float4* d2 = reinterpret_cast<float4*>(sWprojT);
        for (int i = tid; i < 880; i += 256) d2[i] = s2[i];
        if (tid < 240) sBqkv[tid] = bqkv[tid];
        if (tid < 80)  sBproj[tid] = bproj[tid];
        // zero k-pads d=10..15 of sQ/sK in BOTH arenas (3 u32 per row; never clobbered)
        for (int i = tid; i < 6144; i += 256) {
            const int a  = (i >= 3072);
            const int r  = i - a*3072;
            const int b  = (r >= 1536);
            const int r2 = r - b*1536;
            const int row = r2 / 3, p = r2 - row*3;
            char* base = ar0 + a*ARENA + (b ? 35840 : 11264);
            *reinterpret_cast<unsigned*>(base + row*48 + 20 + 4*p) = 0u;
        }
    }

    const unsigned uAr0 = smem_u32(ar0);
    const unsigned uWq  = smem_u32(sWqkvT);
    const unsigned uWp  = smem_u32(sWprojT);

    for (int it = 0; it < 4; it++) {
        const int wBase = blockIdx.x * ATTN_WIN_PER_CTA + it*2;

        // ---- load + l2norm: 2 threads per token (128 tokens) ----
        {
            const int t  = tid >> 1, lg = tid & 1;
            const int wn = t >> 6, tr = t & 63;
            const int wIdx = wBase + wn;
            const int bb = wIdx >> 8, rem = wIdx & 255;
            const int wh = rem >> 4, ww = rem & 15;
            const int ti = tr >> 3, tj = tr & 7;
            int pr, pc;
            if (IS_GRID) { pr = ti*16 + wh; pc = tj*16 + ww; }
            else         { pr = wh*8 + ti;  pc = ww*8 + tj;  }
            const long pix = ((long)bb*128 + pr)*128 + pc;
            const float4* xr = reinterpret_cast<const float4*>(x + pix*80) + lg*10;
            float v[40]; float ss = 0.f;
            #pragma unroll
            for (int u = 0; u < 10; u++) {
                float4 f = xr[u];
                v[4*u+0]=f.x; v[4*u+1]=f.y; v[4*u+2]=f.z; v[4*u+3]=f.w;
                ss += f.x*f.x + f.y*f.y + f.z*f.z + f.w*f.w;
            }
            ss += __shfl_xor_sync(0xffffffffu, ss, 1);
            const float inv = rsqrtf(fmaxf(ss, 1e-24f));
            char* ar = ar0 + wn*ARENA;
            unsigned* xh = reinterpret_cast<unsigned*>(
                reinterpret_cast<__nv_bfloat16*>(ar) + tr*88 + lg*40);
            #pragma unroll
            for (int u = 0; u < 20; u++) xh[u] = pack2(v[2*u]*inv, v[2*u+1]*inv);
            if (lg == 0) reinterpret_cast<float*>(ar + 78848)[tr] = inv;
        }
        __syncthreads();

        // ---- QKV GEMM M=128: 8 warps = 4 mt-pairs x 2 j-groups of 15 ----
        // B via ldmatrix.x4 pairs (7 pairs + 1 x2 tail)
        {
            const int p = w >> 1, jbase = (w & 1) * 15;
            unsigned aB[2];
            #pragma unroll
            for (int mi = 0; mi < 2; mi++) {
                const int mt = 2*p + mi, wn = mt >> 2, lr = (mt & 3)*16;
                aB[mi] = uAr0 + wn*ARENA + (lr + l15)*176 + (lane>>4)*16;
            }
            const unsigned bB4 = uWq + ((jbase + joff)*8 + l7)*176 + khalf*16;
            const unsigned bX2 = uWq + ((jbase + 14)*8 + l7)*176 + (l15>>3)*16;
            float acc[2][15][4];
            #pragma unroll
            for (int mi = 0; mi < 2; mi++)
                #pragma unroll
                for (int j = 0; j < 15; j++)
                    #pragma unroll
                    for (int e = 0; e < 4; e++) acc[mi][j][e] = 0.f;

            #pragma unroll
            for (int ks = 0; ks < 5; ks++) {
                unsigned a0[4], a1[4];
                ldsm_x4(a0, aB[0] + ks*32);
                ldsm_x4(a1, aB[1] + ks*32);
                #pragma unroll
                for (int p2 = 0; p2 < 7; p2++) {
                    unsigned b[4];
                    ldsm_x4(b, bB4 + p2*2816 + ks*32);   // 2 j-tiles = 16 rows * 176B
                    mma_bf16(acc[0][2*p2],   a0, b[0], b[1]);
                    mma_bf16(acc[1][2*p2],   a1, b[0], b[1]);
                    mma_bf16(acc[0][2*p2+1], a0, b[2], b[3]);
                    mma_bf16(acc[1][2*p2+1], a1, b[2], b[3]);
                }
                unsigned b0, b1;
                ldsm_x2(b0, b1, bX2 + ks*32);
                mma_bf16(acc[0][14], a0, b0, b1);
                mma_bf16(acc[1][14], a1, b0, b1);
            }
            // packed scatter (c0 even; segment boundaries odd -> pair never splits)
            #pragma unroll
            for (int mi = 0; mi < 2; mi++) {
                const int mt = 2*p + mi, wn = mt >> 2;
                const int rowA = (mt & 3)*16 + g;
                char* ar = ar0 + wn*ARENA;
                __nv_bfloat16* sQw  = reinterpret_cast<__nv_bfloat16*>(ar + 11264);
                __nv_bfloat16* sKw  = reinterpret_cast<__nv_bfloat16*>(ar + 35840);
                __nv_bfloat16* sVTw = reinterpret_cast<__nv_bfloat16*>(ar + 60416);
                #pragma unroll
                for (int j = 0; j < 15; j++) {
                    const int c0 = (jbase+j)*8 + 2*tq;
                    const int h  = c0 / 30;
                    const int r  = c0 - h*30;          // even
                    const float b0 = sBqkv[c0], b1 = sBqkv[c0+1];
                    const float vA0 = acc[mi][j][0] + b0, vA1 = acc[mi][j][1] + b1;
                    const float vB0 = acc[mi][j][2] + b0, vB1 = acc[mi][j][3] + b1;
                    if (r < 10) {
                        *reinterpret_cast<unsigned*>(sQw + h*1536 + rowA*24 + r) =
                            pack2(vA0*QK_SCALE, vA1*QK_SCALE);
                        *reinterpret_cast<unsigned*>(sQw + h*1536 + (rowA+8)*24 + r) =
                            pack2(vB0*QK_SCALE, vB1*QK_SCALE);
                    } else if (r < 20) {
                        const int d = r - 10;
                        *reinterpret_cast<unsigned*>(sKw + h*1536 + rowA*24 + d) = pack2(vA0, vA1);
                        *reinterpret_cast<unsigned*>(sKw + h*1536 + (rowA+8)*24 + d) = pack2(vB0, vB1);
                    } else {
                        const int d = r - 20;
                        sVTw[h*1152 + d*72     + rowA]     = __float2bfloat16(vA0);
                        sVTw[h*1152 + (d+1)*72 + rowA]     = __float2bfloat16(vA1);
                        sVTw[h*1152 + d*72     + rowA + 8] = __float2bfloat16(vB0);
                        sVTw[h*1152 + (d+1)*72 + rowA + 8] = __float2bfloat16(vB1);
                    }
                }
            }
        }
        __syncthreads();

        // ---- attention: warp w == head w, both windows, reg-resident ----
        // Q via ldsm_x4, K via paired ldsm_x4, V via ldsm_x2
        {
            const int h = w;
            for (int wn = 0; wn < 2; wn++) {
                char* ar = ar0 + wn*ARENA;
                __nv_bfloat16* sOw = reinterpret_cast<__nv_bfloat16*>(ar);   // aliases sXNh
                const unsigned qBase = uAr0 + wn*ARENA + 11264 + h*3072
                                     + l15*48 + (lane>>4)*16;
                const unsigned kBase = uAr0 + wn*ARENA + 35840 + h*3072
                                     + (joff*8 + l7)*48 + khalf*16;
                const unsigned vBase = uAr0 + wn*ARENA + 60416 + h*2304
                                     + l7*144 + khalf*16;

                #pragma unroll
                for (int pass = 0; pass < 2; pass++) {
                    float s[2][8][4];
                    unsigned qa[2][4];
                    ldsm_x4(qa[0], qBase + (pass*2    )*16*48);
                    ldsm_x4(qa[1], qBase + (pass*2 + 1)*16*48);
                    #pragma unroll
                    for (int nt2 = 0; nt2 < 4; nt2++) {
                        unsigned kb[4];
                        ldsm_x4(kb, kBase + nt2*768);   // 2 n-tiles = 16 rows * 48B
                        #pragma unroll
                        for (int mi = 0; mi < 2; mi++) {
                            #pragma unroll
                            for (int e = 0; e < 4; e++) { s[mi][2*nt2][e] = 0.f; s[mi][2*nt2+1][e] = 0.f; }
                            mma_bf16(s[mi][2*nt2],   qa[mi], kb[0], kb[1]);
                            mma_bf16(s[mi][2*nt2+1], qa[mi], kb[2], kb[3]);
                        }
                    }
                    // softmax, no max-subtraction (logits bounded << 88)
                    float invA[2], invB[2];
                    #pragma unroll
                    for (int mi = 0; mi < 2; mi++) {
                        float sA = 0.f, sB = 0.f;
                        #pragma unroll
                        for (int nt = 0; nt < 8; nt++) {
                            float e0 = __expf(s[mi][nt][0]);
                            float e1 = __expf(s[mi][nt][1]);
                            float e2 = __expf(s[mi][nt][2]);
                            float e3 = __expf(s[mi][nt][3]);
                            s[mi][nt][0]=e0; s[mi][nt][1]=e1; s[mi][nt][2]=e2; s[mi][nt][3]=e3;
                            sA += e0 + e1; sB += e2 + e3;
                        }
                        sA += __shfl_xor_sync(0xffffffffu, sA, 1);
                        sA += __shfl_xor_sync(0xffffffffu, sA, 2);
                        sB += __shfl_xor_sync(0xffffffffu, sB, 1);
                        sB += __shfl_xor_sync(0xffffffffu, sB, 2);
                        invA[mi] = 1.0f / sA;
                        invB[mi] = 1.0f / sB;
                    }
                    float o[2][2][4];
                    #pragma unroll
                    for (int mi = 0; mi < 2; mi++)
                        #pragma unroll
                        for (int nt2 = 0; nt2 < 2; nt2++)
                            #pragma unroll
                            for (int e = 0; e < 4; e++) o[mi][nt2][e] = 0.f;
                    #pragma unroll
                    for (int ks = 0; ks < 4; ks++) {
                        unsigned pa[2][4];
                        #pragma unroll
                        for (int mi = 0; mi < 2; mi++) {
                            pa[mi][0] = pack2(s[mi][2*ks  ][0], s[mi][2*ks  ][1]);
                            pa[mi][1] = pack2(s[mi][2*ks  ][2], s[mi][2*ks  ][3]);
                            pa[mi][2] = pack2(s[mi][2*ks+1][0], s[mi][2*ks+1][1]);
                            pa[mi][3] = pack2(s[mi][2*ks+1][2], s[mi][2*ks+1][3]);
                        }
                        #pragma unroll
                        for (int nt2 = 0; nt2 < 2; nt2++) {
                            unsigned vb0, vb1;
                            ldsm_x2(vb0, vb1, vBase + nt2*1152 + ks*32);
                            mma_bf16(o[0][nt2], pa[0], vb0, vb1);
                            mma_bf16(o[1][nt2], pa[1], vb0, vb1);
                        }
                    }
                    #pragma unroll
                    for (int mi = 0; mi < 2; mi++) {
                        const int row = (pass*2+mi)*16 + g;
                        #pragma unroll
                        for (int nt2 = 0; nt2 < 2; nt2++) {
                            const int dh = nt2*8 + 2*tq;
                            if (dh < 10) {
                                *reinterpret_cast<unsigned*>(sOw + row*88 + h*10 + dh) =
                                    pack2(o[mi][nt2][0]*invA[mi], o[mi][nt2][1]*invA[mi]);
                                *reinterpret_cast<unsigned*>(sOw + (row+8)*88 + h*10 + dh) =
                                    pack2(o[mi][nt2][2]*invB[mi], o[mi][nt2][3]*invB[mi]);
                            }
                        }
                    }
                }
            }
        }
        __syncthreads();

        // ---- proj GEMM M=128 + direct-global residual epilogue ----
        // A from sO (aliases arena base); B via ldmatrix.x4 pairs + x2 tail
        {
            const int p = w >> 1, nb = (w & 1) * 5;
            unsigned aB[2];
            #pragma unroll
            for (int mi = 0; mi < 2; mi++) {
                const int mt = 2*p + mi, wn = mt >> 2, lr = (mt & 3)*16;
                aB[mi] = uAr0 + wn*ARENA + (lr + l15)*176 + (lane>>4)*16;
            }
            const unsigned bB4 = uWp + ((nb + joff)*8 + l7)*176 + khalf*16;
            const unsigned bX2 = uWp + ((nb + 4)*8 + l7)*176 + (l15>>3)*16;
            float acc[2][5][4];
            #pragma unroll
            for (int mi = 0; mi < 2; mi++)
                #pragma unroll
                for (int j = 0; j < 5; j++)
                    #pragma unroll
                    for (int e = 0; e < 4; e++) acc[mi][j][e] = 0.f;

            #pragma unroll
            for (int ks = 0; ks < 5; ks++) {
                unsigned a0[4], a1[4];
                ldsm_x4(a0, aB[0] + ks*32);
                ldsm_x4(a1, aB[1] + ks*32);
                #pragma unroll
                for (int p2 = 0; p2 < 2; p2++) {
                    unsigned b[4];
                    ldsm_x4(b, bB4 + p2*2816 + ks*32);
                    mma_bf16(acc[0][2*p2],   a0, b[0], b[1]);
                    mma_bf16(acc[1][2*p2],   a1, b[0], b[1]);
                    mma_bf16(acc[0][2*p2+1], a0, b[2], b[3]);
                    mma_bf16(acc[1][2*p2+1], a1, b[2], b[3]);
                }
                unsigned b0, b1;
                ldsm_x2(b0, b1, bX2 + ks*32);
                mma_bf16(acc[0][4], a0, b0, b1);
                mma_bf16(acc[1][4], a1, b0, b1);
            }
            // epilogue: y = x*inv + acc + bias, fragment layout, float2
            #pragma unroll
            for (int mi = 0; mi < 2; mi++) {
                const int mt = 2*p + mi, wn = mt >> 2;
                const int wIdx = wBase + wn;
                const int bb = wIdx >> 8, rem = wIdx & 255;
                const int wh = rem >> 4, ww = rem & 15;
                char* ar = ar0 + wn*ARENA;
                const float* sInvw = reinterpret_cast<float*>(ar + 78848);
                #pragma unroll
                for (int half = 0; half < 2; half++) {
                    const int tr = (mt & 3)*16 + g + half*8;
                    const int ti = tr >> 3, tj = tr & 7;
                    int pr, pc;
                    if (IS_GRID) { pr = ti*16 + wh; pc = tj*16 + ww; }
                    else         { pr = wh*8 + ti;  pc = ww*8 + tj;  }
                    const long pix = ((long)bb*128 + pr)*128 + pc;
                    const float inv = sInvw[tr];
                    const float* xb = x + pix*80;
                    float* yb = y + pix*80;
                    #pragma unroll
                    for (int j = 0; j < 5; j++) {
                        const int c = (nb+j)*8 + 2*tq;
                        float2 xf = *reinterpret_cast<const float2*>(xb + c);
                        float r0 = xf.x*inv + acc[mi][j][half*2]   + sBproj[c];
                        float r1 = xf.y*inv + acc[mi][j][half*2+1] + sBproj[c+1];
                        *reinterpret_cast<float2*>(yb + c) = make_float2(r0, r1);
                    }
                }
            }
        }
        __syncthreads();   // protect arenas before next iteration
    }
}

// =====================================================================
// Fused MLP (unchanged from R12 passing build): M=128 supertiles,
// 512 thr, B-operand ldmatrix.x4 pairing.
// =====================================================================
constexpr int MLP_SMEM_BYTES = 223104;
constexpr int MLP_NCTA = TOK_TOTAL / 256;   // 2048

template<bool RELU2>
__global__ void __launch_bounds__(512, 1)
mlp_kernel(const float* __restrict__ xin, float* __restrict__ xout,
           const __nv_bfloat16* __restrict__ w1T, const __nv_bfloat16* __restrict__ w2T,
           const float* __restrict__ b2, const float* __restrict__ gamma)
{
    extern __shared__ float smf[];
    char* smb = reinterpret_cast<char*>(smf);
    __nv_bfloat16* sW1T  = reinterpret_cast<__nv_bfloat16*>(smb);            // [320][88]
    __nv_bfloat16* sW2T  = reinterpret_cast<__nv_bfloat16*>(smb + 56320);    // [80][344]
    __nv_bfloat16* sXNh  = reinterpret_cast<__nv_bfloat16*>(smb + 111360);   // [128][88]
    __nv_bfloat16* sH    = reinterpret_cast<__nv_bfloat16*>(smb + 133888);   // [128][344]
    float*         sOutA = reinterpret_cast<float*>(smb + 133888);           // alias [128][81]
    float*         sOutB = reinterpret_cast<float*>(smb + 175360);           // alias [128][81]
    float*         sInv  = reinterpret_cast<float*>(smb + 221952);           // [128]
    float*         sB2   = reinterpret_cast<float*>(smb + 222464);
    float*         sG    = reinterpret_cast<float*>(smb + 222784);

    const int tid = threadIdx.x;
    const int w = tid >> 5, lane = tid & 31;
    const int g = lane >> 2, tq = lane & 3;
    const int l15 = lane & 15, l7 = lane & 7;
    const int joff = lane >> 4;
    const int khalf = (lane >> 3) & 1;

    {
        const float4* s1 = reinterpret_cast<const float4*>(w1T);
        float4* d1 = reinterpret_cast<float4*>(sW1T);
        for (int i = tid; i < 3520; i += 512) d1[i] = s1[i];
        const float4* s2 = reinterpret_cast<const float4*>(w2T);
        float4* d2 = reinterpret_cast<float4*>(sW2T);
        for (int i = tid; i < 3440; i += 512) d2[i] = s2[i];
        if (tid < 80) { sB2[tid] = b2[tid]; sG[tid] = gamma[tid]; }
    }

    const unsigned uXNh = smem_u32(sXNh);
    const unsigned uW1  = smem_u32(sW1T);
    const unsigned uH   = smem_u32(sH);
    const unsigned uW2  = smem_u32(sW2T);

    for (int st = 0; st < 2; st++) {
        const long tokBase = ((long)blockIdx.x*2 + st) * 128;

        {
            const int t = tid >> 2, lg = tid & 3;
            const float4* xr = reinterpret_cast<const float4*>(xin + (tokBase + t)*80) + lg*5;
            float v[20]; float ss = 0.f;
            #pragma unroll
            for (int u = 0; u < 5; u++) {
                float4 f = xr[u];
                v[4*u]=f.x; v[4*u+1]=f.y; v[4*u+2]=f.z; v[4*u+3]=f.w;
                ss += f.x*f.x + f.y*f.y + f.z*f.z + f.w*f.w;
            }
            ss += __shfl_xor_sync(0xffffffffu, ss, 1);
            ss += __shfl_xor_sync(0xffffffffu, ss, 2);
            const float inv = rsqrtf(fmaxf(ss, 1e-24f));
            unsigned* xh = reinterpret_cast<unsigned*>(sXNh + t*88 + lg*20);
            #pragma unroll
            for (int u = 0; u < 10; u++) xh[u] = pack2(v[2*u]*inv, v[2*u+1]*inv);
            if (lg == 0) sInv[t] = inv;
        }
        __syncthreads();

        // ---- GEMM1: 16 warps = 4 mp x 4 ng of 10 ntiles; B x4 pairs ----
        {
            const int mp = w & 3;
            const int ng = w >> 2;
            const unsigned aBase = uXNh + (mp*32 + l15)*176 + (lane>>4)*16;
            const unsigned bB4 = uW1 + ((ng*10 + joff)*8 + l7)*176 + khalf*16;
            float acc[2][10][4];
            #pragma unroll
            for (int mi = 0; mi < 2; mi++)
                #pragma unroll
                for (int j = 0; j < 10; j++)
                    #pragma unroll
                    for (int e = 0; e < 4; e++) acc[mi][j][e] = 0.f;

            #pragma unroll
            for (int ks = 0; ks < 5; ks++) {
                unsigned a[2][4];
                ldsm_x4(a[0], aBase + ks*32);
                ldsm_x4(a[1], aBase + 16*176 + ks*32);
                #pragma unroll
                for (int p2 = 0; p2 < 5; p2++) {
                    unsigned b[4];
                    ldsm_x4(b, bB4 + p2*2816 + ks*32);
                    mma_bf16(acc[0][2*p2],   a[0], b[0], b[1]);
                    mma_bf16(acc[1][2*p2],   a[1], b[0], b[1]);
                    mma_bf16(acc[0][2*p2+1], a[0], b[2], b[3]);
                    mma_bf16(acc[1][2*p2+1], a[1], b[2], b[3]);
                }
            }
            #pragma unroll
            for (int mi = 0; mi < 2; mi++) {
                const int r0 = mp*32 + mi*16 + g;
                #pragma unroll
                for (int j = 0; j < 10; j++) {
                    const int c = (ng*10+j)*8 + 2*tq;
                    *reinterpret_cast<unsigned*>(sH + r0*344 + c) =
                        pack2(fmaxf(acc[mi][j][0], 0.f), fmaxf(acc[mi][j][1], 0.f));
                    *reinterpret_cast<unsigned*>(sH + (r0+8)*344 + c) =
                        pack2(fmaxf(acc[mi][j][2], 0.f), fmaxf(acc[mi][j][3], 0.f));
                }
            }
        }
        __syncthreads();

        // ---- GEMM2: 4 mp x 2 ng x 2 kh; B x4 pairs (2) + x2 tail ----
        {
            const int mp = w & 3;
            const int ng = (w >> 2) & 1;
            const int kh = w >> 3;
            const unsigned aBase = uH + (mp*32 + l15)*688 + (lane>>4)*16 + kh*320;
            const unsigned bB4 = uW2 + ((ng*5 + joff)*8 + l7)*688 + khalf*16 + kh*320;
            const unsigned bX2 = uW2 + ((ng*5 + 4)*8 + l7)*688 + (l15>>3)*16 + kh*320;
            float acc2[2][5][4];
            #pragma unroll
            for (int mi = 0; mi < 2; mi++)
                #pragma unroll
                for (int j = 0; j < 5; j++)
                    #pragma unroll
                    for (int e = 0; e < 4; e++) acc2[mi][j][e] = 0.f;

            #pragma unroll
            for (int ks = 0; ks < 10; ks++) {
                unsigned a[2][4];
                ldsm_x4(a[0], aBase + ks*32);
                ldsm_x4(a[1], aBase + 16*688 + ks*32);
                #pragma unroll
                for (int p2 = 0; p2 < 2; p2++) {
                    unsigned b[4];
                    ldsm_x4(b, bB4 + p2*11008 + ks*32);   // 16 rows * 688B
                    mma_bf16(acc2[0][2*p2],   a[0], b[0], b[1]);
                    mma_bf16(acc2[1][2*p2],   a[1], b[0], b[1]);
                    mma_bf16(acc2[0][2*p2+1], a[0], b[2], b[3]);
                    mma_bf16(acc2[1][2*p2+1], a[1], b[2], b[3]);
                }
                unsigned b0, b1;
                ldsm_x2(b0, b1, bX2 + ks*32);
                mma_bf16(acc2[0][4], a[0], b0, b1);
                mma_bf16(acc2[1][4], a[1], b0, b1);
            }
            __syncthreads();
            float* sOut = kh ? sOutB : sOutA;
            #pragma unroll
            for (int mi = 0; mi < 2; mi++) {
                const int r0 = mp*32 + mi*16 + g;
                #pragma unroll
                for (int j = 0; j < 5; j++) {
                    const int c = (ng*5+j)*8 + 2*tq;
                    sOut[r0*81 + c]         = acc2[mi][j][0];
                    sOut[r0*81 + c + 1]     = acc2[mi][j][1];
                    sOut[(r0+8)*81 + c]     = acc2[mi][j][2];
                    sOut[(r0+8)*81 + c + 1] = acc2[mi][j][3];
                }
            }
        }
        __syncthreads();

        {
            const int t = tid >> 2, lg = tid & 3;
            const float inv = sInv[t];
            const float4* xr = reinterpret_cast<const float4*>(xin + (tokBase + t)*80) + lg*5;
            float4* yr = reinterpret_cast<float4*>(xout + (tokBase + t)*80) + lg*5;
            #pragma unroll
            for (int u = 0; u < 5; u++) {
                float4 xf = xr[u];
                float xv[4] = {xf.x, xf.y, xf.z, xf.w};
                float f[4];
                #pragma unroll
                for (int e = 0; e < 4; e++) {
                    const int idx = lg*20 + 4*u + e;
                    float hv = sOutA[t*81 + idx] + sOutB[t*81 + idx] + sB2[idx];
                    if (RELU2) hv = fmaxf(hv, 0.f);
                    f[e] = xv[e]*inv + hv * sG[idx];
                }
                yr[u] = make_float4(f[0], f[1], f[2], f[3]);
            }
        }
        __syncthreads();
    }
}

// =====================================================================
extern "C" void kernel_launch(void* const* d_in, const int* in_sizes, int n_in,
                              void* d_out, int out_size)
{
    const float* x       = (const float*)d_in[0];
    const float* bw_qkv  = (const float*)d_in[1];
    const float* bb_qkv  = (const float*)d_in[2];
    const float* bw_proj = (const float*)d_in[3];
    const float* bb_proj = (const float*)d_in[4];
    const float* b_gamma = (const float*)d_in[5];
    const float* bw_mlp1 = (const float*)d_in[6];
    const float* bw_mlp2 = (const float*)d_in[7];
    const float* bb_mlp2 = (const float*)d_in[8];
    const float* gw_qkv  = (const float*)d_in[9];
    const float* gb_qkv  = (const float*)d_in[10];
    const float* gw_proj = (const float*)d_in[11];
    const float* gb_proj = (const float*)d_in[12];
    const float* g_gamma = (const float*)d_in[13];
    const float* gw_mlp1 = (const float*)d_in[14];
    const float* gw_mlp2 = (const float*)d_in[15];
    const float* gb_mlp2 = (const float*)d_in[16];
    float* out = (float*)d_out;

    float *buf1 = nullptr, *buf2 = nullptr;
    cudaGetSymbolAddress((void**)&buf1, g_buf1);
    cudaGetSymbolAddress((void**)&buf2, g_buf2);

    __nv_bfloat16 *qkvT_b, *projT_b, *qkvT_g, *projT_g, *w1T_b, *w2T_b, *w1T_g, *w2T_g;
    cudaGetSymbolAddress((void**)&qkvT_b,  g_qkvT_b);
    cudaGetSymbolAddress((void**)&projT_b, g_projT_b);
    cudaGetSymbolAddress((void**)&qkvT_g,  g_qkvT_g);
    cudaGetSymbolAddress((void**)&projT_g, g_projT_g);
    cudaGetSymbolAddress((void**)&w1T_b,   g_w1T_b);
    cudaGetSymbolAddress((void**)&w2T_b,   g_w2T_b);
    cudaGetSymbolAddress((void**)&w1T_g,   g_w1T_g);
    cudaGetSymbolAddress((void**)&w2T_g,   g_w2T_g);

    const size_t smA = ATTN_SMEM_BYTES;   // 215,808 B
    const size_t smM = MLP_SMEM_BYTES;    // 223,104 B
    cudaFuncSetAttribute(attn_kernel<false>, cudaFuncAttributeMaxDynamicSharedMemorySize, (int)smA);
    cudaFuncSetAttribute(attn_kernel<true>,  cudaFuncAttributeMaxDynamicSharedMemorySize, (int)smA);
    cudaFuncSetAttribute(mlp_kernel<true>,   cudaFuncAttributeMaxDynamicSharedMemorySize, (int)smM);
    cudaFuncSetAttribute(mlp_kernel<false>,  cudaFuncAttributeMaxDynamicSharedMemorySize, (int)smM);

    // ---- single prepass launch: all 8 weight panels ----
    {
        dim3 grid(16, 8);
        prep_all<<<grid, 256>>>(bw_qkv, bw_proj, gw_qkv, gw_proj,
                                bw_mlp1, bw_mlp2, gw_mlp1, gw_mlp2,
                                qkvT_b, projT_b, qkvT_g, projT_g,
                                w1T_b, w2T_b, w1T_g, w2T_g);
    }

    // stage 1: block SA
    attn_kernel<false><<<ATTN_NCTA, 256, smA>>>(x,    buf1, qkvT_b, bb_qkv, projT_b, bb_proj);
    mlp_kernel<true>  <<<MLP_NCTA,  512, smM>>>(buf1, buf2, w1T_b, w2T_b, bb_mlp2, b_gamma);
    // stage 2: grid SA
    attn_kernel<true> <<<ATTN_NCTA, 256, smA>>>(buf2, buf1, qkvT_g, gb_qkv, projT_g, gb_proj);
    mlp_kernel<false> <<<MLP_NCTA,  512, smM>>>(buf1, out, w1T_g, w2T_g, gb_mlp2, g_gamma);
}

// round 16
// speedup vs baseline: 1.3790x; 1.0146x over previous
#include <cuda_runtime.h>
#include <cuda_bf16.h>

// ---------------- problem constants ----------------
// x: (32, 128, 128, 80) fp32; C=80, NH=8, DH=10, WIN=GRID=8 -> 64-token windows
// windows per stage: 32 * 16 * 16 = 8192 ; tokens total 524288

#define TOK_TOTAL (32*128*128)

__device__ float g_buf1[(size_t)TOK_TOTAL * 80];
__device__ float g_buf2[(size_t)TOK_TOTAL * 80];

// pre-converted transposed bf16 weight panels (written by prep_all)
__device__ __align__(16) __nv_bfloat16 g_qkvT_b[240*88];
__device__ __align__(16) __nv_bfloat16 g_projT_b[80*88];
__device__ __align__(16) __nv_bfloat16 g_qkvT_g[240*88];
__device__ __align__(16) __nv_bfloat16 g_projT_g[80*88];
__device__ __align__(16) __nv_bfloat16 g_w1T_b[320*88];
__device__ __align__(16) __nv_bfloat16 g_w2T_b[80*344];
__device__ __align__(16) __nv_bfloat16 g_w1T_g[320*88];
__device__ __align__(16) __nv_bfloat16 g_w2T_g[80*344];

// ---------------- helpers ----------------
__device__ __forceinline__ unsigned pack2(float lo, float hi) {
    __nv_bfloat162 t = __floats2bfloat162_rn(lo, hi);
    return *reinterpret_cast<unsigned*>(&t);
}

__device__ __forceinline__ float ex2(float x) {
    float y;
    asm("ex2.approx.f32 %0, %1;" : "=f"(y) : "f"(x));
    return y;
}

__device__ __forceinline__ void mma_bf16(float* c, const unsigned* a, unsigned b0, unsigned b1) {
    asm volatile(
        "mma.sync.aligned.m16n8k16.row.col.f32.bf16.bf16.f32 "
        "{%0,%1,%2,%3}, {%4,%5,%6,%7}, {%8,%9}, {%0,%1,%2,%3};\n"
        : "+f"(c[0]), "+f"(c[1]), "+f"(c[2]), "+f"(c[3])
        : "r"(a[0]), "r"(a[1]), "r"(a[2]), "r"(a[3]), "r"(b0), "r"(b1));
}

__device__ __forceinline__ unsigned smem_u32(const void* p) {
    return (unsigned)__cvta_generic_to_shared(p);
}

__device__ __forceinline__ void ldsm_x4(unsigned* r, unsigned addr) {
    asm volatile("ldmatrix.sync.aligned.m8n8.x4.shared.b16 {%0,%1,%2,%3}, [%4];\n"
                 : "=r"(r[0]), "=r"(r[1]), "=r"(r[2]), "=r"(r[3]) : "r"(addr));
}
__device__ __forceinline__ void ldsm_x2(unsigned& r0, unsigned& r1, unsigned addr) {
    asm volatile("ldmatrix.sync.aligned.m8n8.x2.shared.b16 {%0,%1}, [%2];\n"
                 : "=r"(r0), "=r"(r1) : "r"(addr));
}

// ---------------- single prepass launch: all 8 weight panels ----------------
__global__ void prep_all(
    const float* s0, const float* s1, const float* s2, const float* s3,
    const float* s4, const float* s5, const float* s6, const float* s7,
    __nv_bfloat16* d0, __nv_bfloat16* d1, __nv_bfloat16* d2, __nv_bfloat16* d3,
    __nv_bfloat16* d4, __nv_bfloat16* d5, __nv_bfloat16* d6, __nv_bfloat16* d7)
{
    const int r = blockIdx.y;
    const float* src; __nv_bfloat16* dst; int K, N, stride, rows;
    switch (r) {
        case 0: src=s0; dst=d0; K=80;  N=240; stride=88;  rows=240; break;
        case 1: src=s1; dst=d1; K=80;  N=80;  stride=88;  rows=80;  break;
        case 2: src=s2; dst=d2; K=80;  N=240; stride=88;  rows=240; break;
        case 3: src=s3; dst=d3; K=80;  N=80;  stride=88;  rows=80;  break;
        case 4: src=s4; dst=d4; K=80;  N=320; stride=88;  rows=320; break;
        case 5: src=s5; dst=d5; K=320; N=80;  stride=344; rows=80;  break;
        case 6: src=s6; dst=d6; K=80;  N=320; stride=88;  rows=320; break;
        default:src=s7; dst=d7; K=320; N=80;  stride=344; rows=80;  break;
    }
    const int total = rows * stride;
    for (int idx = blockIdx.x*256 + threadIdx.x; idx < total; idx += gridDim.x*256) {
        int n = idx / stride, k = idx - n*stride;
        float v = (n < N && k < K) ? src[k*N + n] : 0.f;
        dst[idx] = __float2bfloat16(v);
    }
}

// =====================================================================
// Fused window attention: 256 threads = 8 warps, M=128 supertiles.
// R14 deltas: QKV accumulators chunked (j 0..7 then 8..14) to free
// ~56 registers for ptxas scheduling; exp via raw ex2 (log2e folded
// into Q scale); tree-structured softmax row sums.
// smem layout identical to R13 (215808 B).
// =====================================================================
constexpr int ATTN_SMEM_BYTES = 215808;
constexpr int ATTN_WIN_PER_CTA = 8;
constexpr int ATTN_NCTA = 8192 / ATTN_WIN_PER_CTA;     // 1024
constexpr int ARENA = 79104;
// DH^-0.5 * log2(e): ex2(q.k * this) == exp(q.k * DH^-0.5)
constexpr float QK_SCALE_EX2 = 0.31622776601683794f * 1.4426950408889634f;

// QKV scatter for NJ j-tiles starting at j-offset jo (columns (jo+j)*8+2tq)
template<int NJ>
__device__ __forceinline__ void qkv_scatter(
    float acc[2][NJ][4], const int p, const int jo,
    const int g, const int tq, char* ar0, const float* sBqkv)
{
    #pragma unroll
    for (int mi = 0; mi < 2; mi++) {
        const int mt = 2*p + mi, wn = mt >> 2;
        const int rowA = (mt & 3)*16 + g;
        char* ar = ar0 + wn*ARENA;
        __nv_bfloat16* sQw  = reinterpret_cast<__nv_bfloat16*>(ar + 11264);
        __nv_bfloat16* sKw  = reinterpret_cast<__nv_bfloat16*>(ar + 35840);
        __nv_bfloat16* sVTw = reinterpret_cast<__nv_bfloat16*>(ar + 60416);
        #pragma unroll
        for (int j = 0; j < NJ; j++) {
            const int c0 = (jo+j)*8 + 2*tq;
            const int h  = c0 / 30;
            const int r  = c0 - h*30;          // even
            const float b0 = sBqkv[c0], b1 = sBqkv[c0+1];
            const float vA0 = acc[mi][j][0] + b0, vA1 = acc[mi][j][1] + b1;
            const float vB0 = acc[mi][j][2] + b0, vB1 = acc[mi][j][3] + b1;
            if (r < 10) {
                *reinterpret_cast<unsigned*>(sQw + h*1536 + rowA*24 + r) =
                    pack2(vA0*QK_SCALE_EX2, vA1*QK_SCALE_EX2);
                *reinterpret_cast<unsigned*>(sQw + h*1536 + (rowA+8)*24 + r) =
                    pack2(vB0*QK_SCALE_EX2, vB1*QK_SCALE_EX2);
            } else if (r < 20) {
                const int d = r - 10;
                *reinterpret_cast<unsigned*>(sKw + h*1536 + rowA*24 + d) = pack2(vA0, vA1);
                *reinterpret_cast<unsigned*>(sKw + h*1536 + (rowA+8)*24 + d) = pack2(vB0, vB1);
            } else {
                const int d = r - 20;
                sVTw[h*1152 + d*72     + rowA]     = __float2bfloat16(vA0);
                sVTw[h*1152 + (d+1)*72 + rowA]     = __float2bfloat16(vA1);
                sVTw[h*1152 + d*72     + rowA + 8] = __float2bfloat16(vB0);
                sVTw[h*1152 + (d+1)*72 + rowA + 8] = __float2bfloat16(vB1);
            }
        }
    }
}

template<bool IS_GRID>
__global__ void __launch_bounds__(256, 1)
attn_kernel(const float* __restrict__ x, float* __restrict__ y,
            const __nv_bfloat16* __restrict__ wqkvT, const float* __restrict__ bqkv,
            const __nv_bfloat16* __restrict__ wprojT, const float* __restrict__ bproj)
{
    extern __shared__ float smf[];
    char* smb = reinterpret_cast<char*>(smf);
    __nv_bfloat16* sWqkvT  = reinterpret_cast<__nv_bfloat16*>(smb);           // [240][88]
    __nv_bfloat16* sWprojT = reinterpret_cast<__nv_bfloat16*>(smb + 42240);   // [80][88]
    float*         sBqkv   = reinterpret_cast<float*>(smb + 56320);           // [240]
    float*         sBproj  = reinterpret_cast<float*>(smb + 57280);           // [80]
    char*          ar0     = smb + 57600;

    const int tid  = threadIdx.x;
    const int w    = tid >> 5, lane = tid & 31;
    const int g    = lane >> 2, tq  = lane & 3;
    const int l15  = lane & 15, l7 = lane & 7;
    const int joff = lane >> 4;            // x4 B pairing: j-offset 0/1
    const int khalf = (lane >> 3) & 1;     // k-half 0/1

    // ---- one-time staging + pad zeroing ----
    {
        const float4* s1 = reinterpret_cast<const float4*>(wqkvT);
        float4* d1 = reinterpret_cast<float4*>(sWqkvT);
        for (int i = tid; i < 2640; i += 256) d1[i] = s1[i];
        const float4* s2 = reinterpret_cast<const float4*>(wprojT);
        float4* d2 = reinterpret_cast<float4*>(sWprojT);
        for (int i = tid; i < 880; i += 256) d2[i] = s2[i];
        if (tid < 240) sBqkv[tid] = bqkv[tid];
        if (tid < 80)  sBproj[tid] = bproj[tid];
        // zero k-pads d=10..15 of sQ/sK in BOTH arenas (3 u32 per row)
        for (int i = tid; i < 6144; i += 256) {
            const int a  = (i >= 3072);
            const int r  = i - a*3072;
            const int b  = (r >= 1536);
            const int r2 = r - b*1536;
            const int row = r2 / 3, p = r2 - row*3;
            char* base = ar0 + a*ARENA + (b ? 35840 : 11264);
            *reinterpret_cast<unsigned*>(base + row*48 + 20 + 4*p) = 0u;
        }
    }

    const unsigned uAr0 = smem_u32(ar0);
    const unsigned uWq  = smem_u32(sWqkvT);
    const unsigned uWp  = smem_u32(sWprojT);

    for (int it = 0; it < 4; it++) {
        const int wBase = blockIdx.x * ATTN_WIN_PER_CTA + it*2;

        // ---- load + l2norm: 2 threads per token (128 tokens) ----
        {
            const int t  = tid >> 1, lg = tid & 1;
            const int wn = t >> 6, tr = t & 63;
            const int wIdx = wBase + wn;
            const int bb = wIdx >> 8, rem = wIdx & 255;
            const int wh = rem >> 4, ww = rem & 15;
            const int ti = tr >> 3, tj = tr & 7;
            int pr, pc;
            if (IS_GRID) { pr = ti*16 + wh; pc = tj*16 + ww; }
            else         { pr = wh*8 + ti;  pc = ww*8 + tj;  }
            const long pix = ((long)bb*128 + pr)*128 + pc;
            const float4* xr = reinterpret_cast<const float4*>(x + pix*80) + lg*10;
            float v[40]; float ss = 0.f;
            #pragma unroll
            for (int u = 0; u < 10; u++) {
                float4 f = xr[u];
                v[4*u+0]=f.x; v[4*u+1]=f.y; v[4*u+2]=f.z; v[4*u+3]=f.w;
                ss += f.x*f.x + f.y*f.y + f.z*f.z + f.w*f.w;
            }
            ss += __shfl_xor_sync(0xffffffffu, ss, 1);
            const float inv = rsqrtf(fmaxf(ss, 1e-24f));
            char* ar = ar0 + wn*ARENA;
            unsigned* xh = reinterpret_cast<unsigned*>(
                reinterpret_cast<__nv_bfloat16*>(ar) + tr*88 + lg*40);
            #pragma unroll
            for (int u = 0; u < 20; u++) xh[u] = pack2(v[2*u]*inv, v[2*u+1]*inv);
            if (lg == 0) reinterpret_cast<float*>(ar + 78848)[tr] = inv;
        }
        __syncthreads();

        // ---- QKV GEMM M=128, chunked accumulators ----
        {
            const int p = w >> 1, jbase = (w & 1) * 15;
            unsigned aB[2];
            #pragma unroll
            for (int mi = 0; mi < 2; mi++) {
                const int mt = 2*p + mi, wn = mt >> 2, lr = (mt & 3)*16;
                aB[mi] = uAr0 + wn*ARENA + (lr + l15)*176 + (lane>>4)*16;
            }
            // chunk A: j = jbase .. jbase+7 (4 x4 pairs)
            {
                const unsigned bB4 = uWq + ((jbase + joff)*8 + l7)*176 + khalf*16;
                float acc[2][8][4];
                #pragma unroll
                for (int mi = 0; mi < 2; mi++)
                    #pragma unroll
                    for (int j = 0; j < 8; j++)
                        #pragma unroll
                        for (int e = 0; e < 4; e++) acc[mi][j][e] = 0.f;
                #pragma unroll
                for (int ks = 0; ks < 5; ks++) {
                    unsigned a0[4], a1[4];
                    ldsm_x4(a0, aB[0] + ks*32);
                    ldsm_x4(a1, aB[1] + ks*32);
                    #pragma unroll
                    for (int p2 = 0; p2 < 4; p2++) {
                        unsigned b[4];
                        ldsm_x4(b, bB4 + p2*2816 + ks*32);   // 16 rows * 176 B
                        mma_bf16(acc[0][2*p2],   a0, b[0], b[1]);
                        mma_bf16(acc[1][2*p2],   a1, b[0], b[1]);
                        mma_bf16(acc[0][2*p2+1], a0, b[2], b[3]);
                        mma_bf16(acc[1][2*p2+1], a1, b[2], b[3]);
                    }
                }
                qkv_scatter<8>(acc, p, jbase, g, tq, ar0, sBqkv);
            }
            // chunk B: j = jbase+8 .. jbase+14 (3 x4 pairs + x2 tail)
            {
                const unsigned bB4 = uWq + ((jbase + 8 + joff)*8 + l7)*176 + khalf*16;
                const unsigned bX2 = uWq + ((jbase + 14)*8 + l7)*176 + (l15>>3)*16;
                float acc[2][7][4];
                #pragma unroll
                for (int mi = 0; mi < 2; mi++)
                    #pragma unroll
                    for (int j = 0; j < 7; j++)
                        #pragma unroll
                        for (int e = 0; e < 4; e++) acc[mi][j][e] = 0.f;
                #pragma unroll
                for (int ks = 0; ks < 5; ks++) {
                    unsigned a0[4], a1[4];
                    ldsm_x4(a0, aB[0] + ks*32);
                    ldsm_x4(a1, aB[1] + ks*32);
                    #pragma unroll
                    for (int p2 = 0; p2 < 3; p2++) {
                        unsigned b[4];
                        ldsm_x4(b, bB4 + p2*2816 + ks*32);
                        mma_bf16(acc[0][2*p2],   a0, b[0], b[1]);
                        mma_bf16(acc[1][2*p2],   a1, b[0], b[1]);
                        mma_bf16(acc[0][2*p2+1], a0, b[2], b[3]);
                        mma_bf16(acc[1][2*p2+1], a1, b[2], b[3]);
                    }
                    unsigned b0, b1;
                    ldsm_x2(b0, b1, bX2 + ks*32);
                    mma_bf16(acc[0][6], a0, b0, b1);
                    mma_bf16(acc[1][6], a1, b0, b1);
                }
                qkv_scatter<7>(acc, p, jbase + 8, g, tq, ar0, sBqkv);
            }
        }
        __syncthreads();

        // ---- attention: warp w == head w, both windows, reg-resident ----
        {
            const int h = w;
            for (int wn = 0; wn < 2; wn++) {
                char* ar = ar0 + wn*ARENA;
                __nv_bfloat16* sOw = reinterpret_cast<__nv_bfloat16*>(ar);   // aliases sXNh
                const unsigned qBase = uAr0 + wn*ARENA + 11264 + h*3072
                                     + l15*48 + (lane>>4)*16;
                const unsigned kBase = uAr0 + wn*ARENA + 35840 + h*3072
                                     + (joff*8 + l7)*48 + khalf*16;
                const unsigned vBase = uAr0 + wn*ARENA + 60416 + h*2304
                                     + l7*144 + khalf*16;

                #pragma unroll
                for (int pass = 0; pass < 2; pass++) {
                    float s[2][8][4];
                    unsigned qa[2][4];
                    ldsm_x4(qa[0], qBase + (pass*2    )*16*48);
                    ldsm_x4(qa[1], qBase + (pass*2 + 1)*16*48);
                    #pragma unroll
                    for (int nt2 = 0; nt2 < 4; nt2++) {
                        unsigned kb[4];
                        ldsm_x4(kb, kBase + nt2*768);   // 2 n-tiles = 16 rows * 48B
                        #pragma unroll
                        for (int mi = 0; mi < 2; mi++) {
                            #pragma unroll
                            for (int e = 0; e < 4; e++) { s[mi][2*nt2][e] = 0.f; s[mi][2*nt2+1][e] = 0.f; }
                            mma_bf16(s[mi][2*nt2],   qa[mi], kb[0], kb[1]);
                            mma_bf16(s[mi][2*nt2+1], qa[mi], kb[2], kb[3]);
                        }
                    }
                    // softmax via ex2 (log2e pre-folded); tree-structured sums
                    float invA[2], invB[2];
                    #pragma unroll
                    for (int mi = 0; mi < 2; mi++) {
                        float sA0 = 0.f, sA1 = 0.f, sB0 = 0.f, sB1 = 0.f;
                        #pragma unroll
                        for (int nt = 0; nt < 8; nt++) {
                            float e0 = ex2(s[mi][nt][0]);
                            float e1 = ex2(s[mi][nt][1]);
                            float e2 = ex2(s[mi][nt][2]);
                            float e3 = ex2(s[mi][nt][3]);
                            s[mi][nt][0]=e0; s[mi][nt][1]=e1; s[mi][nt][2]=e2; s[mi][nt][3]=e3;
                            if (nt & 1) { sA1 += e0 + e1; sB1 += e2 + e3; }
                            else        { sA0 += e0 + e1; sB0 += e2 + e3; }
                        }
                        float sA = sA0 + sA1, sB = sB0 + sB1;
                        sA += __shfl_xor_sync(0xffffffffu, sA, 1);
                        sA += __shfl_xor_sync(0xffffffffu, sA, 2);
                        sB += __shfl_xor_sync(0xffffffffu, sB, 1);
                        sB += __shfl_xor_sync(0xffffffffu, sB, 2);
                        invA[mi] = 1.0f / sA;
                        invB[mi] = 1.0f / sB;
                    }
                    float o[2][2][4];
                    #pragma unroll
                    for (int mi = 0; mi < 2; mi++)
                        #pragma unroll
                        for (int nt2 = 0; nt2 < 2; nt2++)
                            #pragma unroll
                            for (int e = 0; e < 4; e++) o[mi][nt2][e] = 0.f;
                    #pragma unroll
                    for (int ks = 0; ks < 4; ks++) {
                        unsigned pa[2][4];
                        #pragma unroll
                        for (int mi = 0; mi < 2; mi++) {
                            pa[mi][0] = pack2(s[mi][2*ks  ][0], s[mi][2*ks  ][1]);
                            pa[mi][1] = pack2(s[mi][2*ks  ][2], s[mi][2*ks  ][3]);
                            pa[mi][2] = pack2(s[mi][2*ks+1][0], s[mi][2*ks+1][1]);
                            pa[mi][3] = pack2(s[mi][2*ks+1][2], s[mi][2*ks+1][3]);
                        }
                        #pragma unroll
                        for (int nt2 = 0; nt2 < 2; nt2++) {
                            unsigned vb0, vb1;
                            ldsm_x2(vb0, vb1, vBase + nt2*1152 + ks*32);
                            mma_bf16(o[0][nt2], pa[0], vb0, vb1);
                            mma_bf16(o[1][nt2], pa[1], vb0, vb1);
                        }
                    }
                    #pragma unroll
                    for (int mi = 0; mi < 2; mi++) {
                        const int row = (pass*2+mi)*16 + g;
                        #pragma unroll
                        for (int nt2 = 0; nt2 < 2; nt2++) {
                            const int dh = nt2*8 + 2*tq;
                            if (dh < 10) {
                                *reinterpret_cast<unsigned*>(sOw + row*88 + h*10 + dh) =
                                    pack2(o[mi][nt2][0]*invA[mi], o[mi][nt2][1]*invA[mi]);
                                *reinterpret_cast<unsigned*>(sOw + (row+8)*88 + h*10 + dh) =
                                    pack2(o[mi][nt2][2]*invB[mi], o[mi][nt2][3]*invB[mi]);
                            }
                        }
                    }
                }
            }
        }
        __syncthreads();

        // ---- proj GEMM M=128 + direct-global residual epilogue ----
        {
            const int p = w >> 1, nb = (w & 1) * 5;
            unsigned aB[2];
            #pragma unroll
            for (int mi = 0; mi < 2; mi++) {
                const int mt = 2*p + mi, wn = mt >> 2, lr = (mt & 3)*16;
                aB[mi] = uAr0 + wn*ARENA + (lr + l15)*176 + (lane>>4)*16;
            }
            const unsigned bB4 = uWp + ((nb + joff)*8 + l7)*176 + khalf*16;
            const unsigned bX2 = uWp + ((nb + 4)*8 + l7)*176 + (l15>>3)*16;
            float acc[2][5][4];
            #pragma unroll
            for (int mi = 0; mi < 2; mi++)
                #pragma unroll
                for (int j = 0; j < 5; j++)
                    #pragma unroll
                    for (int e = 0; e < 4; e++) acc[mi][j][e] = 0.f;

            #pragma unroll
            for (int ks = 0; ks < 5; ks++) {
                unsigned a0[4], a1[4];
                ldsm_x4(a0, aB[0] + ks*32);
                ldsm_x4(a1, aB[1] + ks*32);
                #pragma unroll
                for (int p2 = 0; p2 < 2; p2++) {
                    unsigned b[4];
                    ldsm_x4(b, bB4 + p2*2816 + ks*32);
                    mma_bf16(acc[0][2*p2],   a0, b[0], b[1]);
                    mma_bf16(acc[1][2*p2],   a1, b[0], b[1]);
                    mma_bf16(acc[0][2*p2+1], a0, b[2], b[3]);
                    mma_bf16(acc[1][2*p2+1], a1, b[2], b[3]);
                }
                unsigned b0, b1;
                ldsm_x2(b0, b1, bX2 + ks*32);
                mma_bf16(acc[0][4], a0, b0, b1);
                mma_bf16(acc[1][4], a1, b0, b1);
            }
            // epilogue: y = x*inv + acc + bias, fragment layout, float2
            #pragma unroll
            for (int mi = 0; mi < 2; mi++) {
                const int mt = 2*p + mi, wn = mt >> 2;
                const int wIdx = wBase + wn;
                const int bb = wIdx >> 8, rem = wIdx & 255;
                const int wh = rem >> 4, ww = rem & 15;
                char* ar = ar0 + wn*ARENA;
                const float* sInvw = reinterpret_cast<float*>(ar + 78848);
                #pragma unroll
                for (int half = 0; half < 2; half++) {
                    const int tr = (mt & 3)*16 + g + half*8;
                    const int ti = tr >> 3, tj = tr & 7;
                    int pr, pc;
                    if (IS_GRID) { pr = ti*16 + wh; pc = tj*16 + ww; }
                    else         { pr = wh*8 + ti;  pc = ww*8 + tj;  }
                    const long pix = ((long)bb*128 + pr)*128 + pc;
                    const float inv = sInvw[tr];
                    const float* xb = x + pix*80;
                    float* yb = y + pix*80;
                    #pragma unroll
                    for (int j = 0; j < 5; j++) {
                        const int c = (nb+j)*8 + 2*tq;
                        float2 xf = *reinterpret_cast<const float2*>(xb + c);
                        float r0 = xf.x*inv + acc[mi][j][half*2]   + sBproj[c];
                        float r1 = xf.y*inv + acc[mi][j][half*2+1] + sBproj[c+1];
                        *reinterpret_cast<float2*>(yb + c) = make_float2(r0, r1);
                    }
                }
            }
        }
        __syncthreads();   // protect arenas before next iteration
    }
}

// =====================================================================
// Fused MLP (unchanged from R12/R13 passing builds): M=128 supertiles,
// 512 thr, B-operand ldmatrix.x4 pairing.
// =====================================================================
constexpr int MLP_SMEM_BYTES = 223104;
constexpr int MLP_NCTA = TOK_TOTAL / 256;   // 2048

template<bool RELU2>
__global__ void __launch_bounds__(512, 1)
mlp_kernel(const float* __restrict__ xin, float* __restrict__ xout,
           const __nv_bfloat16* __restrict__ w1T, const __nv_bfloat16* __restrict__ w2T,
           const float* __restrict__ b2, const float* __restrict__ gamma)
{
    extern __shared__ float smf[];
    char* smb = reinterpret_cast<char*>(smf);
    __nv_bfloat16* sW1T  = reinterpret_cast<__nv_bfloat16*>(smb);            // [320][88]
    __nv_bfloat16* sW2T  = reinterpret_cast<__nv_bfloat16*>(smb + 56320);    // [80][344]
    __nv_bfloat16* sXNh  = reinterpret_cast<__nv_bfloat16*>(smb + 111360);   // [128][88]
    __nv_bfloat16* sH    = reinterpret_cast<__nv_bfloat16*>(smb + 133888);   // [128][344]
    float*         sOutA = reinterpret_cast<float*>(smb + 133888);           // alias [128][81]
    float*         sOutB = reinterpret_cast<float*>(smb + 175360);           // alias [128][81]
    float*         sInv  = reinterpret_cast<float*>(smb + 221952);           // [128]
    float*         sB2   = reinterpret_cast<float*>(smb + 222464);
    float*         sG    = reinterpret_cast<float*>(smb + 222784);

    const int tid = threadIdx.x;
    const int w = tid >> 5, lane = tid & 31;
    const int g = lane >> 2, tq = lane & 3;
    const int l15 = lane & 15, l7 = lane & 7;
    const int joff = lane >> 4;
    const int khalf = (lane >> 3) & 1;

    {
        const float4* s1 = reinterpret_cast<const float4*>(w1T);
        float4* d1 = reinterpret_cast<float4*>(sW1T);
        for (int i = tid; i < 3520; i += 512) d1[i] = s1[i];
        const float4* s2 = reinterpret_cast<const float4*>(w2T);
        float4* d2 = reinterpret_cast<float4*>(sW2T);
        for (int i = tid; i < 3440; i += 512) d2[i] = s2[i];
        if (tid < 80) { sB2[tid] = b2[tid]; sG[tid] = gamma[tid]; }
    }

    const unsigned uXNh = smem_u32(sXNh);
    const unsigned uW1  = smem_u32(sW1T);
    const unsigned uH   = smem_u32(sH);
    const unsigned uW2  = smem_u32(sW2T);

    for (int st = 0; st < 2; st++) {
        const long tokBase = ((long)blockIdx.x*2 + st) * 128;

        {
            const int t = tid >> 2, lg = tid & 3;
            const float4* xr = reinterpret_cast<const float4*>(xin + (tokBase + t)*80) + lg*5;
            float v[20]; float ss = 0.f;
            #pragma unroll
            for (int u = 0; u < 5; u++) {
                float4 f = xr[u];
                v[4*u]=f.x; v[4*u+1]=f.y; v[4*u+2]=f.z; v[4*u+3]=f.w;
                ss += f.x*f.x + f.y*f.y + f.z*f.z + f.w*f.w;
            }
            ss += __shfl_xor_sync(0xffffffffu, ss, 1);
            ss += __shfl_xor_sync(0xffffffffu, ss, 2);
            const float inv = rsqrtf(fmaxf(ss, 1e-24f));
            unsigned* xh = reinterpret_cast<unsigned*>(sXNh + t*88 + lg*20);
            #pragma unroll
            for (int u = 0; u < 10; u++) xh[u] = pack2(v[2*u]*inv, v[2*u+1]*inv);
            if (lg == 0) sInv[t] = inv;
        }
        __syncthreads();

        // ---- GEMM1: 16 warps = 4 mp x 4 ng of 10 ntiles; B x4 pairs ----
        {
            const int mp = w & 3;
            const int ng = w >> 2;
            const unsigned aBase = uXNh + (mp*32 + l15)*176 + (lane>>4)*16;
            const unsigned bB4 = uW1 + ((ng*10 + joff)*8 + l7)*176 + khalf*16;
            float acc[2][10][4];
            #pragma unroll
            for (int mi = 0; mi < 2; mi++)
                #pragma unroll
                for (int j = 0; j < 10; j++)
                    #pragma unroll
                    for (int e = 0; e < 4; e++) acc[mi][j][e] = 0.f;

            #pragma unroll
            for (int ks = 0; ks < 5; ks++) {
                unsigned a[2][4];
                ldsm_x4(a[0], aBase + ks*32);
                ldsm_x4(a[1], aBase + 16*176 + ks*32);
                #pragma unroll
                for (int p2 = 0; p2 < 5; p2++) {
                    unsigned b[4];
                    ldsm_x4(b, bB4 + p2*2816 + ks*32);
                    mma_bf16(acc[0][2*p2],   a[0], b[0], b[1]);
                    mma_bf16(acc[1][2*p2],   a[1], b[0], b[1]);
                    mma_bf16(acc[0][2*p2+1], a[0], b[2], b[3]);
                    mma_bf16(acc[1][2*p2+1], a[1], b[2], b[3]);
                }
            }
            #pragma unroll
            for (int mi = 0; mi < 2; mi++) {
                const int r0 = mp*32 + mi*16 + g;
                #pragma unroll
                for (int j = 0; j < 10; j++) {
                    const int c = (ng*10+j)*8 + 2*tq;
                    *reinterpret_cast<unsigned*>(sH + r0*344 + c) =
                        pack2(fmaxf(acc[mi][j][0], 0.f), fmaxf(acc[mi][j][1], 0.f));
                    *reinterpret_cast<unsigned*>(sH + (r0+8)*344 + c) =
                        pack2(fmaxf(acc[mi][j][2], 0.f), fmaxf(acc[mi][j][3], 0.f));
                }
            }
        }
        __syncthreads();

        // ---- GEMM2: 4 mp x 2 ng x 2 kh; B x4 pairs (2) + x2 tail ----
        {
            const int mp = w & 3;
            const int ng = (w >> 2) & 1;
            const int kh = w >> 3;
            const unsigned aBase = uH + (mp*32 + l15)*688 + (lane>>4)*16 + kh*320;
            const unsigned bB4 = uW2 + ((ng*5 + joff)*8 + l7)*688 + khalf*16 + kh*320;
            const unsigned bX2 = uW2 + ((ng*5 + 4)*8 + l7)*688 + (l15>>3)*16 + kh*320;
            float acc2[2][5][4];
            #pragma unroll
            for (int mi = 0; mi < 2; mi++)
                #pragma unroll
                for (int j = 0; j < 5; j++)
                    #pragma unroll
                    for (int e = 0; e < 4; e++) acc2[mi][j][e] = 0.f;

            #pragma unroll
            for (int ks = 0; ks < 10; ks++) {
                unsigned a[2][4];
                ldsm_x4(a[0], aBase + ks*32);
                ldsm_x4(a[1], aBase + 16*688 + ks*32);
                #pragma unroll
                for (int p2 = 0; p2 < 2; p2++) {
                    unsigned b[4];
                    ldsm_x4(b, bB4 + p2*11008 + ks*32);   // 16 rows * 688B
                    mma_bf16(acc2[0][2*p2],   a[0], b[0], b[1]);
                    mma_bf16(acc2[1][2*p2],   a[1], b[0], b[1]);
                    mma_bf16(acc2[0][2*p2+1], a[0], b[2], b[3]);
                    mma_bf16(acc2[1][2*p2+1], a[1], b[2], b[3]);
                }
                unsigned b0, b1;
                ldsm_x2(b0, b1, bX2 + ks*32);
                mma_bf16(acc2[0][4], a[0], b0, b1);
                mma_bf16(acc2[1][4], a[1], b0, b1);
            }
            __syncthreads();
            float* sOut = kh ? sOutB : sOutA;
            #pragma unroll
            for (int mi = 0; mi < 2; mi++) {
                const int r0 = mp*32 + mi*16 + g;
                #pragma unroll
                for (int j = 0; j < 5; j++) {
                    const int c = (ng*5+j)*8 + 2*tq;
                    sOut[r0*81 + c]         = acc2[mi][j][0];
                    sOut[r0*81 + c + 1]     = acc2[mi][j][1];
                    sOut[(r0+8)*81 + c]     = acc2[mi][j][2];
                    sOut[(r0+8)*81 + c + 1] = acc2[mi][j][3];
                }
            }
        }
        __syncthreads();

        {
            const int t = tid >> 2, lg = tid & 3;
            const float inv = sInv[t];
            const float4* xr = reinterpret_cast<const float4*>(xin + (tokBase + t)*80) + lg*5;
            float4* yr = reinterpret_cast<float4*>(xout + (tokBase + t)*80) + lg*5;
            #pragma unroll
            for (int u = 0; u < 5; u++) {
                float4 xf = xr[u];
                float xv[4] = {xf.x, xf.y, xf.z, xf.w};
                float f[4];
                #pragma unroll
                for (int e = 0; e < 4; e++) {
                    const int idx = lg*20 + 4*u + e;
                    float hv = sOutA[t*81 + idx] + sOutB[t*81 + idx] + sB2[idx];
                    if (RELU2) hv = fmaxf(hv, 0.f);
                    f[e] = xv[e]*inv + hv * sG[idx];
                }
                yr[u] = make_float4(f[0], f[1], f[2], f[3]);
            }
        }
        __syncthreads();
    }
}

// =====================================================================
extern "C" void kernel_launch(void* const* d_in, const int* in_sizes, int n_in,
                              void* d_out, int out_size)
{
    const float* x       = (const float*)d_in[0];
    const float* bw_qkv  = (const float*)d_in[1];
    const float* bb_qkv  = (const float*)d_in[2];
    const float* bw_proj = (const float*)d_in[3];
    const float* bb_proj = (const float*)d_in[4];
    const float* b_gamma = (const float*)d_in[5];
    const float* bw_mlp1 = (const float*)d_in[6];
    const float* bw_mlp2 = (const float*)d_in[7];
    const float* bb_mlp2 = (const float*)d_in[8];
    const float* gw_qkv  = (const float*)d_in[9];
    const float* gb_qkv  = (const float*)d_in[10];
    const float* gw_proj = (const float*)d_in[11];
    const float* gb_proj = (const float*)d_in[12];
    const float* g_gamma = (const float*)d_in[13];
    const float* gw_mlp1 = (const float*)d_in[14];
    const float* gw_mlp2 = (const float*)d_in[15];
    const float* gb_mlp2 = (const float*)d_in[16];
    float* out = (float*)d_out;

    float *buf1 = nullptr, *buf2 = nullptr;
    cudaGetSymbolAddress((void**)&buf1, g_buf1);
    cudaGetSymbolAddress((void**)&buf2, g_buf2);

    __nv_bfloat16 *qkvT_b, *projT_b, *qkvT_g, *projT_g, *w1T_b, *w2T_b, *w1T_g, *w2T_g;
    cudaGetSymbolAddress((void**)&qkvT_b,  g_qkvT_b);
    cudaGetSymbolAddress((void**)&projT_b, g_projT_b);
    cudaGetSymbolAddress((void**)&qkvT_g,  g_qkvT_g);
    cudaGetSymbolAddress((void**)&projT_g, g_projT_g);
    cudaGetSymbolAddress((void**)&w1T_b,   g_w1T_b);
    cudaGetSymbolAddress((void**)&w2T_b,   g_w2T_b);
    cudaGetSymbolAddress((void**)&w1T_g,   g_w1T_g);
    cudaGetSymbolAddress((void**)&w2T_g,   g_w2T_g);

    const size_t smA = ATTN_SMEM_BYTES;   // 215,808 B
    const size_t smM = MLP_SMEM_BYTES;    // 223,104 B
    cudaFuncSetAttribute(attn_kernel<false>, cudaFuncAttributeMaxDynamicSharedMemorySize, (int)smA);
    cudaFuncSetAttribute(attn_kernel<true>,  cudaFuncAttributeMaxDynamicSharedMemorySize, (int)smA);
    cudaFuncSetAttribute(mlp_kernel<true>,   cudaFuncAttributeMaxDynamicSharedMemorySize, (int)smM);
    cudaFuncSetAttribute(mlp_kernel<false>,  cudaFuncAttributeMaxDynamicSharedMemorySize, (int)smM);

    // ---- single prepass launch: all 8 weight panels ----
    {
        dim3 grid(16, 8);
        prep_all<<<grid, 256>>>(bw_qkv, bw_proj, gw_qkv, gw_proj,
                                bw_mlp1, bw_mlp2, gw_mlp1, gw_mlp2,
                                qkvT_b, projT_b, qkvT_g, projT_g,
                                w1T_b, w2T_b, w1T_g, w2T_g);
    }

    // stage 1: block SA
    attn_kernel<false><<<ATTN_NCTA, 256, smA>>>(x,    buf1, qkvT_b, bb_qkv, projT_b, bb_proj);
    mlp_kernel<true>  <<<MLP_NCTA,  512, smM>>>(buf1, buf2, w1T_b, w2T_b, bb_mlp2, b_gamma);
    // stage 2: grid SA
    attn_kernel<true> <<<ATTN_NCTA, 256, smA>>>(buf2, buf1, qkvT_g, gb_qkv, projT_g, gb_proj);
    mlp_kernel<false> <<<MLP_NCTA,  512, smM>>>(buf1, out, w1T_g, w2T_g, gb_mlp2, g_gamma);
}